// round 9
// baseline (speedup 1.0000x reference)
#include <cuda_runtime.h>
#include <cuda_bf16.h>

#define NTOK 4096
#define CDIM 256
#define NH   8
#define HD   32
// 1/sqrt(32) * log2(e): scores produced directly in log2 domain
#define QSCALE 0.2550181757638722f

typedef unsigned int u32;
typedef unsigned long long u64;

// ---------------- helpers ----------------
__device__ __forceinline__ float ex2f(float x) {
    float r; asm("ex2.approx.ftz.f32 %0, %1;" : "=f"(r) : "f"(x)); return r;
}
// pack: lower 16 bits = bf16(lo), upper = bf16(hi)
__device__ __forceinline__ u32 pkbf(float lo, float hi) {
    u32 r; asm("cvt.rn.bf16x2.f32 %0, %1, %2;" : "=r"(r) : "f"(hi), "f"(lo)); return r;
}
__device__ __forceinline__ void split2(float f0, float f1, u32& hi, u32& lo) {
    hi = pkbf(f0, f1);
    lo = pkbf(f0 - __uint_as_float(hi << 16), f1 - __uint_as_float(hi & 0xFFFF0000u));
}
__device__ __forceinline__ void mma16816(float* d, const u32* a, u32 b0, u32 b1) {
    asm volatile("mma.sync.aligned.m16n8k16.row.col.f32.bf16.bf16.f32 "
        "{%0,%1,%2,%3}, {%4,%5,%6,%7}, {%8,%9}, {%0,%1,%2,%3};"
        : "+f"(d[0]), "+f"(d[1]), "+f"(d[2]), "+f"(d[3])
        : "r"(a[0]), "r"(a[1]), "r"(a[2]), "r"(a[3]), "r"(b0), "r"(b1));
}
__device__ __forceinline__ void ldsm4(u32* r, u32 addr) {
    asm volatile("ldmatrix.sync.aligned.m8n8.x4.shared.b16 {%0,%1,%2,%3}, [%4];"
        : "=r"(r[0]), "=r"(r[1]), "=r"(r[2]), "=r"(r[3]) : "r"(addr));
}
__device__ __forceinline__ void ldsm4t(u32* r, u32 addr) {
    asm volatile("ldmatrix.sync.aligned.m8n8.x4.trans.shared.b16 {%0,%1,%2,%3}, [%4];"
        : "=r"(r[0]), "=r"(r[1]), "=r"(r[2]), "=r"(r[3]) : "r"(addr));
}
__device__ __forceinline__ u32 smem_u32(const void* p) {
    u32 a;
    asm("{ .reg .u64 t; cvta.to.shared.u64 t, %1; cvt.u32.u64 %0, t; }" : "=r"(a) : "l"(p));
    return a;
}
__device__ __forceinline__ void cpa16(u32 s, const void* g) {
    asm volatile("cp.async.cg.shared.global [%0], [%1], 16;" :: "r"(s), "l"(g));
}
#define CP_COMMIT() asm volatile("cp.async.commit_group;" ::: "memory")
#define CP_WAIT0()  asm volatile("cp.async.wait_group 0;" ::: "memory")
#define CP_WAIT1()  asm volatile("cp.async.wait_group 1;" ::: "memory")

// ---------------- scratch (device globals; no allocation allowed) ----------------
__device__ __align__(16) __nv_bfloat16 g_Xh[NTOK*CDIM];     // tok [n][c] hi
__device__ __align__(16) __nv_bfloat16 g_Xl[NTOK*CDIM];
__device__ __align__(16) __nv_bfloat16 g_Wh[3*CDIM*CDIM];   // qkv_w [o][c]
__device__ __align__(16) __nv_bfloat16 g_Wl[3*CDIM*CDIM];
__device__ __align__(16) __nv_bfloat16 g_PWh[CDIM*CDIM];    // proj_w [o][c]
__device__ __align__(16) __nv_bfloat16 g_PWl[CDIM*CDIM];
__device__ __align__(16) __nv_bfloat16 g_Qh[NH*NTOK*HD];    // [h][n][d] (pre-scaled)
__device__ __align__(16) __nv_bfloat16 g_Ql[NH*NTOK*HD];
__device__ __align__(16) __nv_bfloat16 g_Kh[NH*NTOK*HD];
__device__ __align__(16) __nv_bfloat16 g_Kl[NH*NTOK*HD];
__device__ __align__(16) __nv_bfloat16 g_Vh[NH*NTOK*HD];
__device__ __align__(16) __nv_bfloat16 g_Vl[NH*NTOK*HD];
__device__ __align__(16) __nv_bfloat16 g_Th[NTOK*CDIM];     // attn out [n][c]
__device__ __align__(16) __nv_bfloat16 g_Tl[NTOK*CDIM];

// ---------------------------------------------------------------------------
// Kernel 0a: split qkv_w and proj_w into bf16 hi/lo
// ---------------------------------------------------------------------------
__global__ __launch_bounds__(256) void conv_w(const float* __restrict__ wq,
                                              const float* __restrict__ wp) {
    const int i = blockIdx.x * 256 + threadIdx.x;
    if (i < 3*CDIM*CDIM) {
        const float v = wq[i];
        const __nv_bfloat16 h = __float2bfloat16(v);
        g_Wh[i] = h;
        g_Wl[i] = __float2bfloat16(v - __bfloat162float(h));
    }
    if (i < CDIM*CDIM) {
        const float v = wp[i];
        const __nv_bfloat16 h = __float2bfloat16(v);
        g_PWh[i] = h;
        g_PWl[i] = __float2bfloat16(v - __bfloat162float(h));
    }
}

// ---------------------------------------------------------------------------
// Kernel 0b: transpose x [c][n] -> tok [n][c] with bf16 hi/lo split
// ---------------------------------------------------------------------------
__global__ __launch_bounds__(256) void xpose(const float* __restrict__ x) {
    __shared__ float t[32][65];
    const int n0 = blockIdx.x * 64, c0 = blockIdx.y * 32;
    const int tid = threadIdx.x;
    #pragma unroll
    for (int i = tid; i < 2048; i += 256) {
        const int c = i >> 6, n = i & 63;
        t[c][n] = x[(c0 + c)*NTOK + n0 + n];
    }
    __syncthreads();
    const int n = tid >> 2, cg = (tid & 3) * 8;
    u32 hi[4], lo[4];
    #pragma unroll
    for (int k = 0; k < 4; k++)
        split2(t[cg + 2*k][n], t[cg + 2*k + 1][n], hi[k], lo[k]);
    const int ix = ((n0 + n)*CDIM + c0 + cg) >> 3;   // uint4 units (8 bf16)
    ((uint4*)g_Xh)[ix] = make_uint4(hi[0], hi[1], hi[2], hi[3]);
    ((uint4*)g_Xl)[ix] = make_uint4(lo[0], lo[1], lo[2], lo[3]);
}

// ---------------------------------------------------------------------------
// Kernel 1: QKV GEMM on HMMA. Block = 64n x 64o, 128 threads (4 warps x 16n).
// K=256 in 32-chunks, cp.async double-buffered. 3-term bf16 split.
// ---------------------------------------------------------------------------
__global__ __launch_bounds__(128) void qkv_mma() {
    __shared__ __align__(16) uint4 sbuf[2048];   // 2 buffers x 16KB (Ah,Al,Bh,Bl)
    const int tid = threadIdx.x;
    const int w = tid >> 5, l = tid & 31;
    const int g = l >> 2, tg = l & 3;
    const int n0 = blockIdx.x * 64, o0 = blockIdx.y * 64;
    const int qb = w * 16;
    const u32 sb = smem_u32(sbuf);

    const int rowa = qb + (l & 15);
    const int swa  = ((l & 15) >> 1) & 3;
    const int rowk = (l & 7) + ((l >> 4) << 3);
    const u32 kbse = (u32)(rowk * 64);
    const int swk  = (rowk >> 1) & 3;
    const int chpk = (l >> 3) & 1;
    const u32 ck[2] = { (u32)(((0 + chpk) ^ swk) * 16),
                        (u32)(((2 + chpk) ^ swk) * 16) };

    float S[8][4] = {};

    {
        const int c0 = 0;
        for (int i = tid; i < 256; i += 128) {
            const int row = i >> 2, ch = i & 3;
            const u32 dst = sb + (u32)(((row*4) + (ch ^ ((row >> 1) & 3))) * 16);
            cpa16(dst,         g_Xh + (n0+row)*CDIM + c0 + ch*8);
            cpa16(dst + 4096,  g_Xl + (n0+row)*CDIM + c0 + ch*8);
            cpa16(dst + 8192,  g_Wh + (o0+row)*CDIM + c0 + ch*8);
            cpa16(dst + 12288, g_Wl + (o0+row)*CDIM + c0 + ch*8);
        }
        CP_COMMIT();
    }

    for (int it = 0; it < 8; it++) {
        if (it < 7) {
            const int c0 = 32*(it + 1);
            const u32 boff = (u32)(((it + 1) & 1) * 16384);
            for (int i = tid; i < 256; i += 128) {
                const int row = i >> 2, ch = i & 3;
                const u32 dst = sb + boff + (u32)(((row*4) + (ch ^ ((row >> 1) & 3))) * 16);
                cpa16(dst,         g_Xh + (n0+row)*CDIM + c0 + ch*8);
                cpa16(dst + 4096,  g_Xl + (n0+row)*CDIM + c0 + ch*8);
                cpa16(dst + 8192,  g_Wh + (o0+row)*CDIM + c0 + ch*8);
                cpa16(dst + 12288, g_Wl + (o0+row)*CDIM + c0 + ch*8);
            }
            CP_COMMIT();
            CP_WAIT1();
        } else {
            CP_WAIT0();
        }
        __syncthreads();
        const u32 cb = sb + (u32)((it & 1) * 16384);

        u32 ah[2][4], al[2][4];
        #pragma unroll
        for (int kc = 0; kc < 2; kc++) {
            const u32 ch = (u32)((2*kc + (l >> 4)) ^ swa);
            const u32 a = cb + (u32)(rowa*64) + ch*16;
            ldsm4(ah[kc], a);
            ldsm4(al[kc], a + 4096);
        }
        #pragma unroll
        for (int kc = 0; kc < 2; kc++) {
            #pragma unroll
            for (int jp = 0; jp < 4; jp++) {
                u32 bh[4], bl[4];
                const u32 a = cb + 8192 + (u32)(jp*1024) + kbse + ck[kc];
                ldsm4(bh, a);
                ldsm4(bl, a + 4096);
                mma16816(S[2*jp],   ah[kc], bh[0], bh[1]);
                mma16816(S[2*jp],   ah[kc], bl[0], bl[1]);
                mma16816(S[2*jp],   al[kc], bh[0], bh[1]);
                mma16816(S[2*jp+1], ah[kc], bh[2], bh[3]);
                mma16816(S[2*jp+1], ah[kc], bl[2], bl[3]);
                mma16816(S[2*jp+1], al[kc], bh[2], bh[3]);
            }
        }
        __syncthreads();
    }

    const int t = o0 >> 8;
    #pragma unroll
    for (int j = 0; j < 8; j++) {
        const int o = o0 + 16*(j >> 1) + 8*(j & 1) + 2*tg;
        const int hh = (o >> 5) & 7, d = o & 31;
        #pragma unroll
        for (int u = 0; u < 2; u++) {
            const int n = n0 + qb + g + 8*u;
            float f0 = S[j][2*u], f1 = S[j][2*u + 1];
            if (t == 0) { f0 *= QSCALE; f1 *= QSCALE; }
            u32 hi, lo;
            split2(f0, f1, hi, lo);
            const int ix = ((hh*NTOK + n)*HD + d) >> 1;
            if (t == 0)      { ((u32*)g_Qh)[ix] = hi; ((u32*)g_Ql)[ix] = lo; }
            else if (t == 1) { ((u32*)g_Kh)[ix] = hi; ((u32*)g_Kl)[ix] = lo; }
            else             { ((u32*)g_Vh)[ix] = hi; ((u32*)g_Vl)[ix] = lo; }
        }
    }
}

// ---------------------------------------------------------------------------
// Kernel 2: HMMA flash attention, double-buffered K/V prefetch.
// Block = (64 queries, 1 head), 128 threads. Mask dist^2 <= 99.
// ---------------------------------------------------------------------------
__device__ __forceinline__ bool tile_ok(int m0, int zq, int y0q) {
    const int dz  = zq - (m0 >> 8);
    const int y0k = (m0 >> 4) & 15;
    int gap = y0k - (y0q + 3);
    const int g2 = y0q - (y0k + 3);
    if (g2 > gap) gap = g2;
    if (gap < 0) gap = 0;
    return dz*dz + gap*gap <= 99;
}
__device__ __forceinline__ int next_tile(int m0, int mend, int zq, int y0q) {
    for (m0 += 64; m0 <= mend; m0 += 64)
        if (tile_ok(m0, zq, y0q)) return m0;
    return -1;
}

__global__ __launch_bounds__(128, 4) void attn_kernel() {
    // Q: 8KB (hi 4KB + lo 4KB); two 16KB K/V buffers (KH,KL,VH,VL @ 4KB each)
    __shared__ __align__(16) uint4 sbuf[2560];   // 40 KB
    const int tid = threadIdx.x;
    const int w  = tid >> 5, l = tid & 31;
    const int g  = l >> 2, tg = l & 3;
    const int h  = blockIdx.y;
    const int n0 = blockIdx.x * 64;
    const int qb = w * 16;

    const u32 sb = smem_u32(sbuf);
    const u32 QH = sb;
    const u32 KV0 = sb + 8192;   // buffer stride 16384

    const __nv_bfloat16* gqh = g_Qh + h*NTOK*HD;
    const __nv_bfloat16* gql = g_Ql + h*NTOK*HD;
    const __nv_bfloat16* gkh = g_Kh + h*NTOK*HD;
    const __nv_bfloat16* gkl = g_Kl + h*NTOK*HD;
    const __nv_bfloat16* gvh = g_Vh + h*NTOK*HD;
    const __nv_bfloat16* gvl = g_Vl + h*NTOK*HD;

    const int zq  = n0 >> 8;
    const int y0q = (n0 >> 4) & 15;
    const int zlo = (zq - 9 < 0) ? 0 : zq - 9;
    const int zhi = (zq + 9 > 15) ? 15 : zq + 9;
    const int mend = zhi*256 + 192;

    // ---- Q load (own async group) ----
    for (int i = tid; i < 256; i += 128) {
        const int row = i >> 2, ch = i & 3;
        const u32 dst = QH + (u32)(((row*4) + (ch ^ ((row >> 1) & 3))) * 16);
        cpa16(dst,        gqh + (n0+row)*HD + ch*8);
        cpa16(dst + 4096, gql + (n0+row)*HD + ch*8);
    }
    CP_COMMIT();

    // ---- first valid tile: issue K/V load into buffer 0 ----
    int cur = tile_ok(zlo*256, zq, y0q) ? zlo*256
                                        : next_tile(zlo*256, mend, zq, y0q);
    {
        for (int i = tid; i < 256; i += 128) {
            const int row = i >> 2, ch = i & 3;
            const u32 dst = KV0 + (u32)(((row*4) + (ch ^ ((row >> 1) & 3))) * 16);
            cpa16(dst,         gkh + (cur+row)*HD + ch*8);
            cpa16(dst + 4096,  gkl + (cur+row)*HD + ch*8);
            cpa16(dst + 8192,  gvh + (cur+row)*HD + ch*8);
            cpa16(dst + 12288, gvl + (cur+row)*HD + ch*8);
        }
        CP_COMMIT();
    }

    // ---- wait for Q (K/V group may stay in flight), extract A-fragments ----
    CP_WAIT1();
    __syncthreads();
    u32 qh[2][4], ql[2][4];
    {
        const int row = qb + (l & 15);
        const int sw  = ((l & 15) >> 1) & 3;
        #pragma unroll
        for (int kc = 0; kc < 2; kc++) {
            const u32 ch = (u32)((2*kc + (l >> 4)) ^ sw);
            const u32 a  = QH + row*64 + ch*16;
            ldsm4(qh[kc], a);
            ldsm4(ql[kc], a + 4096);
        }
    }

    // per-thread ldmatrix constants for K / V
    const int rowk = (l & 7) + ((l >> 4) << 3);
    const u32 kbse = (u32)(rowk * 64);
    const int swk  = (rowk >> 1) & 3;
    const int chpk = (l >> 3) & 1;
    const u32 ck[2] = { (u32)(((0 + chpk) ^ swk) * 16),
                        (u32)(((2 + chpk) ^ swk) * 16) };
    const int rowv = l & 15;
    const u32 vbse = (u32)(rowv * 64);
    const int swv  = (rowv >> 1) & 3;
    const int tbv  = l >> 4;
    const u32 cv[2] = { (u32)(((0 + tbv) ^ swv) * 16),
                        (u32)(((2 + tbv) ^ swv) * 16) };

    int xq[2], yq[2];
    #pragma unroll
    for (int u = 0; u < 2; u++) {
        const int nq = n0 + qb + g + 8*u;
        xq[u] = nq & 15;
        yq[u] = (nq >> 4) & 15;
    }

    float O[4][4] = {};
    float ls[2] = {0.f, 0.f};
    u32 buf = 0;

    while (cur >= 0) {
        const int nxt = next_tile(cur, mend, zq, y0q);
        if (nxt >= 0) {
            const u32 kvb = KV0 + (buf ^ 1) * 16384;
            for (int i = tid; i < 256; i += 128) {
                const int row = i >> 2, ch = i & 3;
                const u32 dst = kvb + (u32)(((row*4) + (ch ^ ((row >> 1) & 3))) * 16);
                cpa16(dst,         gkh + (nxt+row)*HD + ch*8);
                cpa16(dst + 4096,  gkl + (nxt+row)*HD + ch*8);
                cpa16(dst + 8192,  gvh + (nxt+row)*HD + ch*8);
                cpa16(dst + 12288, gvl + (nxt+row)*HD + ch*8);
            }
            CP_COMMIT();
            CP_WAIT1();
        } else {
            CP_WAIT0();
        }
        __syncthreads();

        const u32 KH = KV0 + buf * 16384;
        const u32 VH = KH + 8192;

        // ---- S = Q K^T ----
        float S[8][4] = {};
        #pragma unroll
        for (int kc = 0; kc < 2; kc++) {
            #pragma unroll
            for (int jp = 0; jp < 4; jp++) {
                u32 bh[4], bl[4];
                const u32 a = KH + (u32)(jp*1024) + kbse + ck[kc];
                ldsm4(bh, a);
                ldsm4(bl, a + 4096);
                mma16816(S[2*jp],   qh[kc], bh[0], bh[1]);
                mma16816(S[2*jp],   qh[kc], bl[0], bl[1]);
                mma16816(S[2*jp],   ql[kc], bh[0], bh[1]);
                mma16816(S[2*jp+1], qh[kc], bh[2], bh[3]);
                mma16816(S[2*jp+1], qh[kc], bl[2], bl[3]);
                mma16816(S[2*jp+1], ql[kc], bh[2], bh[3]);
            }
        }

        // ---- mask + exp2 ----
        const int dz  = zq - (cur >> 8);
        const int y0k = (cur >> 4) & 15;
        const int thr = 99 - dz*dz;
        #pragma unroll
        for (int j = 0; j < 8; j++) {
            const int par = j & 1, jj = j >> 1;
            const int yk = y0k + jj;
            #pragma unroll
            for (int u = 0; u < 2; u++) {
                const int dy = yq[u] - yk;
                const int t2 = thr - dy*dy;
                #pragma unroll
                for (int cc = 0; cc < 2; cc++) {
                    const int dx = xq[u] - (2*tg + cc + 8*par);
                    float p = ex2f(S[j][2*u + cc]);
                    p = (dx*dx <= t2) ? p : 0.f;
                    S[j][2*u + cc] = p;
                    ls[u] += p;
                }
            }
        }

        // ---- O += P V ----
        #pragma unroll
        for (int kc = 0; kc < 4; kc++) {
            u32 ph[4], pl[4];
            #pragma unroll
            for (int hf = 0; hf < 2; hf++) {
                const float* Pj = S[2*kc + hf];
                split2(Pj[0], Pj[1], ph[2*hf],   pl[2*hf]);
                split2(Pj[2], Pj[3], ph[2*hf+1], pl[2*hf+1]);
            }
            #pragma unroll
            for (int np = 0; np < 2; np++) {
                u32 vh[4], vl[4];
                const u32 a = VH + (u32)(kc*1024) + vbse + cv[np];
                ldsm4t(vh, a);
                ldsm4t(vl, a + 4096);
                mma16816(O[2*np],   ph, vh[0], vh[1]);
                mma16816(O[2*np],   ph, vl[0], vl[1]);
                mma16816(O[2*np],   pl, vh[0], vh[1]);
                mma16816(O[2*np+1], ph, vh[2], vh[3]);
                mma16816(O[2*np+1], ph, vl[2], vl[3]);
                mma16816(O[2*np+1], pl, vh[2], vh[3]);
            }
        }
        __syncthreads();   // all warps done with this buffer before it's refilled
        buf ^= 1;
        cur = nxt;
    }

    // ---- epilogue: normalize + bf16 hi/lo store ----
    #pragma unroll
    for (int u = 0; u < 2; u++) {
        ls[u] += __shfl_xor_sync(0xffffffffu, ls[u], 1);
        ls[u] += __shfl_xor_sync(0xffffffffu, ls[u], 2);
        const float inv = 1.0f / ls[u];
        const int row = n0 + qb + g + 8*u;
        const int base = row*CDIM + h*HD;
        #pragma unroll
        for (int t4 = 0; t4 < 4; t4++) {
            u32 hi, lo;
            split2(O[t4][2*u] * inv, O[t4][2*u + 1] * inv, hi, lo);
            const int ix = (base + 8*t4 + 2*tg) >> 1;
            ((u32*)g_Th)[ix] = hi;
            ((u32*)g_Tl)[ix] = lo;
        }
    }
}

// ---------------------------------------------------------------------------
// Kernel 3: proj GEMM on HMMA. out[o][n] = sum_c T[n][c]*pw[o][c] + b[o].
// Block = 64o x 64n, 128 threads (4 warps x 16o). fp32 [C][N] output.
// ---------------------------------------------------------------------------
__global__ __launch_bounds__(128) void proj_mma(const float* __restrict__ bias,
                                                float* __restrict__ out) {
    __shared__ __align__(16) uint4 sbuf[2048];
    const int tid = threadIdx.x;
    const int w = tid >> 5, l = tid & 31;
    const int g = l >> 2, tg = l & 3;
    const int n0 = blockIdx.x * 64, o0 = blockIdx.y * 64;
    const int ob = w * 16;
    const u32 sb = smem_u32(sbuf);

    const int rowa = ob + (l & 15);
    const int swa  = ((l & 15) >> 1) & 3;
    const int rowk = (l & 7) + ((l >> 4) << 3);
    const u32 kbse = (u32)(rowk * 64);
    const int swk  = (rowk >> 1) & 3;
    const int chpk = (l >> 3) & 1;
    const u32 ck[2] = { (u32)(((0 + chpk) ^ swk) * 16),
                        (u32)(((2 + chpk) ^ swk) * 16) };

    float S[8][4] = {};

    {
        const int c0 = 0;
        for (int i = tid; i < 256; i += 128) {
            const int row = i >> 2, ch = i & 3;
            const u32 dst = sb + (u32)(((row*4) + (ch ^ ((row >> 1) & 3))) * 16);
            cpa16(dst,         g_PWh + (o0+row)*CDIM + c0 + ch*8);
            cpa16(dst + 4096,  g_PWl + (o0+row)*CDIM + c0 + ch*8);
            cpa16(dst + 8192,  g_Th  + (n0+row)*CDIM + c0 + ch*8);
            cpa16(dst + 12288, g_Tl  + (n0+row)*CDIM + c0 + ch*8);
        }
        CP_COMMIT();
    }

    for (int it = 0; it < 8; it++) {
        if (it < 7) {
            const int c0 = 32*(it + 1);
            const u32 boff = (u32)(((it + 1) & 1) * 16384);
            for (int i = tid; i < 256; i += 128) {
                const int row = i >> 2, ch = i & 3;
                const u32 dst = sb + boff + (u32)(((row*4) + (ch ^ ((row >> 1) & 3))) * 16);
                cpa16(dst,         g_PWh + (o0+row)*CDIM + c0 + ch*8);
                cpa16(dst + 4096,  g_PWl + (o0+row)*CDIM + c0 + ch*8);
                cpa16(dst + 8192,  g_Th  + (n0+row)*CDIM + c0 + ch*8);
                cpa16(dst + 12288, g_Tl  + (n0+row)*CDIM + c0 + ch*8);
            }
            CP_COMMIT();
            CP_WAIT1();
        } else {
            CP_WAIT0();
        }
        __syncthreads();
        const u32 cb = sb + (u32)((it & 1) * 16384);

        u32 ah[2][4], al[2][4];
        #pragma unroll
        for (int kc = 0; kc < 2; kc++) {
            const u32 ch = (u32)((2*kc + (l >> 4)) ^ swa);
            const u32 a = cb + (u32)(rowa*64) + ch*16;
            ldsm4(ah[kc], a);
            ldsm4(al[kc], a + 4096);
        }
        #pragma unroll
        for (int kc = 0; kc < 2; kc++) {
            #pragma unroll
            for (int jp = 0; jp < 4; jp++) {
                u32 bh[4], bl[4];
                const u32 a = cb + 8192 + (u32)(jp*1024) + kbse + ck[kc];
                ldsm4(bh, a);
                ldsm4(bl, a + 4096);
                mma16816(S[2*jp],   ah[kc], bh[0], bh[1]);
                mma16816(S[2*jp],   ah[kc], bl[0], bl[1]);
                mma16816(S[2*jp],   al[kc], bh[0], bh[1]);
                mma16816(S[2*jp+1], ah[kc], bh[2], bh[3]);
                mma16816(S[2*jp+1], ah[kc], bl[2], bl[3]);
                mma16816(S[2*jp+1], al[kc], bh[2], bh[3]);
            }
        }
        __syncthreads();
    }

    #pragma unroll
    for (int u = 0; u < 2; u++) {
        const int o = o0 + ob + g + 8*u;
        const float bo = bias[o];
        #pragma unroll
        for (int j = 0; j < 8; j++) {
            const int n = n0 + 16*(j >> 1) + 8*(j & 1) + 2*tg;
            float2 v;
            v.x = S[j][2*u]     + bo;
            v.y = S[j][2*u + 1] + bo;
            *(float2*)(out + (size_t)o*NTOK + n) = v;
        }
    }
}

// ---------------------------------------------------------------------------
extern "C" void kernel_launch(void* const* d_in, const int* in_sizes, int n_in,
                              void* d_out, int out_size) {
    const float *x = nullptr, *wq = nullptr, *wp = nullptr, *bp = nullptr;
    for (int i = 0; i < n_in; i++) {
        switch (in_sizes[i]) {
            case 1048576: x  = (const float*)d_in[i]; break;  // x [1,256,16,16,16]
            case 196608:  wq = (const float*)d_in[i]; break;  // qkv_w [768,256]
            case 65536:   wp = (const float*)d_in[i]; break;  // proj_w [256,256]
            case 256:     bp = (const float*)d_in[i]; break;  // proj_b [256]
        }
    }
    float* out = (float*)d_out;

    conv_w  <<<768, 256>>>(wq, wp);
    xpose   <<<dim3(NTOK/64, CDIM/32), 256>>>(x);
    qkv_mma <<<dim3(NTOK/64, 768/64), 128>>>();
    attn_kernel<<<dim3(NTOK/64, NH), 128>>>();
    proj_mma<<<dim3(NTOK/64, CDIM/64), 128>>>(bp, out);
}

// round 10
// speedup vs baseline: 1.0677x; 1.0677x over previous
#include <cuda_runtime.h>
#include <cuda_bf16.h>

#define NTOK 4096
#define CDIM 256
#define NH   8
#define HD   32
// 1/sqrt(32) * log2(e): scores produced directly in log2 domain
#define QSCALE 0.2550181757638722f

typedef unsigned int u32;
typedef unsigned long long u64;

// ---------------- helpers ----------------
__device__ __forceinline__ float ex2f(float x) {
    float r; asm("ex2.approx.ftz.f32 %0, %1;" : "=f"(r) : "f"(x)); return r;
}
// pack: lower 16 bits = bf16(lo), upper = bf16(hi)
__device__ __forceinline__ u32 pkbf(float lo, float hi) {
    u32 r; asm("cvt.rn.bf16x2.f32 %0, %1, %2;" : "=r"(r) : "f"(hi), "f"(lo)); return r;
}
__device__ __forceinline__ void split2(float f0, float f1, u32& hi, u32& lo) {
    hi = pkbf(f0, f1);
    lo = pkbf(f0 - __uint_as_float(hi << 16), f1 - __uint_as_float(hi & 0xFFFF0000u));
}
__device__ __forceinline__ void mma16816(float* d, const u32* a, u32 b0, u32 b1) {
    asm volatile("mma.sync.aligned.m16n8k16.row.col.f32.bf16.bf16.f32 "
        "{%0,%1,%2,%3}, {%4,%5,%6,%7}, {%8,%9}, {%0,%1,%2,%3};"
        : "+f"(d[0]), "+f"(d[1]), "+f"(d[2]), "+f"(d[3])
        : "r"(a[0]), "r"(a[1]), "r"(a[2]), "r"(a[3]), "r"(b0), "r"(b1));
}
__device__ __forceinline__ void ldsm4(u32* r, u32 addr) {
    asm volatile("ldmatrix.sync.aligned.m8n8.x4.shared.b16 {%0,%1,%2,%3}, [%4];"
        : "=r"(r[0]), "=r"(r[1]), "=r"(r[2]), "=r"(r[3]) : "r"(addr));
}
__device__ __forceinline__ void ldsm4t(u32* r, u32 addr) {
    asm volatile("ldmatrix.sync.aligned.m8n8.x4.trans.shared.b16 {%0,%1,%2,%3}, [%4];"
        : "=r"(r[0]), "=r"(r[1]), "=r"(r[2]), "=r"(r[3]) : "r"(addr));
}
__device__ __forceinline__ u32 smem_u32(const void* p) {
    u32 a;
    asm("{ .reg .u64 t; cvta.to.shared.u64 t, %1; cvt.u32.u64 %0, t; }" : "=r"(a) : "l"(p));
    return a;
}
__device__ __forceinline__ void cpa16(u32 s, const void* g) {
    asm volatile("cp.async.cg.shared.global [%0], [%1], 16;" :: "r"(s), "l"(g));
}
#define CP_COMMIT() asm volatile("cp.async.commit_group;" ::: "memory")
#define CP_WAIT0()  asm volatile("cp.async.wait_group 0;" ::: "memory")
#define CP_WAIT1()  asm volatile("cp.async.wait_group 1;" ::: "memory")

// ---------------- scratch (device globals; no allocation allowed) ----------------
__device__ __align__(16) __nv_bfloat16 g_Xh[NTOK*CDIM];     // tok [n][c] hi
__device__ __align__(16) __nv_bfloat16 g_Xl[NTOK*CDIM];
__device__ __align__(16) __nv_bfloat16 g_Wh[3*CDIM*CDIM];   // qkv_w [o][c]
__device__ __align__(16) __nv_bfloat16 g_Wl[3*CDIM*CDIM];
__device__ __align__(16) __nv_bfloat16 g_PWh[CDIM*CDIM];    // proj_w [o][c]
__device__ __align__(16) __nv_bfloat16 g_PWl[CDIM*CDIM];
__device__ __align__(16) __nv_bfloat16 g_Qh[NH*NTOK*HD];    // [h][n][d] (pre-scaled)
__device__ __align__(16) __nv_bfloat16 g_Ql[NH*NTOK*HD];
__device__ __align__(16) __nv_bfloat16 g_Kh[NH*NTOK*HD];
__device__ __align__(16) __nv_bfloat16 g_Kl[NH*NTOK*HD];
__device__ __align__(16) __nv_bfloat16 g_Vh[NH*NTOK*HD];
__device__ __align__(16) __nv_bfloat16 g_Vl[NH*NTOK*HD];
__device__ __align__(16) __nv_bfloat16 g_Th[NTOK*CDIM];     // attn out [n][c]
__device__ __align__(16) __nv_bfloat16 g_Tl[NTOK*CDIM];

// ---------------------------------------------------------------------------
// Kernel 0a: split qkv_w and proj_w into bf16 hi/lo
// ---------------------------------------------------------------------------
__global__ __launch_bounds__(256) void conv_w(const float* __restrict__ wq,
                                              const float* __restrict__ wp) {
    const int i = blockIdx.x * 256 + threadIdx.x;
    if (i < 3*CDIM*CDIM) {
        const float v = wq[i];
        const __nv_bfloat16 h = __float2bfloat16(v);
        g_Wh[i] = h;
        g_Wl[i] = __float2bfloat16(v - __bfloat162float(h));
    }
    if (i < CDIM*CDIM) {
        const float v = wp[i];
        const __nv_bfloat16 h = __float2bfloat16(v);
        g_PWh[i] = h;
        g_PWl[i] = __float2bfloat16(v - __bfloat162float(h));
    }
}

// ---------------------------------------------------------------------------
// Kernel 0b: transpose x [c][n] -> tok [n][c] with bf16 hi/lo split
// ---------------------------------------------------------------------------
__global__ __launch_bounds__(256) void xpose(const float* __restrict__ x) {
    __shared__ float t[32][65];
    const int n0 = blockIdx.x * 64, c0 = blockIdx.y * 32;
    const int tid = threadIdx.x;
    #pragma unroll
    for (int i = tid; i < 2048; i += 256) {
        const int c = i >> 6, n = i & 63;
        t[c][n] = x[(c0 + c)*NTOK + n0 + n];
    }
    __syncthreads();
    const int n = tid >> 2, cg = (tid & 3) * 8;
    u32 hi[4], lo[4];
    #pragma unroll
    for (int k = 0; k < 4; k++)
        split2(t[cg + 2*k][n], t[cg + 2*k + 1][n], hi[k], lo[k]);
    const int ix = ((n0 + n)*CDIM + c0 + cg) >> 3;   // uint4 units (8 bf16)
    ((uint4*)g_Xh)[ix] = make_uint4(hi[0], hi[1], hi[2], hi[3]);
    ((uint4*)g_Xl)[ix] = make_uint4(lo[0], lo[1], lo[2], lo[3]);
}

// ---------------------------------------------------------------------------
// Kernel 1: QKV GEMM on HMMA. Block = 64n x 64o, 128 threads (4 warps x 16n).
// K=256 in 32-chunks, cp.async double-buffered. 3-term bf16 split.
// ---------------------------------------------------------------------------
__global__ __launch_bounds__(128) void qkv_mma() {
    __shared__ __align__(16) uint4 sbuf[2048];   // 2 buffers x 16KB (Ah,Al,Bh,Bl)
    const int tid = threadIdx.x;
    const int w = tid >> 5, l = tid & 31;
    const int g = l >> 2, tg = l & 3;
    const int n0 = blockIdx.x * 64, o0 = blockIdx.y * 64;
    const int qb = w * 16;
    const u32 sb = smem_u32(sbuf);

    const int rowa = qb + (l & 15);
    const int swa  = ((l & 15) >> 1) & 3;
    const int rowk = (l & 7) + ((l >> 4) << 3);
    const u32 kbse = (u32)(rowk * 64);
    const int swk  = (rowk >> 1) & 3;
    const int chpk = (l >> 3) & 1;
    const u32 ck[2] = { (u32)(((0 + chpk) ^ swk) * 16),
                        (u32)(((2 + chpk) ^ swk) * 16) };

    float S[8][4] = {};

    {
        const int c0 = 0;
        for (int i = tid; i < 256; i += 128) {
            const int row = i >> 2, ch = i & 3;
            const u32 dst = sb + (u32)(((row*4) + (ch ^ ((row >> 1) & 3))) * 16);
            cpa16(dst,         g_Xh + (n0+row)*CDIM + c0 + ch*8);
            cpa16(dst + 4096,  g_Xl + (n0+row)*CDIM + c0 + ch*8);
            cpa16(dst + 8192,  g_Wh + (o0+row)*CDIM + c0 + ch*8);
            cpa16(dst + 12288, g_Wl + (o0+row)*CDIM + c0 + ch*8);
        }
        CP_COMMIT();
    }

    for (int it = 0; it < 8; it++) {
        if (it < 7) {
            const int c0 = 32*(it + 1);
            const u32 boff = (u32)(((it + 1) & 1) * 16384);
            for (int i = tid; i < 256; i += 128) {
                const int row = i >> 2, ch = i & 3;
                const u32 dst = sb + boff + (u32)(((row*4) + (ch ^ ((row >> 1) & 3))) * 16);
                cpa16(dst,         g_Xh + (n0+row)*CDIM + c0 + ch*8);
                cpa16(dst + 4096,  g_Xl + (n0+row)*CDIM + c0 + ch*8);
                cpa16(dst + 8192,  g_Wh + (o0+row)*CDIM + c0 + ch*8);
                cpa16(dst + 12288, g_Wl + (o0+row)*CDIM + c0 + ch*8);
            }
            CP_COMMIT();
            CP_WAIT1();
        } else {
            CP_WAIT0();
        }
        __syncthreads();
        const u32 cb = sb + (u32)((it & 1) * 16384);

        u32 ah[2][4], al[2][4];
        #pragma unroll
        for (int kc = 0; kc < 2; kc++) {
            const u32 ch = (u32)((2*kc + (l >> 4)) ^ swa);
            const u32 a = cb + (u32)(rowa*64) + ch*16;
            ldsm4(ah[kc], a);
            ldsm4(al[kc], a + 4096);
        }
        #pragma unroll
        for (int kc = 0; kc < 2; kc++) {
            #pragma unroll
            for (int jp = 0; jp < 4; jp++) {
                u32 bh[4], bl[4];
                const u32 a = cb + 8192 + (u32)(jp*1024) + kbse + ck[kc];
                ldsm4(bh, a);
                ldsm4(bl, a + 4096);
                mma16816(S[2*jp],   ah[kc], bh[0], bh[1]);
                mma16816(S[2*jp],   ah[kc], bl[0], bl[1]);
                mma16816(S[2*jp],   al[kc], bh[0], bh[1]);
                mma16816(S[2*jp+1], ah[kc], bh[2], bh[3]);
                mma16816(S[2*jp+1], ah[kc], bl[2], bl[3]);
                mma16816(S[2*jp+1], al[kc], bh[2], bh[3]);
            }
        }
        __syncthreads();
    }

    const int t = o0 >> 8;
    #pragma unroll
    for (int j = 0; j < 8; j++) {
        const int o = o0 + 16*(j >> 1) + 8*(j & 1) + 2*tg;
        const int hh = (o >> 5) & 7, d = o & 31;
        #pragma unroll
        for (int u = 0; u < 2; u++) {
            const int n = n0 + qb + g + 8*u;
            float f0 = S[j][2*u], f1 = S[j][2*u + 1];
            if (t == 0) { f0 *= QSCALE; f1 *= QSCALE; }
            u32 hi, lo;
            split2(f0, f1, hi, lo);
            const int ix = ((hh*NTOK + n)*HD + d) >> 1;
            if (t == 0)      { ((u32*)g_Qh)[ix] = hi; ((u32*)g_Ql)[ix] = lo; }
            else if (t == 1) { ((u32*)g_Kh)[ix] = hi; ((u32*)g_Kl)[ix] = lo; }
            else             { ((u32*)g_Vh)[ix] = hi; ((u32*)g_Vl)[ix] = lo; }
        }
    }
}

// ---------------------------------------------------------------------------
// Kernel 2: HMMA flash attention, fine-grained split:
// Block = (32 queries, 1 head), 128 threads, grid 1024.
// Warp w: query rows (w&1)*16.., key half (w>>1)*32 of each 64-key tile.
// Partial O/l combined across key-half warps once at the end via smem.
// ---------------------------------------------------------------------------
__device__ __forceinline__ bool tile_ok(int m0, int zq, int y0q) {
    const int dz  = zq - (m0 >> 8);
    const int y0k = (m0 >> 4) & 15;
    int gap = y0k - (y0q + 1);
    const int g2 = y0q - (y0k + 3);
    if (g2 > gap) gap = g2;
    if (gap < 0) gap = 0;
    return dz*dz + gap*gap <= 99;
}
__device__ __forceinline__ int next_tile(int m0, int mend, int zq, int y0q) {
    for (m0 += 64; m0 <= mend; m0 += 64)
        if (tile_ok(m0, zq, y0q)) return m0;
    return -1;
}

__global__ __launch_bounds__(128, 4) void attn_kernel() {
    // Q: 4KB (hi 2KB + lo 2KB); two 16KB K/V buffers (KH,KL,VH,VL @ 4KB each)
    __shared__ __align__(16) uint4 sbuf[2304];   // 36 KB
    const int tid = threadIdx.x;
    const int w  = tid >> 5, l = tid & 31;
    const int g  = l >> 2, tg = l & 3;
    const int qhalf = w & 1;          // 16-row query group
    const int khalf = w >> 1;         // 32-key half of each tile
    const int h  = blockIdx.y;
    const int n0 = blockIdx.x * 32;

    const u32 sb = smem_u32(sbuf);
    const u32 QH = sb;                // lo at +2048
    const u32 KV0 = sb + 4096;        // buffer stride 16384

    const __nv_bfloat16* gqh = g_Qh + h*NTOK*HD;
    const __nv_bfloat16* gql = g_Ql + h*NTOK*HD;
    const __nv_bfloat16* gkh = g_Kh + h*NTOK*HD;
    const __nv_bfloat16* gkl = g_Kl + h*NTOK*HD;
    const __nv_bfloat16* gvh = g_Vh + h*NTOK*HD;
    const __nv_bfloat16* gvl = g_Vl + h*NTOK*HD;

    const int zq  = n0 >> 8;
    const int y0q = (n0 >> 4) & 15;   // queries cover y0q, y0q+1
    const int zlo = (zq - 9 < 0) ? 0 : zq - 9;
    const int zhi = (zq + 9 > 15) ? 15 : zq + 9;
    const int mend = zhi*256 + 192;

    // ---- Q load (32 rows, own async group) ----
    {
        const int row = tid >> 2, ch = tid & 3;
        const u32 dst = QH + (u32)(((row*4) + (ch ^ ((row >> 1) & 3))) * 16);
        cpa16(dst,        gqh + (n0+row)*HD + ch*8);
        cpa16(dst + 2048, gql + (n0+row)*HD + ch*8);
    }
    CP_COMMIT();

    // ---- first valid tile: K/V into buffer 0 ----
    int cur = tile_ok(zlo*256, zq, y0q) ? zlo*256
                                        : next_tile(zlo*256, mend, zq, y0q);
    for (int i = tid; i < 256; i += 128) {
        const int row = i >> 2, ch = i & 3;
        const u32 dst = KV0 + (u32)(((row*4) + (ch ^ ((row >> 1) & 3))) * 16);
        cpa16(dst,         gkh + (cur+row)*HD + ch*8);
        cpa16(dst + 4096,  gkl + (cur+row)*HD + ch*8);
        cpa16(dst + 8192,  gvh + (cur+row)*HD + ch*8);
        cpa16(dst + 12288, gvl + (cur+row)*HD + ch*8);
    }
    CP_COMMIT();

    // ---- wait for Q only, extract A-fragments ----
    CP_WAIT1();
    __syncthreads();
    u32 qh[2][4], ql[2][4];
    {
        const int row = qhalf*16 + (l & 15);
        const int sw  = ((l & 15) >> 1) & 3;
        #pragma unroll
        for (int kc = 0; kc < 2; kc++) {
            const u32 ch = (u32)((2*kc + (l >> 4)) ^ sw);
            const u32 a  = QH + row*64 + ch*16;
            ldsm4(qh[kc], a);
            ldsm4(ql[kc], a + 2048);
        }
    }

    // per-thread ldmatrix constants for K / V
    const int rowk = (l & 7) + ((l >> 4) << 3);
    const u32 kbse = (u32)(rowk * 64);
    const int swk  = (rowk >> 1) & 3;
    const int chpk = (l >> 3) & 1;
    const u32 ck[2] = { (u32)(((0 + chpk) ^ swk) * 16),
                        (u32)(((2 + chpk) ^ swk) * 16) };
    const int rowv = l & 15;
    const u32 vbse = (u32)(rowv * 64);
    const int swv  = (rowv >> 1) & 3;
    const int tbv  = l >> 4;
    const u32 cv[2] = { (u32)(((0 + tbv) ^ swv) * 16),
                        (u32)(((2 + tbv) ^ swv) * 16) };

    int xq[2], yq[2];
    #pragma unroll
    for (int u = 0; u < 2; u++) {
        const int nq = n0 + qhalf*16 + g + 8*u;
        xq[u] = nq & 15;
        yq[u] = (nq >> 4) & 15;
    }

    float O[4][4] = {};
    float ls[2] = {0.f, 0.f};
    u32 buf = 0;

    while (cur >= 0) {
        const int nxt = next_tile(cur, mend, zq, y0q);
        if (nxt >= 0) {
            const u32 kvb = KV0 + (buf ^ 1) * 16384;
            for (int i = tid; i < 256; i += 128) {
                const int row = i >> 2, ch = i & 3;
                const u32 dst = kvb + (u32)(((row*4) + (ch ^ ((row >> 1) & 3))) * 16);
                cpa16(dst,         gkh + (nxt+row)*HD + ch*8);
                cpa16(dst + 4096,  gkl + (nxt+row)*HD + ch*8);
                cpa16(dst + 8192,  gvh + (nxt+row)*HD + ch*8);
                cpa16(dst + 12288, gvl + (nxt+row)*HD + ch*8);
            }
            CP_COMMIT();
            CP_WAIT1();
        } else {
            CP_WAIT0();
        }
        __syncthreads();

        const u32 KH = KV0 + buf * 16384;
        const u32 VH = KH + 8192;

        // ---- S = Q K^T (this warp's 32 keys) ----
        float S[4][4] = {};
        #pragma unroll
        for (int kc = 0; kc < 2; kc++) {
            #pragma unroll
            for (int jp = 0; jp < 2; jp++) {
                u32 bh[4], bl[4];
                const u32 a = KH + (u32)((khalf*2 + jp)*1024) + kbse + ck[kc];
                ldsm4(bh, a);
                ldsm4(bl, a + 4096);
                mma16816(S[2*jp],   qh[kc], bh[0], bh[1]);
                mma16816(S[2*jp],   qh[kc], bl[0], bl[1]);
                mma16816(S[2*jp],   ql[kc], bh[0], bh[1]);
                mma16816(S[2*jp+1], qh[kc], bh[2], bh[3]);
                mma16816(S[2*jp+1], qh[kc], bl[2], bl[3]);
                mma16816(S[2*jp+1], ql[kc], bh[2], bh[3]);
            }
        }

        // ---- mask + exp2 ----
        const int dz   = zq - (cur >> 8);
        const int y0kw = ((cur >> 4) & 15) + khalf*2;
        const int thr  = 99 - dz*dz;
        #pragma unroll
        for (int j = 0; j < 4; j++) {
            const int par = j & 1, jj = j >> 1;
            const int yk = y0kw + jj;
            #pragma unroll
            for (int u = 0; u < 2; u++) {
                const int dy = yq[u] - yk;
                const int t2 = thr - dy*dy;
                #pragma unroll
                for (int cc = 0; cc < 2; cc++) {
                    const int dx = xq[u] - (2*tg + cc + 8*par);
                    float p = ex2f(S[j][2*u + cc]);
                    p = (dx*dx <= t2) ? p : 0.f;
                    S[j][2*u + cc] = p;
                    ls[u] += p;
                }
            }
        }

        // ---- O += P V (this warp's 32 keys) ----
        #pragma unroll
        for (int kc = 0; kc < 2; kc++) {
            u32 ph[4], pl[4];
            #pragma unroll
            for (int hf = 0; hf < 2; hf++) {
                const float* Pj = S[2*kc + hf];
                split2(Pj[0], Pj[1], ph[2*hf],   pl[2*hf]);
                split2(Pj[2], Pj[3], ph[2*hf+1], pl[2*hf+1]);
            }
            #pragma unroll
            for (int np = 0; np < 2; np++) {
                u32 vh[4], vl[4];
                const u32 a = VH + (u32)((khalf*2 + kc)*1024) + vbse + cv[np];
                ldsm4t(vh, a);
                ldsm4t(vl, a + 4096);
                mma16816(O[2*np],   ph, vh[0], vh[1]);
                mma16816(O[2*np],   ph, vl[0], vl[1]);
                mma16816(O[2*np],   pl, vh[0], vh[1]);
                mma16816(O[2*np+1], ph, vh[2], vh[3]);
                mma16816(O[2*np+1], ph, vl[2], vl[3]);
                mma16816(O[2*np+1], pl, vh[2], vh[3]);
            }
        }
        __syncthreads();   // all warps off this buffer before refill
        buf ^= 1;
        cur = nxt;
    }

    // ---- combine key-half partials (khalf 1 -> khalf 0), then store ----
    __syncthreads();
    float* red = (float*)sbuf;
    if (khalf == 1) {
        float* p = red + (qhalf*32 + l)*18;
        #pragma unroll
        for (int t4 = 0; t4 < 4; t4++)
            #pragma unroll
            for (int k = 0; k < 4; k++) p[t4*4 + k] = O[t4][k];
        p[16] = ls[0]; p[17] = ls[1];
    }
    __syncthreads();
    if (khalf == 0) {
        const float* p = red + (qhalf*32 + l)*18;
        #pragma unroll
        for (int t4 = 0; t4 < 4; t4++)
            #pragma unroll
            for (int k = 0; k < 4; k++) O[t4][k] += p[t4*4 + k];
        ls[0] += p[16]; ls[1] += p[17];

        #pragma unroll
        for (int u = 0; u < 2; u++) {
            ls[u] += __shfl_xor_sync(0xffffffffu, ls[u], 1);
            ls[u] += __shfl_xor_sync(0xffffffffu, ls[u], 2);
            const float inv = 1.0f / ls[u];
            const int row = n0 + qhalf*16 + g + 8*u;
            const int base = row*CDIM + h*HD;
            #pragma unroll
            for (int t4 = 0; t4 < 4; t4++) {
                u32 hi, lo;
                split2(O[t4][2*u] * inv, O[t4][2*u + 1] * inv, hi, lo);
                const int ix = (base + 8*t4 + 2*tg) >> 1;
                ((u32*)g_Th)[ix] = hi;
                ((u32*)g_Tl)[ix] = lo;
            }
        }
    }
}

// ---------------------------------------------------------------------------
// Kernel 3: proj GEMM on HMMA. out[o][n] = sum_c T[n][c]*pw[o][c] + b[o].
// Block = 64o x 64n, 128 threads (4 warps x 16o). fp32 [C][N] output.
// ---------------------------------------------------------------------------
__global__ __launch_bounds__(128) void proj_mma(const float* __restrict__ bias,
                                                float* __restrict__ out) {
    __shared__ __align__(16) uint4 sbuf[2048];
    const int tid = threadIdx.x;
    const int w = tid >> 5, l = tid & 31;
    const int g = l >> 2, tg = l & 3;
    const int n0 = blockIdx.x * 64, o0 = blockIdx.y * 64;
    const int ob = w * 16;
    const u32 sb = smem_u32(sbuf);

    const int rowa = ob + (l & 15);
    const int swa  = ((l & 15) >> 1) & 3;
    const int rowk = (l & 7) + ((l >> 4) << 3);
    const u32 kbse = (u32)(rowk * 64);
    const int swk  = (rowk >> 1) & 3;
    const int chpk = (l >> 3) & 1;
    const u32 ck[2] = { (u32)(((0 + chpk) ^ swk) * 16),
                        (u32)(((2 + chpk) ^ swk) * 16) };

    float S[8][4] = {};

    {
        const int c0 = 0;
        for (int i = tid; i < 256; i += 128) {
            const int row = i >> 2, ch = i & 3;
            const u32 dst = sb + (u32)(((row*4) + (ch ^ ((row >> 1) & 3))) * 16);
            cpa16(dst,         g_PWh + (o0+row)*CDIM + c0 + ch*8);
            cpa16(dst + 4096,  g_PWl + (o0+row)*CDIM + c0 + ch*8);
            cpa16(dst + 8192,  g_Th  + (n0+row)*CDIM + c0 + ch*8);
            cpa16(dst + 12288, g_Tl  + (n0+row)*CDIM + c0 + ch*8);
        }
        CP_COMMIT();
    }

    for (int it = 0; it < 8; it++) {
        if (it < 7) {
            const int c0 = 32*(it + 1);
            const u32 boff = (u32)(((it + 1) & 1) * 16384);
            for (int i = tid; i < 256; i += 128) {
                const int row = i >> 2, ch = i & 3;
                const u32 dst = sb + boff + (u32)(((row*4) + (ch ^ ((row >> 1) & 3))) * 16);
                cpa16(dst,         g_PWh + (o0+row)*CDIM + c0 + ch*8);
                cpa16(dst + 4096,  g_PWl + (o0+row)*CDIM + c0 + ch*8);
                cpa16(dst + 8192,  g_Th  + (n0+row)*CDIM + c0 + ch*8);
                cpa16(dst + 12288, g_Tl  + (n0+row)*CDIM + c0 + ch*8);
            }
            CP_COMMIT();
            CP_WAIT1();
        } else {
            CP_WAIT0();
        }
        __syncthreads();
        const u32 cb = sb + (u32)((it & 1) * 16384);

        u32 ah[2][4], al[2][4];
        #pragma unroll
        for (int kc = 0; kc < 2; kc++) {
            const u32 ch = (u32)((2*kc + (l >> 4)) ^ swa);
            const u32 a = cb + (u32)(rowa*64) + ch*16;
            ldsm4(ah[kc], a);
            ldsm4(al[kc], a + 4096);
        }
        #pragma unroll
        for (int kc = 0; kc < 2; kc++) {
            #pragma unroll
            for (int jp = 0; jp < 4; jp++) {
                u32 bh[4], bl[4];
                const u32 a = cb + 8192 + (u32)(jp*1024) + kbse + ck[kc];
                ldsm4(bh, a);
                ldsm4(bl, a + 4096);
                mma16816(S[2*jp],   ah[kc], bh[0], bh[1]);
                mma16816(S[2*jp],   ah[kc], bl[0], bl[1]);
                mma16816(S[2*jp],   al[kc], bh[0], bh[1]);
                mma16816(S[2*jp+1], ah[kc], bh[2], bh[3]);
                mma16816(S[2*jp+1], ah[kc], bl[2], bl[3]);
                mma16816(S[2*jp+1], al[kc], bh[2], bh[3]);
            }
        }
        __syncthreads();
    }

    #pragma unroll
    for (int u = 0; u < 2; u++) {
        const int o = o0 + ob + g + 8*u;
        const float bo = bias[o];
        #pragma unroll
        for (int j = 0; j < 8; j++) {
            const int n = n0 + 16*(j >> 1) + 8*(j & 1) + 2*tg;
            float2 v;
            v.x = S[j][2*u]     + bo;
            v.y = S[j][2*u + 1] + bo;
            *(float2*)(out + (size_t)o*NTOK + n) = v;
        }
    }
}

// ---------------------------------------------------------------------------
extern "C" void kernel_launch(void* const* d_in, const int* in_sizes, int n_in,
                              void* d_out, int out_size) {
    const float *x = nullptr, *wq = nullptr, *wp = nullptr, *bp = nullptr;
    for (int i = 0; i < n_in; i++) {
        switch (in_sizes[i]) {
            case 1048576: x  = (const float*)d_in[i]; break;  // x [1,256,16,16,16]
            case 196608:  wq = (const float*)d_in[i]; break;  // qkv_w [768,256]
            case 65536:   wp = (const float*)d_in[i]; break;  // proj_w [256,256]
            case 256:     bp = (const float*)d_in[i]; break;  // proj_b [256]
        }
    }
    float* out = (float*)d_out;

    conv_w  <<<768, 256>>>(wq, wp);
    xpose   <<<dim3(NTOK/64, CDIM/32), 256>>>(x);
    qkv_mma <<<dim3(NTOK/64, 768/64), 128>>>();
    attn_kernel<<<dim3(NTOK/32, NH), 128>>>();
    proj_mma<<<dim3(NTOK/64, CDIM/64), 128>>>(bp, out);
}

// round 11
// speedup vs baseline: 1.0787x; 1.0102x over previous
#include <cuda_runtime.h>
#include <cuda_bf16.h>

#define NTOK 4096
#define CDIM 256
#define NH   8
#define HD   32
// 1/sqrt(32) * log2(e): scores produced directly in log2 domain
#define QSCALE 0.2550181757638722f
#define NITEMS ((NTOK/32)*NH)   // 1024 attention work items

typedef unsigned int u32;
typedef unsigned long long u64;

// ---------------- helpers ----------------
__device__ __forceinline__ float ex2f(float x) {
    float r; asm("ex2.approx.ftz.f32 %0, %1;" : "=f"(r) : "f"(x)); return r;
}
// pack: lower 16 bits = bf16(lo), upper = bf16(hi)
__device__ __forceinline__ u32 pkbf(float lo, float hi) {
    u32 r; asm("cvt.rn.bf16x2.f32 %0, %1, %2;" : "=r"(r) : "f"(hi), "f"(lo)); return r;
}
__device__ __forceinline__ void split2(float f0, float f1, u32& hi, u32& lo) {
    hi = pkbf(f0, f1);
    lo = pkbf(f0 - __uint_as_float(hi << 16), f1 - __uint_as_float(hi & 0xFFFF0000u));
}
__device__ __forceinline__ void mma16816(float* d, const u32* a, u32 b0, u32 b1) {
    asm volatile("mma.sync.aligned.m16n8k16.row.col.f32.bf16.bf16.f32 "
        "{%0,%1,%2,%3}, {%4,%5,%6,%7}, {%8,%9}, {%0,%1,%2,%3};"
        : "+f"(d[0]), "+f"(d[1]), "+f"(d[2]), "+f"(d[3])
        : "r"(a[0]), "r"(a[1]), "r"(a[2]), "r"(a[3]), "r"(b0), "r"(b1));
}
__device__ __forceinline__ void ldsm4(u32* r, u32 addr) {
    asm volatile("ldmatrix.sync.aligned.m8n8.x4.shared.b16 {%0,%1,%2,%3}, [%4];"
        : "=r"(r[0]), "=r"(r[1]), "=r"(r[2]), "=r"(r[3]) : "r"(addr));
}
__device__ __forceinline__ void ldsm4t(u32* r, u32 addr) {
    asm volatile("ldmatrix.sync.aligned.m8n8.x4.trans.shared.b16 {%0,%1,%2,%3}, [%4];"
        : "=r"(r[0]), "=r"(r[1]), "=r"(r[2]), "=r"(r[3]) : "r"(addr));
}
__device__ __forceinline__ u32 smem_u32(const void* p) {
    u32 a;
    asm("{ .reg .u64 t; cvta.to.shared.u64 t, %1; cvt.u32.u64 %0, t; }" : "=r"(a) : "l"(p));
    return a;
}
__device__ __forceinline__ void cpa16(u32 s, const void* g) {
    asm volatile("cp.async.cg.shared.global [%0], [%1], 16;" :: "r"(s), "l"(g));
}
#define CP_COMMIT() asm volatile("cp.async.commit_group;" ::: "memory")
#define CP_WAIT0()  asm volatile("cp.async.wait_group 0;" ::: "memory")
#define CP_WAIT1()  asm volatile("cp.async.wait_group 1;" ::: "memory")

// ---------------- scratch (device globals; no allocation allowed) ----------------
__device__ __align__(16) __nv_bfloat16 g_Xh[NTOK*CDIM];     // tok [n][c] hi
__device__ __align__(16) __nv_bfloat16 g_Xl[NTOK*CDIM];
__device__ __align__(16) __nv_bfloat16 g_Wh[3*CDIM*CDIM];   // qkv_w [o][c]
__device__ __align__(16) __nv_bfloat16 g_Wl[3*CDIM*CDIM];
__device__ __align__(16) __nv_bfloat16 g_PWh[CDIM*CDIM];    // proj_w [o][c]
__device__ __align__(16) __nv_bfloat16 g_PWl[CDIM*CDIM];
__device__ __align__(16) __nv_bfloat16 g_Qh[NH*NTOK*HD];    // [h][n][d] (pre-scaled)
__device__ __align__(16) __nv_bfloat16 g_Ql[NH*NTOK*HD];
__device__ __align__(16) __nv_bfloat16 g_Kh[NH*NTOK*HD];
__device__ __align__(16) __nv_bfloat16 g_Kl[NH*NTOK*HD];
__device__ __align__(16) __nv_bfloat16 g_Vh[NH*NTOK*HD];
__device__ __align__(16) __nv_bfloat16 g_Vl[NH*NTOK*HD];
__device__ __align__(16) __nv_bfloat16 g_Th[NTOK*CDIM];     // attn out [n][c]
__device__ __align__(16) __nv_bfloat16 g_Tl[NTOK*CDIM];

__device__ int g_ctr;                     // work-queue counter
// central-z first so the long items schedule first
__constant__ int c_ztab[16] = {7,8,6,9,5,10,4,11,3,12,2,13,1,14,0,15};

__global__ void reset_ctr() { g_ctr = 0; }

// ---------------------------------------------------------------------------
// Kernel 0a: split qkv_w and proj_w into bf16 hi/lo
// ---------------------------------------------------------------------------
__global__ __launch_bounds__(256) void conv_w(const float* __restrict__ wq,
                                              const float* __restrict__ wp) {
    const int i = blockIdx.x * 256 + threadIdx.x;
    if (i < 3*CDIM*CDIM) {
        const float v = wq[i];
        const __nv_bfloat16 h = __float2bfloat16(v);
        g_Wh[i] = h;
        g_Wl[i] = __float2bfloat16(v - __bfloat162float(h));
    }
    if (i < CDIM*CDIM) {
        const float v = wp[i];
        const __nv_bfloat16 h = __float2bfloat16(v);
        g_PWh[i] = h;
        g_PWl[i] = __float2bfloat16(v - __bfloat162float(h));
    }
}

// ---------------------------------------------------------------------------
// Kernel 0b: transpose x [c][n] -> tok [n][c] with bf16 hi/lo split
// ---------------------------------------------------------------------------
__global__ __launch_bounds__(256) void xpose(const float* __restrict__ x) {
    __shared__ float t[32][65];
    const int n0 = blockIdx.x * 64, c0 = blockIdx.y * 32;
    const int tid = threadIdx.x;
    #pragma unroll
    for (int i = tid; i < 2048; i += 256) {
        const int c = i >> 6, n = i & 63;
        t[c][n] = x[(c0 + c)*NTOK + n0 + n];
    }
    __syncthreads();
    const int n = tid >> 2, cg = (tid & 3) * 8;
    u32 hi[4], lo[4];
    #pragma unroll
    for (int k = 0; k < 4; k++)
        split2(t[cg + 2*k][n], t[cg + 2*k + 1][n], hi[k], lo[k]);
    const int ix = ((n0 + n)*CDIM + c0 + cg) >> 3;   // uint4 units (8 bf16)
    ((uint4*)g_Xh)[ix] = make_uint4(hi[0], hi[1], hi[2], hi[3]);
    ((uint4*)g_Xl)[ix] = make_uint4(lo[0], lo[1], lo[2], lo[3]);
}

// ---------------------------------------------------------------------------
// Kernel 1: QKV GEMM on HMMA. Block = 64n x 64o, 128 threads (4 warps x 16n).
// K=256 in 32-chunks, cp.async double-buffered. 3-term bf16 split.
// ---------------------------------------------------------------------------
__global__ __launch_bounds__(128) void qkv_mma() {
    __shared__ __align__(16) uint4 sbuf[2048];   // 2 buffers x 16KB (Ah,Al,Bh,Bl)
    const int tid = threadIdx.x;
    const int w = tid >> 5, l = tid & 31;
    const int g = l >> 2, tg = l & 3;
    const int n0 = blockIdx.x * 64, o0 = blockIdx.y * 64;
    const int qb = w * 16;
    const u32 sb = smem_u32(sbuf);

    const int rowa = qb + (l & 15);
    const int swa  = ((l & 15) >> 1) & 3;
    const int rowk = (l & 7) + ((l >> 4) << 3);
    const u32 kbse = (u32)(rowk * 64);
    const int swk  = (rowk >> 1) & 3;
    const int chpk = (l >> 3) & 1;
    const u32 ck[2] = { (u32)(((0 + chpk) ^ swk) * 16),
                        (u32)(((2 + chpk) ^ swk) * 16) };

    float S[8][4] = {};

    {
        const int c0 = 0;
        for (int i = tid; i < 256; i += 128) {
            const int row = i >> 2, ch = i & 3;
            const u32 dst = sb + (u32)(((row*4) + (ch ^ ((row >> 1) & 3))) * 16);
            cpa16(dst,         g_Xh + (n0+row)*CDIM + c0 + ch*8);
            cpa16(dst + 4096,  g_Xl + (n0+row)*CDIM + c0 + ch*8);
            cpa16(dst + 8192,  g_Wh + (o0+row)*CDIM + c0 + ch*8);
            cpa16(dst + 12288, g_Wl + (o0+row)*CDIM + c0 + ch*8);
        }
        CP_COMMIT();
    }

    for (int it = 0; it < 8; it++) {
        if (it < 7) {
            const int c0 = 32*(it + 1);
            const u32 boff = (u32)(((it + 1) & 1) * 16384);
            for (int i = tid; i < 256; i += 128) {
                const int row = i >> 2, ch = i & 3;
                const u32 dst = sb + boff + (u32)(((row*4) + (ch ^ ((row >> 1) & 3))) * 16);
                cpa16(dst,         g_Xh + (n0+row)*CDIM + c0 + ch*8);
                cpa16(dst + 4096,  g_Xl + (n0+row)*CDIM + c0 + ch*8);
                cpa16(dst + 8192,  g_Wh + (o0+row)*CDIM + c0 + ch*8);
                cpa16(dst + 12288, g_Wl + (o0+row)*CDIM + c0 + ch*8);
            }
            CP_COMMIT();
            CP_WAIT1();
        } else {
            CP_WAIT0();
        }
        __syncthreads();
        const u32 cb = sb + (u32)((it & 1) * 16384);

        u32 ah[2][4], al[2][4];
        #pragma unroll
        for (int kc = 0; kc < 2; kc++) {
            const u32 ch = (u32)((2*kc + (l >> 4)) ^ swa);
            const u32 a = cb + (u32)(rowa*64) + ch*16;
            ldsm4(ah[kc], a);
            ldsm4(al[kc], a + 4096);
        }
        #pragma unroll
        for (int kc = 0; kc < 2; kc++) {
            #pragma unroll
            for (int jp = 0; jp < 4; jp++) {
                u32 bh[4], bl[4];
                const u32 a = cb + 8192 + (u32)(jp*1024) + kbse + ck[kc];
                ldsm4(bh, a);
                ldsm4(bl, a + 4096);
                mma16816(S[2*jp],   ah[kc], bh[0], bh[1]);
                mma16816(S[2*jp],   ah[kc], bl[0], bl[1]);
                mma16816(S[2*jp],   al[kc], bh[0], bh[1]);
                mma16816(S[2*jp+1], ah[kc], bh[2], bh[3]);
                mma16816(S[2*jp+1], ah[kc], bl[2], bl[3]);
                mma16816(S[2*jp+1], al[kc], bh[2], bh[3]);
            }
        }
        __syncthreads();
    }

    const int t = o0 >> 8;
    #pragma unroll
    for (int j = 0; j < 8; j++) {
        const int o = o0 + 16*(j >> 1) + 8*(j & 1) + 2*tg;
        const int hh = (o >> 5) & 7, d = o & 31;
        #pragma unroll
        for (int u = 0; u < 2; u++) {
            const int n = n0 + qb + g + 8*u;
            float f0 = S[j][2*u], f1 = S[j][2*u + 1];
            if (t == 0) { f0 *= QSCALE; f1 *= QSCALE; }
            u32 hi, lo;
            split2(f0, f1, hi, lo);
            const int ix = ((hh*NTOK + n)*HD + d) >> 1;
            if (t == 0)      { ((u32*)g_Qh)[ix] = hi; ((u32*)g_Ql)[ix] = lo; }
            else if (t == 1) { ((u32*)g_Kh)[ix] = hi; ((u32*)g_Kl)[ix] = lo; }
            else             { ((u32*)g_Vh)[ix] = hi; ((u32*)g_Vl)[ix] = lo; }
        }
    }
}

// ---------------------------------------------------------------------------
// Kernel 2: HMMA flash attention, persistent work-queue version.
// Grid = 592 (one full wave). Item = (32 queries, 1 head), central-z first.
// Pipeline per tile: prefetch(next) -> compute(cur) -> wait -> ONE sync.
// Warp w: query rows (w&1)*16.., key half (w>>1)*32. Mask dist^2 <= 99.
// ---------------------------------------------------------------------------
__device__ __forceinline__ bool tile_ok(int m0, int zq, int y0q) {
    const int dz  = zq - (m0 >> 8);
    const int y0k = (m0 >> 4) & 15;
    int gap = y0k - (y0q + 1);
    const int g2 = y0q - (y0k + 3);
    if (g2 > gap) gap = g2;
    if (gap < 0) gap = 0;
    return dz*dz + gap*gap <= 99;
}
__device__ __forceinline__ int next_tile(int m0, int mend, int zq, int y0q) {
    for (m0 += 64; m0 <= mend; m0 += 64)
        if (tile_ok(m0, zq, y0q)) return m0;
    return -1;
}

__global__ __launch_bounds__(128, 4) void attn_kernel() {
    // Q: 4KB (hi 2KB + lo 2KB); two 16KB K/V buffers (KH,KL,VH,VL @ 4KB each)
    __shared__ __align__(16) uint4 sbuf[2304];   // 36 KB
    __shared__ int s_item;
    const int tid = threadIdx.x;
    const int w  = tid >> 5, l = tid & 31;
    const int g  = l >> 2, tg = l & 3;
    const int qhalf = w & 1;          // 16-row query group
    const int khalf = w >> 1;         // 32-key half of each tile

    const u32 sb = smem_u32(sbuf);
    const u32 QH = sb;                // lo at +2048
    const u32 KV0 = sb + 4096;        // buffer stride 16384

    // per-thread ldmatrix constants (item-independent)
    const int rowk = (l & 7) + ((l >> 4) << 3);
    const u32 kbse = (u32)(rowk * 64);
    const int swk  = (rowk >> 1) & 3;
    const int chpk = (l >> 3) & 1;
    const u32 ck[2] = { (u32)(((0 + chpk) ^ swk) * 16),
                        (u32)(((2 + chpk) ^ swk) * 16) };
    const int rowv = l & 15;
    const u32 vbse = (u32)(rowv * 64);
    const int swv  = (rowv >> 1) & 3;
    const int tbv  = l >> 4;
    const u32 cv[2] = { (u32)(((0 + tbv) ^ swv) * 16),
                        (u32)(((2 + tbv) ^ swv) * 16) };
    const int qrow = qhalf*16 + (l & 15);
    const int qsw  = ((l & 15) >> 1) & 3;

    for (;;) {
        __syncthreads();             // protect s_item + smem from prior item
        if (tid == 0) s_item = atomicAdd(&g_ctr, 1);
        __syncthreads();
        const int item = s_item;
        if (item >= NITEMS) break;

        const int h = item & 7;
        const int r = item >> 3;
        const int n0 = (c_ztab[r >> 3] * 8 + (r & 7)) * 32;

        const __nv_bfloat16* gqh = g_Qh + h*NTOK*HD;
        const __nv_bfloat16* gql = g_Ql + h*NTOK*HD;
        const __nv_bfloat16* gkh = g_Kh + h*NTOK*HD;
        const __nv_bfloat16* gkl = g_Kl + h*NTOK*HD;
        const __nv_bfloat16* gvh = g_Vh + h*NTOK*HD;
        const __nv_bfloat16* gvl = g_Vl + h*NTOK*HD;

        const int zq  = n0 >> 8;
        const int y0q = (n0 >> 4) & 15;
        const int zlo = (zq - 9 < 0) ? 0 : zq - 9;
        const int zhi = (zq + 9 > 15) ? 15 : zq + 9;
        const int mend = zhi*256 + 192;

        int xq[2], yq[2];
        int dx2[2][4];               // tile-invariant mask terms
        #pragma unroll
        for (int u = 0; u < 2; u++) {
            const int nq = n0 + qhalf*16 + g + 8*u;
            xq[u] = nq & 15;
            yq[u] = (nq >> 4) & 15;
            #pragma unroll
            for (int pc = 0; pc < 4; pc++) {     // pc = par*2+cc
                const int dx = xq[u] - (2*tg + (pc & 1) + 8*(pc >> 1));
                dx2[u][pc] = dx*dx;
            }
        }

        // ---- prologue: Q + first K/V tile, one group ----
        int cur = tile_ok(zlo*256, zq, y0q) ? zlo*256
                                            : next_tile(zlo*256, mend, zq, y0q);
        {
            const int row = tid >> 2, ch = tid & 3;
            const u32 dst = QH + (u32)(((row*4) + (ch ^ ((row >> 1) & 3))) * 16);
            cpa16(dst,        gqh + (n0+row)*HD + ch*8);
            cpa16(dst + 2048, gql + (n0+row)*HD + ch*8);
        }
        for (int i = tid; i < 256; i += 128) {
            const int row = i >> 2, ch = i & 3;
            const u32 dst = KV0 + (u32)(((row*4) + (ch ^ ((row >> 1) & 3))) * 16);
            cpa16(dst,         gkh + (cur+row)*HD + ch*8);
            cpa16(dst + 4096,  gkl + (cur+row)*HD + ch*8);
            cpa16(dst + 8192,  gvh + (cur+row)*HD + ch*8);
            cpa16(dst + 12288, gvl + (cur+row)*HD + ch*8);
        }
        CP_COMMIT();
        CP_WAIT0();
        __syncthreads();

        // ---- Q fragments ----
        u32 qh[2][4], ql[2][4];
        #pragma unroll
        for (int kc = 0; kc < 2; kc++) {
            const u32 ch = (u32)((2*kc + (l >> 4)) ^ qsw);
            const u32 a  = QH + qrow*64 + ch*16;
            ldsm4(qh[kc], a);
            ldsm4(ql[kc], a + 2048);
        }

        float O[4][4] = {};
        float ls[2] = {0.f, 0.f};
        u32 buf = 0;

        while (cur >= 0) {
            // prefetch next valid tile into the other buffer, then compute
            const int nxt = next_tile(cur, mend, zq, y0q);
            if (nxt >= 0) {
                const u32 kvb = KV0 + (buf ^ 1) * 16384;
                for (int i = tid; i < 256; i += 128) {
                    const int row = i >> 2, ch = i & 3;
                    const u32 dst = kvb + (u32)(((row*4) + (ch ^ ((row >> 1) & 3))) * 16);
                    cpa16(dst,         gkh + (nxt+row)*HD + ch*8);
                    cpa16(dst + 4096,  gkl + (nxt+row)*HD + ch*8);
                    cpa16(dst + 8192,  gvh + (nxt+row)*HD + ch*8);
                    cpa16(dst + 12288, gvl + (nxt+row)*HD + ch*8);
                }
                CP_COMMIT();
            }

            const u32 KH = KV0 + buf * 16384;
            const u32 VH = KH + 8192;

            // ---- S = Q K^T (this warp's 32 keys) ----
            float S[4][4] = {};
            #pragma unroll
            for (int kc = 0; kc < 2; kc++) {
                #pragma unroll
                for (int jp = 0; jp < 2; jp++) {
                    u32 bh[4], bl[4];
                    const u32 a = KH + (u32)((khalf*2 + jp)*1024) + kbse + ck[kc];
                    ldsm4(bh, a);
                    ldsm4(bl, a + 4096);
                    mma16816(S[2*jp],   qh[kc], bh[0], bh[1]);
                    mma16816(S[2*jp],   qh[kc], bl[0], bl[1]);
                    mma16816(S[2*jp],   ql[kc], bh[0], bh[1]);
                    mma16816(S[2*jp+1], qh[kc], bh[2], bh[3]);
                    mma16816(S[2*jp+1], qh[kc], bl[2], bl[3]);
                    mma16816(S[2*jp+1], ql[kc], bh[2], bh[3]);
                }
            }

            // ---- mask + exp2 (dx^2 precomputed) ----
            const int dz   = zq - (cur >> 8);
            const int y0kw = ((cur >> 4) & 15) + khalf*2;
            const int thr  = 99 - dz*dz;
            #pragma unroll
            for (int j = 0; j < 4; j++) {
                const int par = j & 1, jj = j >> 1;
                const int yk = y0kw + jj;
                #pragma unroll
                for (int u = 0; u < 2; u++) {
                    const int dy = yq[u] - yk;
                    const int t2 = thr - dy*dy;
                    #pragma unroll
                    for (int cc = 0; cc < 2; cc++) {
                        float p = ex2f(S[j][2*u + cc]);
                        p = (dx2[u][par*2 + cc] <= t2) ? p : 0.f;
                        S[j][2*u + cc] = p;
                        ls[u] += p;
                    }
                }
            }

            // ---- O += P V (this warp's 32 keys) ----
            #pragma unroll
            for (int kc = 0; kc < 2; kc++) {
                u32 ph[4], pl[4];
                #pragma unroll
                for (int hf = 0; hf < 2; hf++) {
                    const float* Pj = S[2*kc + hf];
                    split2(Pj[0], Pj[1], ph[2*hf],   pl[2*hf]);
                    split2(Pj[2], Pj[3], ph[2*hf+1], pl[2*hf+1]);
                }
                #pragma unroll
                for (int np = 0; np < 2; np++) {
                    u32 vh[4], vl[4];
                    const u32 a = VH + (u32)((khalf*2 + kc)*1024) + vbse + cv[np];
                    ldsm4t(vh, a);
                    ldsm4t(vl, a + 4096);
                    mma16816(O[2*np],   ph, vh[0], vh[1]);
                    mma16816(O[2*np],   ph, vl[0], vl[1]);
                    mma16816(O[2*np],   pl, vh[0], vh[1]);
                    mma16816(O[2*np+1], ph, vh[2], vh[3]);
                    mma16816(O[2*np+1], ph, vl[2], vl[3]);
                    mma16816(O[2*np+1], pl, vh[2], vh[3]);
                }
            }

            // single sync per tile: prefetch data ready+visible, buffer safe
            CP_WAIT0();
            __syncthreads();
            buf ^= 1;
            cur = nxt;
        }

        // ---- combine key-half partials (khalf 1 -> khalf 0), then store ----
        float* red = (float*)sbuf;
        if (khalf == 1) {
            float* p = red + (qhalf*32 + l)*18;
            #pragma unroll
            for (int t4 = 0; t4 < 4; t4++)
                #pragma unroll
                for (int k = 0; k < 4; k++) p[t4*4 + k] = O[t4][k];
            p[16] = ls[0]; p[17] = ls[1];
        }
        __syncthreads();
        if (khalf == 0) {
            const float* p = red + (qhalf*32 + l)*18;
            #pragma unroll
            for (int t4 = 0; t4 < 4; t4++)
                #pragma unroll
                for (int k = 0; k < 4; k++) O[t4][k] += p[t4*4 + k];
            ls[0] += p[16]; ls[1] += p[17];

            #pragma unroll
            for (int u = 0; u < 2; u++) {
                ls[u] += __shfl_xor_sync(0xffffffffu, ls[u], 1);
                ls[u] += __shfl_xor_sync(0xffffffffu, ls[u], 2);
                const float inv = 1.0f / ls[u];
                const int row = n0 + qhalf*16 + g + 8*u;
                const int base = row*CDIM + h*HD;
                #pragma unroll
                for (int t4 = 0; t4 < 4; t4++) {
                    u32 hi, lo;
                    split2(O[t4][2*u] * inv, O[t4][2*u + 1] * inv, hi, lo);
                    const int ix = (base + 8*t4 + 2*tg) >> 1;
                    ((u32*)g_Th)[ix] = hi;
                    ((u32*)g_Tl)[ix] = lo;
                }
            }
        }
    }
}

// ---------------------------------------------------------------------------
// Kernel 3: proj GEMM on HMMA. out[o][n] = sum_c T[n][c]*pw[o][c] + b[o].
// Block = 64o x 64n, 128 threads (4 warps x 16o). fp32 [C][N] output.
// ---------------------------------------------------------------------------
__global__ __launch_bounds__(128) void proj_mma(const float* __restrict__ bias,
                                                float* __restrict__ out) {
    __shared__ __align__(16) uint4 sbuf[2048];
    const int tid = threadIdx.x;
    const int w = tid >> 5, l = tid & 31;
    const int g = l >> 2, tg = l & 3;
    const int n0 = blockIdx.x * 64, o0 = blockIdx.y * 64;
    const int ob = w * 16;
    const u32 sb = smem_u32(sbuf);

    const int rowa = ob + (l & 15);
    const int swa  = ((l & 15) >> 1) & 3;
    const int rowk = (l & 7) + ((l >> 4) << 3);
    const u32 kbse = (u32)(rowk * 64);
    const int swk  = (rowk >> 1) & 3;
    const int chpk = (l >> 3) & 1;
    const u32 ck[2] = { (u32)(((0 + chpk) ^ swk) * 16),
                        (u32)(((2 + chpk) ^ swk) * 16) };

    float S[8][4] = {};

    {
        const int c0 = 0;
        for (int i = tid; i < 256; i += 128) {
            const int row = i >> 2, ch = i & 3;
            const u32 dst = sb + (u32)(((row*4) + (ch ^ ((row >> 1) & 3))) * 16);
            cpa16(dst,         g_PWh + (o0+row)*CDIM + c0 + ch*8);
            cpa16(dst + 4096,  g_PWl + (o0+row)*CDIM + c0 + ch*8);
            cpa16(dst + 8192,  g_Th  + (n0+row)*CDIM + c0 + ch*8);
            cpa16(dst + 12288, g_Tl  + (n0+row)*CDIM + c0 + ch*8);
        }
        CP_COMMIT();
    }

    for (int it = 0; it < 8; it++) {
        if (it < 7) {
            const int c0 = 32*(it + 1);
            const u32 boff = (u32)(((it + 1) & 1) * 16384);
            for (int i = tid; i < 256; i += 128) {
                const int row = i >> 2, ch = i & 3;
                const u32 dst = sb + boff + (u32)(((row*4) + (ch ^ ((row >> 1) & 3))) * 16);
                cpa16(dst,         g_PWh + (o0+row)*CDIM + c0 + ch*8);
                cpa16(dst + 4096,  g_PWl + (o0+row)*CDIM + c0 + ch*8);
                cpa16(dst + 8192,  g_Th  + (n0+row)*CDIM + c0 + ch*8);
                cpa16(dst + 12288, g_Tl  + (n0+row)*CDIM + c0 + ch*8);
            }
            CP_COMMIT();
            CP_WAIT1();
        } else {
            CP_WAIT0();
        }
        __syncthreads();
        const u32 cb = sb + (u32)((it & 1) * 16384);

        u32 ah[2][4], al[2][4];
        #pragma unroll
        for (int kc = 0; kc < 2; kc++) {
            const u32 ch = (u32)((2*kc + (l >> 4)) ^ swa);
            const u32 a = cb + (u32)(rowa*64) + ch*16;
            ldsm4(ah[kc], a);
            ldsm4(al[kc], a + 4096);
        }
        #pragma unroll
        for (int kc = 0; kc < 2; kc++) {
            #pragma unroll
            for (int jp = 0; jp < 4; jp++) {
                u32 bh[4], bl[4];
                const u32 a = cb + 8192 + (u32)(jp*1024) + kbse + ck[kc];
                ldsm4(bh, a);
                ldsm4(bl, a + 4096);
                mma16816(S[2*jp],   ah[kc], bh[0], bh[1]);
                mma16816(S[2*jp],   ah[kc], bl[0], bl[1]);
                mma16816(S[2*jp],   al[kc], bh[0], bh[1]);
                mma16816(S[2*jp+1], ah[kc], bh[2], bh[3]);
                mma16816(S[2*jp+1], ah[kc], bl[2], bl[3]);
                mma16816(S[2*jp+1], al[kc], bh[2], bh[3]);
            }
        }
        __syncthreads();
    }

    #pragma unroll
    for (int u = 0; u < 2; u++) {
        const int o = o0 + ob + g + 8*u;
        const float bo = bias[o];
        #pragma unroll
        for (int j = 0; j < 8; j++) {
            const int n = n0 + 16*(j >> 1) + 8*(j & 1) + 2*tg;
            float2 v;
            v.x = S[j][2*u]     + bo;
            v.y = S[j][2*u + 1] + bo;
            *(float2*)(out + (size_t)o*NTOK + n) = v;
        }
    }
}

// ---------------------------------------------------------------------------
extern "C" void kernel_launch(void* const* d_in, const int* in_sizes, int n_in,
                              void* d_out, int out_size) {
    const float *x = nullptr, *wq = nullptr, *wp = nullptr, *bp = nullptr;
    for (int i = 0; i < n_in; i++) {
        switch (in_sizes[i]) {
            case 1048576: x  = (const float*)d_in[i]; break;  // x [1,256,16,16,16]
            case 196608:  wq = (const float*)d_in[i]; break;  // qkv_w [768,256]
            case 65536:   wp = (const float*)d_in[i]; break;  // proj_w [256,256]
            case 256:     bp = (const float*)d_in[i]; break;  // proj_b [256]
        }
    }
    float* out = (float*)d_out;

    reset_ctr<<<1, 1>>>();
    conv_w  <<<768, 256>>>(wq, wp);
    xpose   <<<dim3(NTOK/64, CDIM/32), 256>>>(x);
    qkv_mma <<<dim3(NTOK/64, 768/64), 128>>>();
    attn_kernel<<<592, 128>>>();
    proj_mma<<<dim3(NTOK/64, CDIM/64), 128>>>(bp, out);
}

// round 12
// speedup vs baseline: 1.2302x; 1.1405x over previous
#include <cuda_runtime.h>
#include <cuda_fp16.h>

#define NTOK 4096
#define CDIM 256
#define NH   8
#define HD   32
// 1/sqrt(32) * log2(e): scores produced directly in log2 domain
#define QSCALE 0.2550181757638722f
#define NITEMS ((NTOK/32)*NH)   // 1024 attention work items

typedef unsigned int u32;
typedef unsigned long long u64;

// ---------------- helpers ----------------
__device__ __forceinline__ float ex2f(float x) {
    float r; asm("ex2.approx.ftz.f32 %0, %1;" : "=f"(r) : "f"(x)); return r;
}
// pack two floats to f16x2: lower 16 bits = f16(lo), upper = f16(hi)
__device__ __forceinline__ u32 pkhf(float lo, float hi) {
    u32 r; asm("cvt.rn.f16x2.f32 %0, %1, %2;" : "=r"(r) : "f"(hi), "f"(lo)); return r;
}
__device__ __forceinline__ float f16lo(u32 v) {
    float f; asm("{.reg .b16 h,x; mov.b32 {h,x}, %1; cvt.f32.f16 %0, h;}" : "=f"(f) : "r"(v)); return f;
}
__device__ __forceinline__ float f16hi(u32 v) {
    float f; asm("{.reg .b16 x,h; mov.b32 {x,h}, %1; cvt.f32.f16 %0, h;}" : "=f"(f) : "r"(v)); return f;
}
__device__ __forceinline__ void split2(float f0, float f1, u32& hi, u32& lo) {
    hi = pkhf(f0, f1);
    lo = pkhf(f0 - f16lo(hi), f1 - f16hi(hi));
}
__device__ __forceinline__ void mma16816(float* d, const u32* a, u32 b0, u32 b1) {
    asm volatile("mma.sync.aligned.m16n8k16.row.col.f32.f16.f16.f32 "
        "{%0,%1,%2,%3}, {%4,%5,%6,%7}, {%8,%9}, {%0,%1,%2,%3};"
        : "+f"(d[0]), "+f"(d[1]), "+f"(d[2]), "+f"(d[3])
        : "r"(a[0]), "r"(a[1]), "r"(a[2]), "r"(a[3]), "r"(b0), "r"(b1));
}
__device__ __forceinline__ void ldsm4(u32* r, u32 addr) {
    asm volatile("ldmatrix.sync.aligned.m8n8.x4.shared.b16 {%0,%1,%2,%3}, [%4];"
        : "=r"(r[0]), "=r"(r[1]), "=r"(r[2]), "=r"(r[3]) : "r"(addr));
}
__device__ __forceinline__ void ldsm4t(u32* r, u32 addr) {
    asm volatile("ldmatrix.sync.aligned.m8n8.x4.trans.shared.b16 {%0,%1,%2,%3}, [%4];"
        : "=r"(r[0]), "=r"(r[1]), "=r"(r[2]), "=r"(r[3]) : "r"(addr));
}
__device__ __forceinline__ u32 smem_u32(const void* p) {
    u32 a;
    asm("{ .reg .u64 t; cvta.to.shared.u64 t, %1; cvt.u32.u64 %0, t; }" : "=r"(a) : "l"(p));
    return a;
}
__device__ __forceinline__ void cpa16(u32 s, const void* g) {
    asm volatile("cp.async.cg.shared.global [%0], [%1], 16;" :: "r"(s), "l"(g));
}
#define CP_COMMIT() asm volatile("cp.async.commit_group;" ::: "memory")
#define CP_WAIT0()  asm volatile("cp.async.wait_group 0;" ::: "memory")
#define CP_WAIT1()  asm volatile("cp.async.wait_group 1;" ::: "memory")

// ---------------- scratch (device globals; no allocation allowed) ----------------
__device__ __align__(16) __half g_Xh[NTOK*CDIM];     // tok [n][c] hi
__device__ __align__(16) __half g_Xl[NTOK*CDIM];
__device__ __align__(16) __half g_Wh[3*CDIM*CDIM];   // qkv_w [o][c]
__device__ __align__(16) __half g_Wl[3*CDIM*CDIM];
__device__ __align__(16) __half g_PWh[CDIM*CDIM];    // proj_w [o][c]
__device__ __align__(16) __half g_PWl[CDIM*CDIM];
__device__ __align__(16) __half g_Qh[NH*NTOK*HD];    // [h][n][d] (pre-scaled)
__device__ __align__(16) __half g_Ql[NH*NTOK*HD];
__device__ __align__(16) __half g_Kh[NH*NTOK*HD];
__device__ __align__(16) __half g_Kl[NH*NTOK*HD];
__device__ __align__(16) __half g_Vh[NH*NTOK*HD];
__device__ __align__(16) __half g_Vl[NH*NTOK*HD];
__device__ __align__(16) __half g_Th[NTOK*CDIM];     // attn out [n][c]
__device__ __align__(16) __half g_Tl[NTOK*CDIM];

__device__ int g_ctr;                     // work-queue counter
// central-z first so the long items schedule first
__constant__ int c_ztab[16] = {7,8,6,9,5,10,4,11,3,12,2,13,1,14,0,15};

__global__ void reset_ctr() { g_ctr = 0; }

// ---------------------------------------------------------------------------
// Kernel 0a: split qkv_w and proj_w into f16 hi/lo
// ---------------------------------------------------------------------------
__global__ __launch_bounds__(256) void conv_w(const float* __restrict__ wq,
                                              const float* __restrict__ wp) {
    const int i = blockIdx.x * 256 + threadIdx.x;
    if (i < 3*CDIM*CDIM) {
        const float v = wq[i];
        const __half h = __float2half_rn(v);
        g_Wh[i] = h;
        g_Wl[i] = __float2half_rn(v - __half2float(h));
    }
    if (i < CDIM*CDIM) {
        const float v = wp[i];
        const __half h = __float2half_rn(v);
        g_PWh[i] = h;
        g_PWl[i] = __float2half_rn(v - __half2float(h));
    }
}

// ---------------------------------------------------------------------------
// Kernel 0b: transpose x [c][n] -> tok [n][c] with f16 hi/lo split
// ---------------------------------------------------------------------------
__global__ __launch_bounds__(256) void xpose(const float* __restrict__ x) {
    __shared__ float t[32][65];
    const int n0 = blockIdx.x * 64, c0 = blockIdx.y * 32;
    const int tid = threadIdx.x;
    #pragma unroll
    for (int i = tid; i < 2048; i += 256) {
        const int c = i >> 6, n = i & 63;
        t[c][n] = x[(c0 + c)*NTOK + n0 + n];
    }
    __syncthreads();
    const int n = tid >> 2, cg = (tid & 3) * 8;
    u32 hi[4], lo[4];
    #pragma unroll
    for (int k = 0; k < 4; k++)
        split2(t[cg + 2*k][n], t[cg + 2*k + 1][n], hi[k], lo[k]);
    const int ix = ((n0 + n)*CDIM + c0 + cg) >> 3;   // uint4 units (8 halves)
    ((uint4*)g_Xh)[ix] = make_uint4(hi[0], hi[1], hi[2], hi[3]);
    ((uint4*)g_Xl)[ix] = make_uint4(lo[0], lo[1], lo[2], lo[3]);
}

// ---------------------------------------------------------------------------
// Kernel 1: QKV GEMM on HMMA (f16 3-term split). Block = 64n x 64o, 128 thr.
// ---------------------------------------------------------------------------
__global__ __launch_bounds__(128) void qkv_mma() {
    __shared__ __align__(16) uint4 sbuf[2048];   // 2 buffers x 16KB (Ah,Al,Bh,Bl)
    const int tid = threadIdx.x;
    const int w = tid >> 5, l = tid & 31;
    const int g = l >> 2, tg = l & 3;
    const int n0 = blockIdx.x * 64, o0 = blockIdx.y * 64;
    const int qb = w * 16;
    const u32 sb = smem_u32(sbuf);

    const int rowa = qb + (l & 15);
    const int swa  = ((l & 15) >> 1) & 3;
    const int rowk = (l & 7) + ((l >> 4) << 3);
    const u32 kbse = (u32)(rowk * 64);
    const int swk  = (rowk >> 1) & 3;
    const int chpk = (l >> 3) & 1;
    const u32 ck[2] = { (u32)(((0 + chpk) ^ swk) * 16),
                        (u32)(((2 + chpk) ^ swk) * 16) };

    float S[8][4] = {};

    {
        const int c0 = 0;
        for (int i = tid; i < 256; i += 128) {
            const int row = i >> 2, ch = i & 3;
            const u32 dst = sb + (u32)(((row*4) + (ch ^ ((row >> 1) & 3))) * 16);
            cpa16(dst,         g_Xh + (n0+row)*CDIM + c0 + ch*8);
            cpa16(dst + 4096,  g_Xl + (n0+row)*CDIM + c0 + ch*8);
            cpa16(dst + 8192,  g_Wh + (o0+row)*CDIM + c0 + ch*8);
            cpa16(dst + 12288, g_Wl + (o0+row)*CDIM + c0 + ch*8);
        }
        CP_COMMIT();
    }

    for (int it = 0; it < 8; it++) {
        if (it < 7) {
            const int c0 = 32*(it + 1);
            const u32 boff = (u32)(((it + 1) & 1) * 16384);
            for (int i = tid; i < 256; i += 128) {
                const int row = i >> 2, ch = i & 3;
                const u32 dst = sb + boff + (u32)(((row*4) + (ch ^ ((row >> 1) & 3))) * 16);
                cpa16(dst,         g_Xh + (n0+row)*CDIM + c0 + ch*8);
                cpa16(dst + 4096,  g_Xl + (n0+row)*CDIM + c0 + ch*8);
                cpa16(dst + 8192,  g_Wh + (o0+row)*CDIM + c0 + ch*8);
                cpa16(dst + 12288, g_Wl + (o0+row)*CDIM + c0 + ch*8);
            }
            CP_COMMIT();
            CP_WAIT1();
        } else {
            CP_WAIT0();
        }
        __syncthreads();
        const u32 cb = sb + (u32)((it & 1) * 16384);

        u32 ah[2][4], al[2][4];
        #pragma unroll
        for (int kc = 0; kc < 2; kc++) {
            const u32 ch = (u32)((2*kc + (l >> 4)) ^ swa);
            const u32 a = cb + (u32)(rowa*64) + ch*16;
            ldsm4(ah[kc], a);
            ldsm4(al[kc], a + 4096);
        }
        #pragma unroll
        for (int kc = 0; kc < 2; kc++) {
            #pragma unroll
            for (int jp = 0; jp < 4; jp++) {
                u32 bh[4], bl[4];
                const u32 a = cb + 8192 + (u32)(jp*1024) + kbse + ck[kc];
                ldsm4(bh, a);
                ldsm4(bl, a + 4096);
                mma16816(S[2*jp],   ah[kc], bh[0], bh[1]);
                mma16816(S[2*jp],   ah[kc], bl[0], bl[1]);
                mma16816(S[2*jp],   al[kc], bh[0], bh[1]);
                mma16816(S[2*jp+1], ah[kc], bh[2], bh[3]);
                mma16816(S[2*jp+1], ah[kc], bl[2], bl[3]);
                mma16816(S[2*jp+1], al[kc], bh[2], bh[3]);
            }
        }
        __syncthreads();
    }

    const int t = o0 >> 8;
    #pragma unroll
    for (int j = 0; j < 8; j++) {
        const int o = o0 + 16*(j >> 1) + 8*(j & 1) + 2*tg;
        const int hh = (o >> 5) & 7, d = o & 31;
        #pragma unroll
        for (int u = 0; u < 2; u++) {
            const int n = n0 + qb + g + 8*u;
            float f0 = S[j][2*u], f1 = S[j][2*u + 1];
            if (t == 0) { f0 *= QSCALE; f1 *= QSCALE; }
            u32 hi, lo;
            split2(f0, f1, hi, lo);
            const int ix = ((hh*NTOK + n)*HD + d) >> 1;
            if (t == 0)      { ((u32*)g_Qh)[ix] = hi; ((u32*)g_Ql)[ix] = lo; }
            else if (t == 1) { ((u32*)g_Kh)[ix] = hi; ((u32*)g_Kl)[ix] = lo; }
            else             { ((u32*)g_Vh)[ix] = hi; ((u32*)g_Vl)[ix] = lo; }
        }
    }
}

// ---------------------------------------------------------------------------
// Kernel 2: HMMA flash attention, persistent work-queue, fp16 splits.
// S = 3-term; PV = 2-term (Ph*Vh + Ph*Vl; fp16 P rounding ~2^-11 -> ok).
// Grid = 592. Item = (32 queries, 1 head). Mask dist^2 <= 99.
// ---------------------------------------------------------------------------
__device__ __forceinline__ bool tile_ok(int m0, int zq, int y0q) {
    const int dz  = zq - (m0 >> 8);
    const int y0k = (m0 >> 4) & 15;
    int gap = y0k - (y0q + 1);
    const int g2 = y0q - (y0k + 3);
    if (g2 > gap) gap = g2;
    if (gap < 0) gap = 0;
    return dz*dz + gap*gap <= 99;
}
__device__ __forceinline__ int next_tile(int m0, int mend, int zq, int y0q) {
    for (m0 += 64; m0 <= mend; m0 += 64)
        if (tile_ok(m0, zq, y0q)) return m0;
    return -1;
}

__global__ __launch_bounds__(128, 4) void attn_kernel() {
    // Q: 4KB (hi 2KB + lo 2KB); two 16KB K/V buffers (KH,KL,VH,VL @ 4KB each)
    __shared__ __align__(16) uint4 sbuf[2304];   // 36 KB
    __shared__ int s_item;
    const int tid = threadIdx.x;
    const int w  = tid >> 5, l = tid & 31;
    const int g  = l >> 2, tg = l & 3;
    const int qhalf = w & 1;          // 16-row query group
    const int khalf = w >> 1;         // 32-key half of each tile

    const u32 sb = smem_u32(sbuf);
    const u32 QH = sb;                // lo at +2048
    const u32 KV0 = sb + 4096;        // buffer stride 16384

    // per-thread ldmatrix constants (item-independent)
    const int rowk = (l & 7) + ((l >> 4) << 3);
    const u32 kbse = (u32)(rowk * 64);
    const int swk  = (rowk >> 1) & 3;
    const int chpk = (l >> 3) & 1;
    const u32 ck[2] = { (u32)(((0 + chpk) ^ swk) * 16),
                        (u32)(((2 + chpk) ^ swk) * 16) };
    const int rowv = l & 15;
    const u32 vbse = (u32)(rowv * 64);
    const int swv  = (rowv >> 1) & 3;
    const int tbv  = l >> 4;
    const u32 cv[2] = { (u32)(((0 + tbv) ^ swv) * 16),
                        (u32)(((2 + tbv) ^ swv) * 16) };
    const int qrow = qhalf*16 + (l & 15);
    const int qsw  = ((l & 15) >> 1) & 3;

    for (;;) {
        __syncthreads();             // protect s_item + smem from prior item
        if (tid == 0) s_item = atomicAdd(&g_ctr, 1);
        __syncthreads();
        const int item = s_item;
        if (item >= NITEMS) break;

        const int h = item & 7;
        const int r = item >> 3;
        const int n0 = (c_ztab[r >> 3] * 8 + (r & 7)) * 32;

        const __half* gqh = g_Qh + h*NTOK*HD;
        const __half* gql = g_Ql + h*NTOK*HD;
        const __half* gkh = g_Kh + h*NTOK*HD;
        const __half* gkl = g_Kl + h*NTOK*HD;
        const __half* gvh = g_Vh + h*NTOK*HD;
        const __half* gvl = g_Vl + h*NTOK*HD;

        const int zq  = n0 >> 8;
        const int y0q = (n0 >> 4) & 15;
        const int zlo = (zq - 9 < 0) ? 0 : zq - 9;
        const int zhi = (zq + 9 > 15) ? 15 : zq + 9;
        const int mend = zhi*256 + 192;

        int xq[2], yq[2];
        int dx2[2][4];               // tile-invariant mask terms
        #pragma unroll
        for (int u = 0; u < 2; u++) {
            const int nq = n0 + qhalf*16 + g + 8*u;
            xq[u] = nq & 15;
            yq[u] = (nq >> 4) & 15;
            #pragma unroll
            for (int pc = 0; pc < 4; pc++) {     // pc = par*2+cc
                const int dx = xq[u] - (2*tg + (pc & 1) + 8*(pc >> 1));
                dx2[u][pc] = dx*dx;
            }
        }

        // ---- prologue: Q + first K/V tile, one group ----
        int cur = tile_ok(zlo*256, zq, y0q) ? zlo*256
                                            : next_tile(zlo*256, mend, zq, y0q);
        {
            const int row = tid >> 2, ch = tid & 3;
            const u32 dst = QH + (u32)(((row*4) + (ch ^ ((row >> 1) & 3))) * 16);
            cpa16(dst,        gqh + (n0+row)*HD + ch*8);
            cpa16(dst + 2048, gql + (n0+row)*HD + ch*8);
        }
        for (int i = tid; i < 256; i += 128) {
            const int row = i >> 2, ch = i & 3;
            const u32 dst = KV0 + (u32)(((row*4) + (ch ^ ((row >> 1) & 3))) * 16);
            cpa16(dst,         gkh + (cur+row)*HD + ch*8);
            cpa16(dst + 4096,  gkl + (cur+row)*HD + ch*8);
            cpa16(dst + 8192,  gvh + (cur+row)*HD + ch*8);
            cpa16(dst + 12288, gvl + (cur+row)*HD + ch*8);
        }
        CP_COMMIT();
        CP_WAIT0();
        __syncthreads();

        // ---- Q fragments ----
        u32 qh[2][4], ql[2][4];
        #pragma unroll
        for (int kc = 0; kc < 2; kc++) {
            const u32 ch = (u32)((2*kc + (l >> 4)) ^ qsw);
            const u32 a  = QH + qrow*64 + ch*16;
            ldsm4(qh[kc], a);
            ldsm4(ql[kc], a + 2048);
        }

        float O[4][4] = {};
        float ls[2] = {0.f, 0.f};
        u32 buf = 0;

        while (cur >= 0) {
            // prefetch next valid tile into the other buffer, then compute
            const int nxt = next_tile(cur, mend, zq, y0q);
            if (nxt >= 0) {
                const u32 kvb = KV0 + (buf ^ 1) * 16384;
                for (int i = tid; i < 256; i += 128) {
                    const int row = i >> 2, ch = i & 3;
                    const u32 dst = kvb + (u32)(((row*4) + (ch ^ ((row >> 1) & 3))) * 16);
                    cpa16(dst,         gkh + (nxt+row)*HD + ch*8);
                    cpa16(dst + 4096,  gkl + (nxt+row)*HD + ch*8);
                    cpa16(dst + 8192,  gvh + (nxt+row)*HD + ch*8);
                    cpa16(dst + 12288, gvl + (nxt+row)*HD + ch*8);
                }
                CP_COMMIT();
            }

            const u32 KH = KV0 + buf * 16384;
            const u32 VH = KH + 8192;

            // ---- S = Q K^T (this warp's 32 keys, 3-term fp16) ----
            float S[4][4] = {};
            #pragma unroll
            for (int kc = 0; kc < 2; kc++) {
                #pragma unroll
                for (int jp = 0; jp < 2; jp++) {
                    u32 bh[4], bl[4];
                    const u32 a = KH + (u32)((khalf*2 + jp)*1024) + kbse + ck[kc];
                    ldsm4(bh, a);
                    ldsm4(bl, a + 4096);
                    mma16816(S[2*jp],   qh[kc], bh[0], bh[1]);
                    mma16816(S[2*jp],   qh[kc], bl[0], bl[1]);
                    mma16816(S[2*jp],   ql[kc], bh[0], bh[1]);
                    mma16816(S[2*jp+1], qh[kc], bh[2], bh[3]);
                    mma16816(S[2*jp+1], qh[kc], bl[2], bl[3]);
                    mma16816(S[2*jp+1], ql[kc], bh[2], bh[3]);
                }
            }

            // ---- mask + exp2 (dx^2 precomputed) ----
            const int dz   = zq - (cur >> 8);
            const int y0kw = ((cur >> 4) & 15) + khalf*2;
            const int thr  = 99 - dz*dz;
            #pragma unroll
            for (int j = 0; j < 4; j++) {
                const int par = j & 1, jj = j >> 1;
                const int yk = y0kw + jj;
                #pragma unroll
                for (int u = 0; u < 2; u++) {
                    const int dy = yq[u] - yk;
                    const int t2 = thr - dy*dy;
                    #pragma unroll
                    for (int cc = 0; cc < 2; cc++) {
                        float p = ex2f(S[j][2*u + cc]);
                        p = (dx2[u][par*2 + cc] <= t2) ? p : 0.f;
                        S[j][2*u + cc] = p;
                        ls[u] += p;
                    }
                }
            }

            // ---- O += P V (2-term: Ph*Vh + Ph*Vl) ----
            #pragma unroll
            for (int kc = 0; kc < 2; kc++) {
                u32 ph[4];
                #pragma unroll
                for (int hf = 0; hf < 2; hf++) {
                    const float* Pj = S[2*kc + hf];
                    ph[2*hf]   = pkhf(Pj[0], Pj[1]);
                    ph[2*hf+1] = pkhf(Pj[2], Pj[3]);
                }
                #pragma unroll
                for (int np = 0; np < 2; np++) {
                    u32 vh[4], vl[4];
                    const u32 a = VH + (u32)((khalf*2 + kc)*1024) + vbse + cv[np];
                    ldsm4t(vh, a);
                    ldsm4t(vl, a + 4096);
                    mma16816(O[2*np],   ph, vh[0], vh[1]);
                    mma16816(O[2*np],   ph, vl[0], vl[1]);
                    mma16816(O[2*np+1], ph, vh[2], vh[3]);
                    mma16816(O[2*np+1], ph, vl[2], vl[3]);
                }
            }

            // single sync per tile: prefetch data ready+visible, buffer safe
            CP_WAIT0();
            __syncthreads();
            buf ^= 1;
            cur = nxt;
        }

        // ---- combine key-half partials (khalf 1 -> khalf 0), then store ----
        float* red = (float*)sbuf;
        if (khalf == 1) {
            float* p = red + (qhalf*32 + l)*18;
            #pragma unroll
            for (int t4 = 0; t4 < 4; t4++)
                #pragma unroll
                for (int k = 0; k < 4; k++) p[t4*4 + k] = O[t4][k];
            p[16] = ls[0]; p[17] = ls[1];
        }
        __syncthreads();
        if (khalf == 0) {
            const float* p = red + (qhalf*32 + l)*18;
            #pragma unroll
            for (int t4 = 0; t4 < 4; t4++)
                #pragma unroll
                for (int k = 0; k < 4; k++) O[t4][k] += p[t4*4 + k];
            ls[0] += p[16]; ls[1] += p[17];

            #pragma unroll
            for (int u = 0; u < 2; u++) {
                ls[u] += __shfl_xor_sync(0xffffffffu, ls[u], 1);
                ls[u] += __shfl_xor_sync(0xffffffffu, ls[u], 2);
                const float inv = 1.0f / ls[u];
                const int row = n0 + qhalf*16 + g + 8*u;
                const int base = row*CDIM + h*HD;
                #pragma unroll
                for (int t4 = 0; t4 < 4; t4++) {
                    u32 hi, lo;
                    split2(O[t4][2*u] * inv, O[t4][2*u + 1] * inv, hi, lo);
                    const int ix = (base + 8*t4 + 2*tg) >> 1;
                    ((u32*)g_Th)[ix] = hi;
                    ((u32*)g_Tl)[ix] = lo;
                }
            }
        }
    }
}

// ---------------------------------------------------------------------------
// Kernel 3: proj GEMM on HMMA (f16 3-term). out[o][n] = T[n][:].pw[o][:] + b.
// Block = 64o x 64n, 128 threads. fp32 [C][N] output.
// ---------------------------------------------------------------------------
__global__ __launch_bounds__(128) void proj_mma(const float* __restrict__ bias,
                                                float* __restrict__ out) {
    __shared__ __align__(16) uint4 sbuf[2048];
    const int tid = threadIdx.x;
    const int w = tid >> 5, l = tid & 31;
    const int g = l >> 2, tg = l & 3;
    const int n0 = blockIdx.x * 64, o0 = blockIdx.y * 64;
    const int ob = w * 16;
    const u32 sb = smem_u32(sbuf);

    const int rowa = ob + (l & 15);
    const int swa  = ((l & 15) >> 1) & 3;
    const int rowk = (l & 7) + ((l >> 4) << 3);
    const u32 kbse = (u32)(rowk * 64);
    const int swk  = (rowk >> 1) & 3;
    const int chpk = (l >> 3) & 1;
    const u32 ck[2] = { (u32)(((0 + chpk) ^ swk) * 16),
                        (u32)(((2 + chpk) ^ swk) * 16) };

    float S[8][4] = {};

    {
        const int c0 = 0;
        for (int i = tid; i < 256; i += 128) {
            const int row = i >> 2, ch = i & 3;
            const u32 dst = sb + (u32)(((row*4) + (ch ^ ((row >> 1) & 3))) * 16);
            cpa16(dst,         g_PWh + (o0+row)*CDIM + c0 + ch*8);
            cpa16(dst + 4096,  g_PWl + (o0+row)*CDIM + c0 + ch*8);
            cpa16(dst + 8192,  g_Th  + (n0+row)*CDIM + c0 + ch*8);
            cpa16(dst + 12288, g_Tl  + (n0+row)*CDIM + c0 + ch*8);
        }
        CP_COMMIT();
    }

    for (int it = 0; it < 8; it++) {
        if (it < 7) {
            const int c0 = 32*(it + 1);
            const u32 boff = (u32)(((it + 1) & 1) * 16384);
            for (int i = tid; i < 256; i += 128) {
                const int row = i >> 2, ch = i & 3;
                const u32 dst = sb + boff + (u32)(((row*4) + (ch ^ ((row >> 1) & 3))) * 16);
                cpa16(dst,         g_PWh + (o0+row)*CDIM + c0 + ch*8);
                cpa16(dst + 4096,  g_PWl + (o0+row)*CDIM + c0 + ch*8);
                cpa16(dst + 8192,  g_Th  + (n0+row)*CDIM + c0 + ch*8);
                cpa16(dst + 12288, g_Tl  + (n0+row)*CDIM + c0 + ch*8);
            }
            CP_COMMIT();
            CP_WAIT1();
        } else {
            CP_WAIT0();
        }
        __syncthreads();
        const u32 cb = sb + (u32)((it & 1) * 16384);

        u32 ah[2][4], al[2][4];
        #pragma unroll
        for (int kc = 0; kc < 2; kc++) {
            const u32 ch = (u32)((2*kc + (l >> 4)) ^ swa);
            const u32 a = cb + (u32)(rowa*64) + ch*16;
            ldsm4(ah[kc], a);
            ldsm4(al[kc], a + 4096);
        }
        #pragma unroll
        for (int kc = 0; kc < 2; kc++) {
            #pragma unroll
            for (int jp = 0; jp < 4; jp++) {
                u32 bh[4], bl[4];
                const u32 a = cb + 8192 + (u32)(jp*1024) + kbse + ck[kc];
                ldsm4(bh, a);
                ldsm4(bl, a + 4096);
                mma16816(S[2*jp],   ah[kc], bh[0], bh[1]);
                mma16816(S[2*jp],   ah[kc], bl[0], bl[1]);
                mma16816(S[2*jp],   al[kc], bh[0], bh[1]);
                mma16816(S[2*jp+1], ah[kc], bh[2], bh[3]);
                mma16816(S[2*jp+1], ah[kc], bl[2], bl[3]);
                mma16816(S[2*jp+1], al[kc], bh[2], bh[3]);
            }
        }
        __syncthreads();
    }

    #pragma unroll
    for (int u = 0; u < 2; u++) {
        const int o = o0 + ob + g + 8*u;
        const float bo = bias[o];
        #pragma unroll
        for (int j = 0; j < 8; j++) {
            const int n = n0 + 16*(j >> 1) + 8*(j & 1) + 2*tg;
            float2 v;
            v.x = S[j][2*u]     + bo;
            v.y = S[j][2*u + 1] + bo;
            *(float2*)(out + (size_t)o*NTOK + n) = v;
        }
    }
}

// ---------------------------------------------------------------------------
extern "C" void kernel_launch(void* const* d_in, const int* in_sizes, int n_in,
                              void* d_out, int out_size) {
    const float *x = nullptr, *wq = nullptr, *wp = nullptr, *bp = nullptr;
    for (int i = 0; i < n_in; i++) {
        switch (in_sizes[i]) {
            case 1048576: x  = (const float*)d_in[i]; break;  // x [1,256,16,16,16]
            case 196608:  wq = (const float*)d_in[i]; break;  // qkv_w [768,256]
            case 65536:   wp = (const float*)d_in[i]; break;  // proj_w [256,256]
            case 256:     bp = (const float*)d_in[i]; break;  // proj_b [256]
        }
    }
    float* out = (float*)d_out;

    reset_ctr<<<1, 1>>>();
    conv_w  <<<768, 256>>>(wq, wp);
    xpose   <<<dim3(NTOK/64, CDIM/32), 256>>>(x);
    qkv_mma <<<dim3(NTOK/64, 768/64), 128>>>();
    attn_kernel<<<592, 128>>>();
    proj_mma<<<dim3(NTOK/64, CDIM/64), 128>>>(bp, out);
}

// round 13
// speedup vs baseline: 1.3655x; 1.1100x over previous
#include <cuda_runtime.h>
#include <cuda_fp16.h>

#define NTOK 4096
#define CDIM 256
#define NH   8
#define HD   32
// 1/sqrt(32) * log2(e): scores produced directly in log2 domain
#define QSCALE 0.2550181757638722f
#define NITEMS ((NTOK/32)*NH)   // 1024 attention work items

typedef unsigned int u32;
typedef unsigned long long u64;

// ---------------- helpers ----------------
__device__ __forceinline__ float ex2f(float x) {
    float r; asm("ex2.approx.ftz.f32 %0, %1;" : "=f"(r) : "f"(x)); return r;
}
// pack two floats to f16x2: lower 16 bits = f16(lo), upper = f16(hi)
__device__ __forceinline__ u32 pkhf(float lo, float hi) {
    u32 r; asm("cvt.rn.f16x2.f32 %0, %1, %2;" : "=r"(r) : "f"(hi), "f"(lo)); return r;
}
__device__ __forceinline__ float f16lo(u32 v) {
    float f; asm("{.reg .b16 h,x; mov.b32 {h,x}, %1; cvt.f32.f16 %0, h;}" : "=f"(f) : "r"(v)); return f;
}
__device__ __forceinline__ float f16hi(u32 v) {
    float f; asm("{.reg .b16 x,h; mov.b32 {x,h}, %1; cvt.f32.f16 %0, h;}" : "=f"(f) : "r"(v)); return f;
}
__device__ __forceinline__ void split2(float f0, float f1, u32& hi, u32& lo) {
    hi = pkhf(f0, f1);
    lo = pkhf(f0 - f16lo(hi), f1 - f16hi(hi));
}
__device__ __forceinline__ void mma16816(float* d, const u32* a, u32 b0, u32 b1) {
    asm volatile("mma.sync.aligned.m16n8k16.row.col.f32.f16.f16.f32 "
        "{%0,%1,%2,%3}, {%4,%5,%6,%7}, {%8,%9}, {%0,%1,%2,%3};"
        : "+f"(d[0]), "+f"(d[1]), "+f"(d[2]), "+f"(d[3])
        : "r"(a[0]), "r"(a[1]), "r"(a[2]), "r"(a[3]), "r"(b0), "r"(b1));
}
__device__ __forceinline__ void ldsm4(u32* r, u32 addr) {
    asm volatile("ldmatrix.sync.aligned.m8n8.x4.shared.b16 {%0,%1,%2,%3}, [%4];"
        : "=r"(r[0]), "=r"(r[1]), "=r"(r[2]), "=r"(r[3]) : "r"(addr));
}
__device__ __forceinline__ void ldsm4t(u32* r, u32 addr) {
    asm volatile("ldmatrix.sync.aligned.m8n8.x4.trans.shared.b16 {%0,%1,%2,%3}, [%4];"
        : "=r"(r[0]), "=r"(r[1]), "=r"(r[2]), "=r"(r[3]) : "r"(addr));
}
__device__ __forceinline__ u32 smem_u32(const void* p) {
    u32 a;
    asm("{ .reg .u64 t; cvta.to.shared.u64 t, %1; cvt.u32.u64 %0, t; }" : "=r"(a) : "l"(p));
    return a;
}
__device__ __forceinline__ void cpa16(u32 s, const void* g) {
    asm volatile("cp.async.cg.shared.global [%0], [%1], 16;" :: "r"(s), "l"(g));
}
#define CP_COMMIT() asm volatile("cp.async.commit_group;" ::: "memory")
#define CP_WAIT0()  asm volatile("cp.async.wait_group 0;" ::: "memory")
#define CP_WAIT1()  asm volatile("cp.async.wait_group 1;" ::: "memory")

// ---------------- scratch (device globals; no allocation allowed) ----------------
__device__ __align__(16) __half g_Xh[NTOK*CDIM];     // tok [n][c] hi
__device__ __align__(16) __half g_Xl[NTOK*CDIM];
__device__ __align__(16) __half g_Wh[3*CDIM*CDIM];   // qkv_w [o][c]
__device__ __align__(16) __half g_Wl[3*CDIM*CDIM];
__device__ __align__(16) __half g_PWh[CDIM*CDIM];    // proj_w [o][c]
__device__ __align__(16) __half g_PWl[CDIM*CDIM];
__device__ __align__(16) __half g_Qh[NH*NTOK*HD];    // [h][n][d] (pre-scaled)
__device__ __align__(16) __half g_Kh[NH*NTOK*HD];
__device__ __align__(16) __half g_Kl[NH*NTOK*HD];
__device__ __align__(16) __half g_Vh[NH*NTOK*HD];
__device__ __align__(16) __half g_Vl[NH*NTOK*HD];
__device__ __align__(16) __half g_Th[NTOK*CDIM];     // attn out [n][c]
__device__ __align__(16) __half g_Tl[NTOK*CDIM];

__device__ int g_ctr;                     // work-queue counter
// central-z first so the long items schedule first
__constant__ int c_ztab[16] = {7,8,6,9,5,10,4,11,3,12,2,13,1,14,0,15};

__global__ void reset_ctr() { g_ctr = 0; }

// ---------------------------------------------------------------------------
// Kernel 0a: split qkv_w and proj_w into f16 hi/lo
// ---------------------------------------------------------------------------
__global__ __launch_bounds__(256) void conv_w(const float* __restrict__ wq,
                                              const float* __restrict__ wp) {
    const int i = blockIdx.x * 256 + threadIdx.x;
    if (i < 3*CDIM*CDIM) {
        const float v = wq[i];
        const __half h = __float2half_rn(v);
        g_Wh[i] = h;
        g_Wl[i] = __float2half_rn(v - __half2float(h));
    }
    if (i < CDIM*CDIM) {
        const float v = wp[i];
        const __half h = __float2half_rn(v);
        g_PWh[i] = h;
        g_PWl[i] = __float2half_rn(v - __half2float(h));
    }
}

// ---------------------------------------------------------------------------
// Kernel 0b: transpose x [c][n] -> tok [n][c] with f16 hi/lo split
// ---------------------------------------------------------------------------
__global__ __launch_bounds__(256) void xpose(const float* __restrict__ x) {
    __shared__ float t[32][65];
    const int n0 = blockIdx.x * 64, c0 = blockIdx.y * 32;
    const int tid = threadIdx.x;
    #pragma unroll
    for (int i = tid; i < 2048; i += 256) {
        const int c = i >> 6, n = i & 63;
        t[c][n] = x[(c0 + c)*NTOK + n0 + n];
    }
    __syncthreads();
    const int n = tid >> 2, cg = (tid & 3) * 8;
    u32 hi[4], lo[4];
    #pragma unroll
    for (int k = 0; k < 4; k++)
        split2(t[cg + 2*k][n], t[cg + 2*k + 1][n], hi[k], lo[k]);
    const int ix = ((n0 + n)*CDIM + c0 + cg) >> 3;   // uint4 units (8 halves)
    ((uint4*)g_Xh)[ix] = make_uint4(hi[0], hi[1], hi[2], hi[3]);
    ((uint4*)g_Xl)[ix] = make_uint4(lo[0], lo[1], lo[2], lo[3]);
}

// ---------------------------------------------------------------------------
// Kernel 1: QKV GEMM on HMMA (f16 3-term split). Block = 64n x 64o, 128 thr.
// ---------------------------------------------------------------------------
__global__ __launch_bounds__(128) void qkv_mma() {
    __shared__ __align__(16) uint4 sbuf[2048];   // 2 buffers x 16KB (Ah,Al,Bh,Bl)
    const int tid = threadIdx.x;
    const int w = tid >> 5, l = tid & 31;
    const int g = l >> 2, tg = l & 3;
    const int n0 = blockIdx.x * 64, o0 = blockIdx.y * 64;
    const int qb = w * 16;
    const u32 sb = smem_u32(sbuf);

    const int rowa = qb + (l & 15);
    const int swa  = ((l & 15) >> 1) & 3;
    const int rowk = (l & 7) + ((l >> 4) << 3);
    const u32 kbse = (u32)(rowk * 64);
    const int swk  = (rowk >> 1) & 3;
    const int chpk = (l >> 3) & 1;
    const u32 ck[2] = { (u32)(((0 + chpk) ^ swk) * 16),
                        (u32)(((2 + chpk) ^ swk) * 16) };

    float S[8][4] = {};

    {
        const int c0 = 0;
        for (int i = tid; i < 256; i += 128) {
            const int row = i >> 2, ch = i & 3;
            const u32 dst = sb + (u32)(((row*4) + (ch ^ ((row >> 1) & 3))) * 16);
            cpa16(dst,         g_Xh + (n0+row)*CDIM + c0 + ch*8);
            cpa16(dst + 4096,  g_Xl + (n0+row)*CDIM + c0 + ch*8);
            cpa16(dst + 8192,  g_Wh + (o0+row)*CDIM + c0 + ch*8);
            cpa16(dst + 12288, g_Wl + (o0+row)*CDIM + c0 + ch*8);
        }
        CP_COMMIT();
    }

    for (int it = 0; it < 8; it++) {
        if (it < 7) {
            const int c0 = 32*(it + 1);
            const u32 boff = (u32)(((it + 1) & 1) * 16384);
            for (int i = tid; i < 256; i += 128) {
                const int row = i >> 2, ch = i & 3;
                const u32 dst = sb + boff + (u32)(((row*4) + (ch ^ ((row >> 1) & 3))) * 16);
                cpa16(dst,         g_Xh + (n0+row)*CDIM + c0 + ch*8);
                cpa16(dst + 4096,  g_Xl + (n0+row)*CDIM + c0 + ch*8);
                cpa16(dst + 8192,  g_Wh + (o0+row)*CDIM + c0 + ch*8);
                cpa16(dst + 12288, g_Wl + (o0+row)*CDIM + c0 + ch*8);
            }
            CP_COMMIT();
            CP_WAIT1();
        } else {
            CP_WAIT0();
        }
        __syncthreads();
        const u32 cb = sb + (u32)((it & 1) * 16384);

        u32 ah[2][4], al[2][4];
        #pragma unroll
        for (int kc = 0; kc < 2; kc++) {
            const u32 ch = (u32)((2*kc + (l >> 4)) ^ swa);
            const u32 a = cb + (u32)(rowa*64) + ch*16;
            ldsm4(ah[kc], a);
            ldsm4(al[kc], a + 4096);
        }
        #pragma unroll
        for (int kc = 0; kc < 2; kc++) {
            #pragma unroll
            for (int jp = 0; jp < 4; jp++) {
                u32 bh[4], bl[4];
                const u32 a = cb + 8192 + (u32)(jp*1024) + kbse + ck[kc];
                ldsm4(bh, a);
                ldsm4(bl, a + 4096);
                mma16816(S[2*jp],   ah[kc], bh[0], bh[1]);
                mma16816(S[2*jp],   ah[kc], bl[0], bl[1]);
                mma16816(S[2*jp],   al[kc], bh[0], bh[1]);
                mma16816(S[2*jp+1], ah[kc], bh[2], bh[3]);
                mma16816(S[2*jp+1], ah[kc], bl[2], bl[3]);
                mma16816(S[2*jp+1], al[kc], bh[2], bh[3]);
            }
        }
        __syncthreads();
    }

    const int t = o0 >> 8;
    #pragma unroll
    for (int j = 0; j < 8; j++) {
        const int o = o0 + 16*(j >> 1) + 8*(j & 1) + 2*tg;
        const int hh = (o >> 5) & 7, d = o & 31;
        #pragma unroll
        for (int u = 0; u < 2; u++) {
            const int n = n0 + qb + g + 8*u;
            float f0 = S[j][2*u], f1 = S[j][2*u + 1];
            if (t == 0) { f0 *= QSCALE; f1 *= QSCALE; }
            u32 hi, lo;
            split2(f0, f1, hi, lo);
            const int ix = ((hh*NTOK + n)*HD + d) >> 1;
            if (t == 0)      { ((u32*)g_Qh)[ix] = hi; }   // Q-lo unused downstream
            else if (t == 1) { ((u32*)g_Kh)[ix] = hi; ((u32*)g_Kl)[ix] = lo; }
            else             { ((u32*)g_Vh)[ix] = hi; ((u32*)g_Vl)[ix] = lo; }
        }
    }
}

// ---------------------------------------------------------------------------
// Kernel 2: HMMA flash attention, persistent work-queue, fp16 splits.
// S = 2-term (Qh*Kh + Qh*Kl); PV = 2-term (Ph*Vh + Ph*Vl).
// Grid = 592. Item = (32 queries, 1 head). Mask dist^2 <= 99.
// ---------------------------------------------------------------------------
__device__ __forceinline__ bool tile_ok(int m0, int zq, int y0q) {
    const int dz  = zq - (m0 >> 8);
    const int y0k = (m0 >> 4) & 15;
    int gap = y0k - (y0q + 1);
    const int g2 = y0q - (y0k + 3);
    if (g2 > gap) gap = g2;
    if (gap < 0) gap = 0;
    return dz*dz + gap*gap <= 99;
}
__device__ __forceinline__ int next_tile(int m0, int mend, int zq, int y0q) {
    for (m0 += 64; m0 <= mend; m0 += 64)
        if (tile_ok(m0, zq, y0q)) return m0;
    return -1;
}

__global__ __launch_bounds__(128, 4) void attn_kernel() {
    // Q: 2KB (hi only); two 16KB K/V buffers (KH,KL,VH,VL @ 4KB each)
    __shared__ __align__(16) uint4 sbuf[2176];   // 34 KB
    __shared__ int s_item;
    const int tid = threadIdx.x;
    const int w  = tid >> 5, l = tid & 31;
    const int g  = l >> 2, tg = l & 3;
    const int qhalf = w & 1;          // 16-row query group
    const int khalf = w >> 1;         // 32-key half of each tile

    const u32 sb = smem_u32(sbuf);
    const u32 QH = sb;                // 2KB
    const u32 KV0 = sb + 2048;        // buffer stride 16384

    // per-thread ldmatrix constants (item-independent)
    const int rowk = (l & 7) + ((l >> 4) << 3);
    const u32 kbse = (u32)(rowk * 64);
    const int swk  = (rowk >> 1) & 3;
    const int chpk = (l >> 3) & 1;
    const u32 ck[2] = { (u32)(((0 + chpk) ^ swk) * 16),
                        (u32)(((2 + chpk) ^ swk) * 16) };
    const int rowv = l & 15;
    const u32 vbse = (u32)(rowv * 64);
    const int swv  = (rowv >> 1) & 3;
    const int tbv  = l >> 4;
    const u32 cv[2] = { (u32)(((0 + tbv) ^ swv) * 16),
                        (u32)(((2 + tbv) ^ swv) * 16) };
    const int qrow = qhalf*16 + (l & 15);
    const int qsw  = ((l & 15) >> 1) & 3;

    for (;;) {
        __syncthreads();             // protect s_item + smem from prior item
        if (tid == 0) s_item = atomicAdd(&g_ctr, 1);
        __syncthreads();
        const int item = s_item;
        if (item >= NITEMS) break;

        const int h = item & 7;
        const int r = item >> 3;
        const int n0 = (c_ztab[r >> 3] * 8 + (r & 7)) * 32;

        const __half* gqh = g_Qh + h*NTOK*HD;
        const __half* gkh = g_Kh + h*NTOK*HD;
        const __half* gkl = g_Kl + h*NTOK*HD;
        const __half* gvh = g_Vh + h*NTOK*HD;
        const __half* gvl = g_Vl + h*NTOK*HD;

        const int zq  = n0 >> 8;
        const int y0q = (n0 >> 4) & 15;
        const int zlo = (zq - 9 < 0) ? 0 : zq - 9;
        const int zhi = (zq + 9 > 15) ? 15 : zq + 9;
        const int mend = zhi*256 + 192;

        int xq[2], yq[2];
        int dx2[2][4];               // tile-invariant mask terms
        #pragma unroll
        for (int u = 0; u < 2; u++) {
            const int nq = n0 + qhalf*16 + g + 8*u;
            xq[u] = nq & 15;
            yq[u] = (nq >> 4) & 15;
            #pragma unroll
            for (int pc = 0; pc < 4; pc++) {     // pc = par*2+cc
                const int dx = xq[u] - (2*tg + (pc & 1) + 8*(pc >> 1));
                dx2[u][pc] = dx*dx;
            }
        }

        // ---- prologue: Q + first K/V tile, one group ----
        int cur = tile_ok(zlo*256, zq, y0q) ? zlo*256
                                            : next_tile(zlo*256, mend, zq, y0q);
        if (tid < 128) {
            const int row = tid >> 2, ch = tid & 3;
            const u32 dst = QH + (u32)(((row*4) + (ch ^ ((row >> 1) & 3))) * 16);
            cpa16(dst, gqh + (n0+row)*HD + ch*8);
        }
        for (int i = tid; i < 256; i += 128) {
            const int row = i >> 2, ch = i & 3;
            const u32 dst = KV0 + (u32)(((row*4) + (ch ^ ((row >> 1) & 3))) * 16);
            cpa16(dst,         gkh + (cur+row)*HD + ch*8);
            cpa16(dst + 4096,  gkl + (cur+row)*HD + ch*8);
            cpa16(dst + 8192,  gvh + (cur+row)*HD + ch*8);
            cpa16(dst + 12288, gvl + (cur+row)*HD + ch*8);
        }
        CP_COMMIT();
        CP_WAIT0();
        __syncthreads();

        // ---- Q fragments (hi only) ----
        u32 qh[2][4];
        #pragma unroll
        for (int kc = 0; kc < 2; kc++) {
            const u32 ch = (u32)((2*kc + (l >> 4)) ^ qsw);
            ldsm4(qh[kc], QH + qrow*64 + ch*16);
        }

        float O[4][4] = {};
        float ls[2] = {0.f, 0.f};
        u32 buf = 0;

        while (cur >= 0) {
            // prefetch next valid tile into the other buffer, then compute
            const int nxt = next_tile(cur, mend, zq, y0q);
            if (nxt >= 0) {
                const u32 kvb = KV0 + (buf ^ 1) * 16384;
                for (int i = tid; i < 256; i += 128) {
                    const int row = i >> 2, ch = i & 3;
                    const u32 dst = kvb + (u32)(((row*4) + (ch ^ ((row >> 1) & 3))) * 16);
                    cpa16(dst,         gkh + (nxt+row)*HD + ch*8);
                    cpa16(dst + 4096,  gkl + (nxt+row)*HD + ch*8);
                    cpa16(dst + 8192,  gvh + (nxt+row)*HD + ch*8);
                    cpa16(dst + 12288, gvl + (nxt+row)*HD + ch*8);
                }
                CP_COMMIT();
            }

            const u32 KH = KV0 + buf * 16384;
            const u32 VH = KH + 8192;

            // ---- S = Q K^T (this warp's 32 keys, 2-term) ----
            float S[4][4] = {};
            #pragma unroll
            for (int kc = 0; kc < 2; kc++) {
                #pragma unroll
                for (int jp = 0; jp < 2; jp++) {
                    u32 bh[4], bl[4];
                    const u32 a = KH + (u32)((khalf*2 + jp)*1024) + kbse + ck[kc];
                    ldsm4(bh, a);
                    ldsm4(bl, a + 4096);
                    mma16816(S[2*jp],   qh[kc], bh[0], bh[1]);
                    mma16816(S[2*jp],   qh[kc], bl[0], bl[1]);
                    mma16816(S[2*jp+1], qh[kc], bh[2], bh[3]);
                    mma16816(S[2*jp+1], qh[kc], bl[2], bl[3]);
                }
            }

            // ---- mask + exp2 (dx^2 precomputed) ----
            const int dz   = zq - (cur >> 8);
            const int y0kw = ((cur >> 4) & 15) + khalf*2;
            const int thr  = 99 - dz*dz;
            #pragma unroll
            for (int j = 0; j < 4; j++) {
                const int par = j & 1, jj = j >> 1;
                const int yk = y0kw + jj;
                #pragma unroll
                for (int u = 0; u < 2; u++) {
                    const int dy = yq[u] - yk;
                    const int t2 = thr - dy*dy;
                    #pragma unroll
                    for (int cc = 0; cc < 2; cc++) {
                        float p = ex2f(S[j][2*u + cc]);
                        p = (dx2[u][par*2 + cc] <= t2) ? p : 0.f;
                        S[j][2*u + cc] = p;
                        ls[u] += p;
                    }
                }
            }

            // ---- O += P V (2-term: Ph*Vh + Ph*Vl) ----
            #pragma unroll
            for (int kc = 0; kc < 2; kc++) {
                u32 ph[4];
                #pragma unroll
                for (int hf = 0; hf < 2; hf++) {
                    const float* Pj = S[2*kc + hf];
                    ph[2*hf]   = pkhf(Pj[0], Pj[1]);
                    ph[2*hf+1] = pkhf(Pj[2], Pj[3]);
                }
                #pragma unroll
                for (int np = 0; np < 2; np++) {
                    u32 vh[4], vl[4];
                    const u32 a = VH + (u32)((khalf*2 + kc)*1024) + vbse + cv[np];
                    ldsm4t(vh, a);
                    ldsm4t(vl, a + 4096);
                    mma16816(O[2*np],   ph, vh[0], vh[1]);
                    mma16816(O[2*np],   ph, vl[0], vl[1]);
                    mma16816(O[2*np+1], ph, vh[2], vh[3]);
                    mma16816(O[2*np+1], ph, vl[2], vl[3]);
                }
            }

            // single sync per tile: prefetch data ready+visible, buffer safe
            CP_WAIT0();
            __syncthreads();
            buf ^= 1;
            cur = nxt;
        }

        // ---- combine key-half partials (khalf 1 -> khalf 0), then store ----
        float* red = (float*)sbuf;
        if (khalf == 1) {
            float* p = red + (qhalf*32 + l)*18;
            #pragma unroll
            for (int t4 = 0; t4 < 4; t4++)
                #pragma unroll
                for (int k = 0; k < 4; k++) p[t4*4 + k] = O[t4][k];
            p[16] = ls[0]; p[17] = ls[1];
        }
        __syncthreads();
        if (khalf == 0) {
            const float* p = red + (qhalf*32 + l)*18;
            #pragma unroll
            for (int t4 = 0; t4 < 4; t4++)
                #pragma unroll
                for (int k = 0; k < 4; k++) O[t4][k] += p[t4*4 + k];
            ls[0] += p[16]; ls[1] += p[17];

            #pragma unroll
            for (int u = 0; u < 2; u++) {
                ls[u] += __shfl_xor_sync(0xffffffffu, ls[u], 1);
                ls[u] += __shfl_xor_sync(0xffffffffu, ls[u], 2);
                const float inv = 1.0f / ls[u];
                const int row = n0 + qhalf*16 + g + 8*u;
                const int base = row*CDIM + h*HD;
                #pragma unroll
                for (int t4 = 0; t4 < 4; t4++) {
                    u32 hi, lo;
                    split2(O[t4][2*u] * inv, O[t4][2*u + 1] * inv, hi, lo);
                    const int ix = (base + 8*t4 + 2*tg) >> 1;
                    ((u32*)g_Th)[ix] = hi;
                    ((u32*)g_Tl)[ix] = lo;
                }
            }
        }
    }
}

// ---------------------------------------------------------------------------
// Kernel 3: proj GEMM on HMMA (f16 3-term). out[o][n] = T[n][:].pw[o][:] + b.
// Block = 64o x 64n, 128 threads. fp32 [C][N] output.
// ---------------------------------------------------------------------------
__global__ __launch_bounds__(128) void proj_mma(const float* __restrict__ bias,
                                                float* __restrict__ out) {
    __shared__ __align__(16) uint4 sbuf[2048];
    const int tid = threadIdx.x;
    const int w = tid >> 5, l = tid & 31;
    const int g = l >> 2, tg = l & 3;
    const int n0 = blockIdx.x * 64, o0 = blockIdx.y * 64;
    const int ob = w * 16;
    const u32 sb = smem_u32(sbuf);

    const int rowa = ob + (l & 15);
    const int swa  = ((l & 15) >> 1) & 3;
    const int rowk = (l & 7) + ((l >> 4) << 3);
    const u32 kbse = (u32)(rowk * 64);
    const int swk  = (rowk >> 1) & 3;
    const int chpk = (l >> 3) & 1;
    const u32 ck[2] = { (u32)(((0 + chpk) ^ swk) * 16),
                        (u32)(((2 + chpk) ^ swk) * 16) };

    float S[8][4] = {};

    {
        const int c0 = 0;
        for (int i = tid; i < 256; i += 128) {
            const int row = i >> 2, ch = i & 3;
            const u32 dst = sb + (u32)(((row*4) + (ch ^ ((row >> 1) & 3))) * 16);
            cpa16(dst,         g_PWh + (o0+row)*CDIM + c0 + ch*8);
            cpa16(dst + 4096,  g_PWl + (o0+row)*CDIM + c0 + ch*8);
            cpa16(dst + 8192,  g_Th  + (n0+row)*CDIM + c0 + ch*8);
            cpa16(dst + 12288, g_Tl  + (n0+row)*CDIM + c0 + ch*8);
        }
        CP_COMMIT();
    }

    for (int it = 0; it < 8; it++) {
        if (it < 7) {
            const int c0 = 32*(it + 1);
            const u32 boff = (u32)(((it + 1) & 1) * 16384);
            for (int i = tid; i < 256; i += 128) {
                const int row = i >> 2, ch = i & 3;
                const u32 dst = sb + boff + (u32)(((row*4) + (ch ^ ((row >> 1) & 3))) * 16);
                cpa16(dst,         g_PWh + (o0+row)*CDIM + c0 + ch*8);
                cpa16(dst + 4096,  g_PWl + (o0+row)*CDIM + c0 + ch*8);
                cpa16(dst + 8192,  g_Th  + (n0+row)*CDIM + c0 + ch*8);
                cpa16(dst + 12288, g_Tl  + (n0+row)*CDIM + c0 + ch*8);
            }
            CP_COMMIT();
            CP_WAIT1();
        } else {
            CP_WAIT0();
        }
        __syncthreads();
        const u32 cb = sb + (u32)((it & 1) * 16384);

        u32 ah[2][4], al[2][4];
        #pragma unroll
        for (int kc = 0; kc < 2; kc++) {
            const u32 ch = (u32)((2*kc + (l >> 4)) ^ swa);
            const u32 a = cb + (u32)(rowa*64) + ch*16;
            ldsm4(ah[kc], a);
            ldsm4(al[kc], a + 4096);
        }
        #pragma unroll
        for (int kc = 0; kc < 2; kc++) {
            #pragma unroll
            for (int jp = 0; jp < 4; jp++) {
                u32 bh[4], bl[4];
                const u32 a = cb + 8192 + (u32)(jp*1024) + kbse + ck[kc];
                ldsm4(bh, a);
                ldsm4(bl, a + 4096);
                mma16816(S[2*jp],   ah[kc], bh[0], bh[1]);
                mma16816(S[2*jp],   ah[kc], bl[0], bl[1]);
                mma16816(S[2*jp],   al[kc], bh[0], bh[1]);
                mma16816(S[2*jp+1], ah[kc], bh[2], bh[3]);
                mma16816(S[2*jp+1], ah[kc], bl[2], bl[3]);
                mma16816(S[2*jp+1], al[kc], bh[2], bh[3]);
            }
        }
        __syncthreads();
    }

    #pragma unroll
    for (int u = 0; u < 2; u++) {
        const int o = o0 + ob + g + 8*u;
        const float bo = bias[o];
        #pragma unroll
        for (int j = 0; j < 8; j++) {
            const int n = n0 + 16*(j >> 1) + 8*(j & 1) + 2*tg;
            float2 v;
            v.x = S[j][2*u]     + bo;
            v.y = S[j][2*u + 1] + bo;
            *(float2*)(out + (size_t)o*NTOK + n) = v;
        }
    }
}

// ---------------------------------------------------------------------------
extern "C" void kernel_launch(void* const* d_in, const int* in_sizes, int n_in,
                              void* d_out, int out_size) {
    const float *x = nullptr, *wq = nullptr, *wp = nullptr, *bp = nullptr;
    for (int i = 0; i < n_in; i++) {
        switch (in_sizes[i]) {
            case 1048576: x  = (const float*)d_in[i]; break;  // x [1,256,16,16,16]
            case 196608:  wq = (const float*)d_in[i]; break;  // qkv_w [768,256]
            case 65536:   wp = (const float*)d_in[i]; break;  // proj_w [256,256]
            case 256:     bp = (const float*)d_in[i]; break;  // proj_b [256]
        }
    }
    float* out = (float*)d_out;

    reset_ctr<<<1, 1>>>();
    conv_w  <<<768, 256>>>(wq, wp);
    xpose   <<<dim3(NTOK/64, CDIM/32), 256>>>(x);
    qkv_mma <<<dim3(NTOK/64, 768/64), 128>>>();
    attn_kernel<<<592, 128>>>();
    proj_mma<<<dim3(NTOK/64, CDIM/64), 128>>>(bp, out);
}

// round 14
// speedup vs baseline: 1.7676x; 1.2945x over previous
#include <cuda_runtime.h>
#include <cuda_fp16.h>

#define NTOK 4096
#define CDIM 256
#define NH   8
#define HD   32
// 1/sqrt(32) * log2(e): scores produced directly in log2 domain
#define QSCALE 0.2550181757638722f
#define NITEMS ((NTOK/32)*NH)   // 1024 attention work items

typedef unsigned int u32;
typedef unsigned long long u64;

// ---------------- helpers ----------------
__device__ __forceinline__ float ex2f(float x) {
    float r; asm("ex2.approx.ftz.f32 %0, %1;" : "=f"(r) : "f"(x)); return r;
}
// pack two floats to f16x2: lower 16 bits = f16(lo), upper = f16(hi)
__device__ __forceinline__ u32 pkhf(float lo, float hi) {
    u32 r; asm("cvt.rn.f16x2.f32 %0, %1, %2;" : "=r"(r) : "f"(hi), "f"(lo)); return r;
}
__device__ __forceinline__ float f16lo(u32 v) {
    float f; asm("{.reg .b16 h,x; mov.b32 {h,x}, %1; cvt.f32.f16 %0, h;}" : "=f"(f) : "r"(v)); return f;
}
__device__ __forceinline__ float f16hi(u32 v) {
    float f; asm("{.reg .b16 x,h; mov.b32 {x,h}, %1; cvt.f32.f16 %0, h;}" : "=f"(f) : "r"(v)); return f;
}
__device__ __forceinline__ void split2(float f0, float f1, u32& hi, u32& lo) {
    hi = pkhf(f0, f1);
    lo = pkhf(f0 - f16lo(hi), f1 - f16hi(hi));
}
__device__ __forceinline__ void mma16816(float* d, const u32* a, u32 b0, u32 b1) {
    asm volatile("mma.sync.aligned.m16n8k16.row.col.f32.f16.f16.f32 "
        "{%0,%1,%2,%3}, {%4,%5,%6,%7}, {%8,%9}, {%0,%1,%2,%3};"
        : "+f"(d[0]), "+f"(d[1]), "+f"(d[2]), "+f"(d[3])
        : "r"(a[0]), "r"(a[1]), "r"(a[2]), "r"(a[3]), "r"(b0), "r"(b1));
}
__device__ __forceinline__ void ldsm4(u32* r, u32 addr) {
    asm volatile("ldmatrix.sync.aligned.m8n8.x4.shared.b16 {%0,%1,%2,%3}, [%4];"
        : "=r"(r[0]), "=r"(r[1]), "=r"(r[2]), "=r"(r[3]) : "r"(addr));
}
__device__ __forceinline__ void ldsm4t(u32* r, u32 addr) {
    asm volatile("ldmatrix.sync.aligned.m8n8.x4.trans.shared.b16 {%0,%1,%2,%3}, [%4];"
        : "=r"(r[0]), "=r"(r[1]), "=r"(r[2]), "=r"(r[3]) : "r"(addr));
}
__device__ __forceinline__ u32 smem_u32(const void* p) {
    u32 a;
    asm("{ .reg .u64 t; cvta.to.shared.u64 t, %1; cvt.u32.u64 %0, t; }" : "=r"(a) : "l"(p));
    return a;
}
__device__ __forceinline__ void cpa16(u32 s, const void* g) {
    asm volatile("cp.async.cg.shared.global [%0], [%1], 16;" :: "r"(s), "l"(g));
}
#define CP_COMMIT() asm volatile("cp.async.commit_group;" ::: "memory")
#define CP_WAIT0()  asm volatile("cp.async.wait_group 0;" ::: "memory")
#define CP_WAIT1()  asm volatile("cp.async.wait_group 1;" ::: "memory")

// ---------------- scratch (device globals; no allocation allowed) ----------------
__device__ __align__(16) __half g_Xh[NTOK*CDIM];     // tok [n][c] hi
__device__ __align__(16) __half g_Xl[NTOK*CDIM];
__device__ __align__(16) __half g_Wh[3*CDIM*CDIM];   // qkv_w [o][c]
__device__ __align__(16) __half g_Wl[3*CDIM*CDIM];
__device__ __align__(16) __half g_PWh[CDIM*CDIM];    // proj_w [o][c]
__device__ __align__(16) __half g_PWl[CDIM*CDIM];
__device__ __align__(16) __half g_Qh[NH*NTOK*HD];    // [h][n][d] (pre-scaled)
__device__ __align__(16) __half g_Kh[NH*NTOK*HD];
__device__ __align__(16) __half g_Vh[NH*NTOK*HD];
__device__ __align__(16) __half g_Th[NTOK*CDIM];     // attn out [n][c]
__device__ __align__(16) __half g_Tl[NTOK*CDIM];

__device__ int g_ctr;                     // work-queue counter
// central-z first so the long items schedule first
__constant__ int c_ztab[16] = {7,8,6,9,5,10,4,11,3,12,2,13,1,14,0,15};

__global__ void reset_ctr() { g_ctr = 0; }

// ---------------------------------------------------------------------------
// Kernel 0a: split qkv_w and proj_w into f16 hi/lo
// ---------------------------------------------------------------------------
__global__ __launch_bounds__(256) void conv_w(const float* __restrict__ wq,
                                              const float* __restrict__ wp) {
    const int i = blockIdx.x * 256 + threadIdx.x;
    if (i < 3*CDIM*CDIM) {
        const float v = wq[i];
        const __half h = __float2half_rn(v);
        g_Wh[i] = h;
        g_Wl[i] = __float2half_rn(v - __half2float(h));
    }
    if (i < CDIM*CDIM) {
        const float v = wp[i];
        const __half h = __float2half_rn(v);
        g_PWh[i] = h;
        g_PWl[i] = __float2half_rn(v - __half2float(h));
    }
}

// ---------------------------------------------------------------------------
// Kernel 0b: transpose x [c][n] -> tok [n][c] with f16 hi/lo split
// ---------------------------------------------------------------------------
__global__ __launch_bounds__(256) void xpose(const float* __restrict__ x) {
    __shared__ float t[32][65];
    const int n0 = blockIdx.x * 64, c0 = blockIdx.y * 32;
    const int tid = threadIdx.x;
    #pragma unroll
    for (int i = tid; i < 2048; i += 256) {
        const int c = i >> 6, n = i & 63;
        t[c][n] = x[(c0 + c)*NTOK + n0 + n];
    }
    __syncthreads();
    const int n = tid >> 2, cg = (tid & 3) * 8;
    u32 hi[4], lo[4];
    #pragma unroll
    for (int k = 0; k < 4; k++)
        split2(t[cg + 2*k][n], t[cg + 2*k + 1][n], hi[k], lo[k]);
    const int ix = ((n0 + n)*CDIM + c0 + cg) >> 3;   // uint4 units (8 halves)
    ((uint4*)g_Xh)[ix] = make_uint4(hi[0], hi[1], hi[2], hi[3]);
    ((uint4*)g_Xl)[ix] = make_uint4(lo[0], lo[1], lo[2], lo[3]);
}

// ---------------------------------------------------------------------------
// Kernel 1: QKV GEMM on HMMA (f16 3-term split). Block = 64n x 64o, 128 thr.
// Epilogue stores Q/K/V hi only (attention is single-term fp16).
// ---------------------------------------------------------------------------
__global__ __launch_bounds__(128) void qkv_mma() {
    __shared__ __align__(16) uint4 sbuf[2048];   // 2 buffers x 16KB (Ah,Al,Bh,Bl)
    const int tid = threadIdx.x;
    const int w = tid >> 5, l = tid & 31;
    const int g = l >> 2, tg = l & 3;
    const int n0 = blockIdx.x * 64, o0 = blockIdx.y * 64;
    const int qb = w * 16;
    const u32 sb = smem_u32(sbuf);

    const int rowa = qb + (l & 15);
    const int swa  = ((l & 15) >> 1) & 3;
    const int rowk = (l & 7) + ((l >> 4) << 3);
    const u32 kbse = (u32)(rowk * 64);
    const int swk  = (rowk >> 1) & 3;
    const int chpk = (l >> 3) & 1;
    const u32 ck[2] = { (u32)(((0 + chpk) ^ swk) * 16),
                        (u32)(((2 + chpk) ^ swk) * 16) };

    float S[8][4] = {};

    {
        const int c0 = 0;
        for (int i = tid; i < 256; i += 128) {
            const int row = i >> 2, ch = i & 3;
            const u32 dst = sb + (u32)(((row*4) + (ch ^ ((row >> 1) & 3))) * 16);
            cpa16(dst,         g_Xh + (n0+row)*CDIM + c0 + ch*8);
            cpa16(dst + 4096,  g_Xl + (n0+row)*CDIM + c0 + ch*8);
            cpa16(dst + 8192,  g_Wh + (o0+row)*CDIM + c0 + ch*8);
            cpa16(dst + 12288, g_Wl + (o0+row)*CDIM + c0 + ch*8);
        }
        CP_COMMIT();
    }

    for (int it = 0; it < 8; it++) {
        if (it < 7) {
            const int c0 = 32*(it + 1);
            const u32 boff = (u32)(((it + 1) & 1) * 16384);
            for (int i = tid; i < 256; i += 128) {
                const int row = i >> 2, ch = i & 3;
                const u32 dst = sb + boff + (u32)(((row*4) + (ch ^ ((row >> 1) & 3))) * 16);
                cpa16(dst,         g_Xh + (n0+row)*CDIM + c0 + ch*8);
                cpa16(dst + 4096,  g_Xl + (n0+row)*CDIM + c0 + ch*8);
                cpa16(dst + 8192,  g_Wh + (o0+row)*CDIM + c0 + ch*8);
                cpa16(dst + 12288, g_Wl + (o0+row)*CDIM + c0 + ch*8);
            }
            CP_COMMIT();
            CP_WAIT1();
        } else {
            CP_WAIT0();
        }
        __syncthreads();
        const u32 cb = sb + (u32)((it & 1) * 16384);

        u32 ah[2][4], al[2][4];
        #pragma unroll
        for (int kc = 0; kc < 2; kc++) {
            const u32 ch = (u32)((2*kc + (l >> 4)) ^ swa);
            const u32 a = cb + (u32)(rowa*64) + ch*16;
            ldsm4(ah[kc], a);
            ldsm4(al[kc], a + 4096);
        }
        #pragma unroll
        for (int kc = 0; kc < 2; kc++) {
            #pragma unroll
            for (int jp = 0; jp < 4; jp++) {
                u32 bh[4], bl[4];
                const u32 a = cb + 8192 + (u32)(jp*1024) + kbse + ck[kc];
                ldsm4(bh, a);
                ldsm4(bl, a + 4096);
                mma16816(S[2*jp],   ah[kc], bh[0], bh[1]);
                mma16816(S[2*jp],   ah[kc], bl[0], bl[1]);
                mma16816(S[2*jp],   al[kc], bh[0], bh[1]);
                mma16816(S[2*jp+1], ah[kc], bh[2], bh[3]);
                mma16816(S[2*jp+1], ah[kc], bl[2], bl[3]);
                mma16816(S[2*jp+1], al[kc], bh[2], bh[3]);
            }
        }
        __syncthreads();
    }

    const int t = o0 >> 8;
    #pragma unroll
    for (int j = 0; j < 8; j++) {
        const int o = o0 + 16*(j >> 1) + 8*(j & 1) + 2*tg;
        const int hh = (o >> 5) & 7, d = o & 31;
        #pragma unroll
        for (int u = 0; u < 2; u++) {
            const int n = n0 + qb + g + 8*u;
            float f0 = S[j][2*u], f1 = S[j][2*u + 1];
            if (t == 0) { f0 *= QSCALE; f1 *= QSCALE; }
            const u32 hi = pkhf(f0, f1);
            const int ix = ((hh*NTOK + n)*HD + d) >> 1;
            if (t == 0)      ((u32*)g_Qh)[ix] = hi;
            else if (t == 1) ((u32*)g_Kh)[ix] = hi;
            else             ((u32*)g_Vh)[ix] = hi;
        }
    }
}

// ---------------------------------------------------------------------------
// Kernel 2: HMMA flash attention, persistent work-queue, pure fp16 (1-term).
// Grid = 592. Item = (32 queries, 1 head). Mask dist^2 <= 99.
// Warp w: query rows (w&1)*16.., key half (w>>1)*32 of each 64-key tile.
// ---------------------------------------------------------------------------
__device__ __forceinline__ bool tile_ok(int m0, int zq, int y0q) {
    const int dz  = zq - (m0 >> 8);
    const int y0k = (m0 >> 4) & 15;
    int gap = y0k - (y0q + 1);
    const int g2 = y0q - (y0k + 3);
    if (g2 > gap) gap = g2;
    if (gap < 0) gap = 0;
    return dz*dz + gap*gap <= 99;
}
__device__ __forceinline__ int next_tile(int m0, int mend, int zq, int y0q) {
    for (m0 += 64; m0 <= mend; m0 += 64)
        if (tile_ok(m0, zq, y0q)) return m0;
    return -1;
}

__global__ __launch_bounds__(128, 5) void attn_kernel() {
    // Q: 2KB (hi only); two 8KB K/V buffers (KH 4KB + VH 4KB)
    __shared__ __align__(16) uint4 sbuf[1152];   // 18 KB
    __shared__ int s_item;
    const int tid = threadIdx.x;
    const int w  = tid >> 5, l = tid & 31;
    const int g  = l >> 2, tg = l & 3;
    const int qhalf = w & 1;          // 16-row query group
    const int khalf = w >> 1;         // 32-key half of each tile

    const u32 sb = smem_u32(sbuf);
    const u32 QH = sb;                // 2KB
    const u32 KV0 = sb + 2048;        // buffer stride 8192

    // per-thread ldmatrix constants (item-independent)
    const int rowk = (l & 7) + ((l >> 4) << 3);
    const u32 kbse = (u32)(rowk * 64);
    const int swk  = (rowk >> 1) & 3;
    const int chpk = (l >> 3) & 1;
    const u32 ck[2] = { (u32)(((0 + chpk) ^ swk) * 16),
                        (u32)(((2 + chpk) ^ swk) * 16) };
    const int rowv = l & 15;
    const u32 vbse = (u32)(rowv * 64);
    const int swv  = (rowv >> 1) & 3;
    const int tbv  = l >> 4;
    const u32 cv[2] = { (u32)(((0 + tbv) ^ swv) * 16),
                        (u32)(((2 + tbv) ^ swv) * 16) };
    const int qrow = qhalf*16 + (l & 15);
    const int qsw  = ((l & 15) >> 1) & 3;

    for (;;) {
        __syncthreads();             // protect s_item + smem from prior item
        if (tid == 0) s_item = atomicAdd(&g_ctr, 1);
        __syncthreads();
        const int item = s_item;
        if (item >= NITEMS) break;

        const int h = item & 7;
        const int r = item >> 3;
        const int n0 = (c_ztab[r >> 3] * 8 + (r & 7)) * 32;

        const __half* gqh = g_Qh + h*NTOK*HD;
        const __half* gkh = g_Kh + h*NTOK*HD;
        const __half* gvh = g_Vh + h*NTOK*HD;

        const int zq  = n0 >> 8;
        const int y0q = (n0 >> 4) & 15;
        const int zlo = (zq - 9 < 0) ? 0 : zq - 9;
        const int zhi = (zq + 9 > 15) ? 15 : zq + 9;
        const int mend = zhi*256 + 192;

        int xq[2], yq[2];
        int dx2[2][4];               // tile-invariant mask terms
        #pragma unroll
        for (int u = 0; u < 2; u++) {
            const int nq = n0 + qhalf*16 + g + 8*u;
            xq[u] = nq & 15;
            yq[u] = (nq >> 4) & 15;
            #pragma unroll
            for (int pc = 0; pc < 4; pc++) {     // pc = par*2+cc
                const int dx = xq[u] - (2*tg + (pc & 1) + 8*(pc >> 1));
                dx2[u][pc] = dx*dx;
            }
        }

        // ---- prologue: Q + first K/V tile, one group ----
        int cur = tile_ok(zlo*256, zq, y0q) ? zlo*256
                                            : next_tile(zlo*256, mend, zq, y0q);
        {
            const int row = tid >> 2, ch = tid & 3;
            const u32 dst = QH + (u32)(((row*4) + (ch ^ ((row >> 1) & 3))) * 16);
            cpa16(dst, gqh + (n0+row)*HD + ch*8);
        }
        for (int i = tid; i < 256; i += 128) {
            const int row = i >> 2, ch = i & 3;
            const u32 dst = KV0 + (u32)(((row*4) + (ch ^ ((row >> 1) & 3))) * 16);
            cpa16(dst,        gkh + (cur+row)*HD + ch*8);
            cpa16(dst + 4096, gvh + (cur+row)*HD + ch*8);
        }
        CP_COMMIT();
        CP_WAIT0();
        __syncthreads();

        // ---- Q fragments (hi only) ----
        u32 qh[2][4];
        #pragma unroll
        for (int kc = 0; kc < 2; kc++) {
            const u32 ch = (u32)((2*kc + (l >> 4)) ^ qsw);
            ldsm4(qh[kc], QH + qrow*64 + ch*16);
        }

        float O[4][4] = {};
        float ls[2] = {0.f, 0.f};
        u32 buf = 0;

        while (cur >= 0) {
            // prefetch next valid tile into the other buffer, then compute
            const int nxt = next_tile(cur, mend, zq, y0q);
            if (nxt >= 0) {
                const u32 kvb = KV0 + (buf ^ 1) * 8192;
                for (int i = tid; i < 256; i += 128) {
                    const int row = i >> 2, ch = i & 3;
                    const u32 dst = kvb + (u32)(((row*4) + (ch ^ ((row >> 1) & 3))) * 16);
                    cpa16(dst,        gkh + (nxt+row)*HD + ch*8);
                    cpa16(dst + 4096, gvh + (nxt+row)*HD + ch*8);
                }
                CP_COMMIT();
            }

            const u32 KH = KV0 + buf * 8192;
            const u32 VH = KH + 4096;

            // ---- S = Q K^T (this warp's 32 keys, single-term) ----
            float S[4][4] = {};
            #pragma unroll
            for (int kc = 0; kc < 2; kc++) {
                #pragma unroll
                for (int jp = 0; jp < 2; jp++) {
                    u32 bh[4];
                    ldsm4(bh, KH + (u32)((khalf*2 + jp)*1024) + kbse + ck[kc]);
                    mma16816(S[2*jp],   qh[kc], bh[0], bh[1]);
                    mma16816(S[2*jp+1], qh[kc], bh[2], bh[3]);
                }
            }

            // ---- mask + exp2 (dx^2 precomputed) ----
            const int dz   = zq - (cur >> 8);
            const int y0kw = ((cur >> 4) & 15) + khalf*2;
            const int thr  = 99 - dz*dz;
            #pragma unroll
            for (int j = 0; j < 4; j++) {
                const int par = j & 1, jj = j >> 1;
                const int yk = y0kw + jj;
                #pragma unroll
                for (int u = 0; u < 2; u++) {
                    const int dy = yq[u] - yk;
                    const int t2 = thr - dy*dy;
                    #pragma unroll
                    for (int cc = 0; cc < 2; cc++) {
                        float p = ex2f(S[j][2*u + cc]);
                        p = (dx2[u][par*2 + cc] <= t2) ? p : 0.f;
                        S[j][2*u + cc] = p;
                        ls[u] += p;
                    }
                }
            }

            // ---- O += P V (single-term) ----
            #pragma unroll
            for (int kc = 0; kc < 2; kc++) {
                u32 ph[4];
                #pragma unroll
                for (int hf = 0; hf < 2; hf++) {
                    const float* Pj = S[2*kc + hf];
                    ph[2*hf]   = pkhf(Pj[0], Pj[1]);
                    ph[2*hf+1] = pkhf(Pj[2], Pj[3]);
                }
                #pragma unroll
                for (int np = 0; np < 2; np++) {
                    u32 vh[4];
                    ldsm4t(vh, VH + (u32)((khalf*2 + kc)*1024) + vbse + cv[np]);
                    mma16816(O[2*np],   ph, vh[0], vh[1]);
                    mma16816(O[2*np+1], ph, vh[2], vh[3]);
                }
            }

            // single sync per tile: prefetch data ready+visible, buffer safe
            CP_WAIT0();
            __syncthreads();
            buf ^= 1;
            cur = nxt;
        }

        // ---- combine key-half partials (khalf 1 -> khalf 0), then store ----
        float* red = (float*)sbuf;
        if (khalf == 1) {
            float* p = red + (qhalf*32 + l)*18;
            #pragma unroll
            for (int t4 = 0; t4 < 4; t4++)
                #pragma unroll
                for (int k = 0; k < 4; k++) p[t4*4 + k] = O[t4][k];
            p[16] = ls[0]; p[17] = ls[1];
        }
        __syncthreads();
        if (khalf == 0) {
            const float* p = red + (qhalf*32 + l)*18;
            #pragma unroll
            for (int t4 = 0; t4 < 4; t4++)
                #pragma unroll
                for (int k = 0; k < 4; k++) O[t4][k] += p[t4*4 + k];
            ls[0] += p[16]; ls[1] += p[17];

            #pragma unroll
            for (int u = 0; u < 2; u++) {
                ls[u] += __shfl_xor_sync(0xffffffffu, ls[u], 1);
                ls[u] += __shfl_xor_sync(0xffffffffu, ls[u], 2);
                const float inv = 1.0f / ls[u];
                const int row = n0 + qhalf*16 + g + 8*u;
                const int base = row*CDIM + h*HD;
                #pragma unroll
                for (int t4 = 0; t4 < 4; t4++) {
                    u32 hi, lo;
                    split2(O[t4][2*u] * inv, O[t4][2*u + 1] * inv, hi, lo);
                    const int ix = (base + 8*t4 + 2*tg) >> 1;
                    ((u32*)g_Th)[ix] = hi;
                    ((u32*)g_Tl)[ix] = lo;
                }
            }
        }
    }
}

// ---------------------------------------------------------------------------
// Kernel 3: proj GEMM on HMMA (f16 3-term). out[o][n] = T[n][:].pw[o][:] + b.
// Block = 64o x 64n, 128 threads. fp32 [C][N] output.
// ---------------------------------------------------------------------------
__global__ __launch_bounds__(128) void proj_mma(const float* __restrict__ bias,
                                                float* __restrict__ out) {
    __shared__ __align__(16) uint4 sbuf[2048];
    const int tid = threadIdx.x;
    const int w = tid >> 5, l = tid & 31;
    const int g = l >> 2, tg = l & 3;
    const int n0 = blockIdx.x * 64, o0 = blockIdx.y * 64;
    const int ob = w * 16;
    const u32 sb = smem_u32(sbuf);

    const int rowa = ob + (l & 15);
    const int swa  = ((l & 15) >> 1) & 3;
    const int rowk = (l & 7) + ((l >> 4) << 3);
    const u32 kbse = (u32)(rowk * 64);
    const int swk  = (rowk >> 1) & 3;
    const int chpk = (l >> 3) & 1;
    const u32 ck[2] = { (u32)(((0 + chpk) ^ swk) * 16),
                        (u32)(((2 + chpk) ^ swk) * 16) };

    float S[8][4] = {};

    {
        const int c0 = 0;
        for (int i = tid; i < 256; i += 128) {
            const int row = i >> 2, ch = i & 3;
            const u32 dst = sb + (u32)(((row*4) + (ch ^ ((row >> 1) & 3))) * 16);
            cpa16(dst,         g_PWh + (o0+row)*CDIM + c0 + ch*8);
            cpa16(dst + 4096,  g_PWl + (o0+row)*CDIM + c0 + ch*8);
            cpa16(dst + 8192,  g_Th  + (n0+row)*CDIM + c0 + ch*8);
            cpa16(dst + 12288, g_Tl  + (n0+row)*CDIM + c0 + ch*8);
        }
        CP_COMMIT();
    }

    for (int it = 0; it < 8; it++) {
        if (it < 7) {
            const int c0 = 32*(it + 1);
            const u32 boff = (u32)(((it + 1) & 1) * 16384);
            for (int i = tid; i < 256; i += 128) {
                const int row = i >> 2, ch = i & 3;
                const u32 dst = sb + boff + (u32)(((row*4) + (ch ^ ((row >> 1) & 3))) * 16);
                cpa16(dst,         g_PWh + (o0+row)*CDIM + c0 + ch*8);
                cpa16(dst + 4096,  g_PWl + (o0+row)*CDIM + c0 + ch*8);
                cpa16(dst + 8192,  g_Th  + (n0+row)*CDIM + c0 + ch*8);
                cpa16(dst + 12288, g_Tl  + (n0+row)*CDIM + c0 + ch*8);
            }
            CP_COMMIT();
            CP_WAIT1();
        } else {
            CP_WAIT0();
        }
        __syncthreads();
        const u32 cb = sb + (u32)((it & 1) * 16384);

        u32 ah[2][4], al[2][4];
        #pragma unroll
        for (int kc = 0; kc < 2; kc++) {
            const u32 ch = (u32)((2*kc + (l >> 4)) ^ swa);
            const u32 a = cb + (u32)(rowa*64) + ch*16;
            ldsm4(ah[kc], a);
            ldsm4(al[kc], a + 4096);
        }
        #pragma unroll
        for (int kc = 0; kc < 2; kc++) {
            #pragma unroll
            for (int jp = 0; jp < 4; jp++) {
                u32 bh[4], bl[4];
                const u32 a = cb + 8192 + (u32)(jp*1024) + kbse + ck[kc];
                ldsm4(bh, a);
                ldsm4(bl, a + 4096);
                mma16816(S[2*jp],   ah[kc], bh[0], bh[1]);
                mma16816(S[2*jp],   ah[kc], bl[0], bl[1]);
                mma16816(S[2*jp],   al[kc], bh[0], bh[1]);
                mma16816(S[2*jp+1], ah[kc], bh[2], bh[3]);
                mma16816(S[2*jp+1], ah[kc], bl[2], bl[3]);
                mma16816(S[2*jp+1], al[kc], bh[2], bh[3]);
            }
        }
        __syncthreads();
    }

    #pragma unroll
    for (int u = 0; u < 2; u++) {
        const int o = o0 + ob + g + 8*u;
        const float bo = bias[o];
        #pragma unroll
        for (int j = 0; j < 8; j++) {
            const int n = n0 + 16*(j >> 1) + 8*(j & 1) + 2*tg;
            float2 v;
            v.x = S[j][2*u]     + bo;
            v.y = S[j][2*u + 1] + bo;
            *(float2*)(out + (size_t)o*NTOK + n) = v;
        }
    }
}

// ---------------------------------------------------------------------------
extern "C" void kernel_launch(void* const* d_in, const int* in_sizes, int n_in,
                              void* d_out, int out_size) {
    const float *x = nullptr, *wq = nullptr, *wp = nullptr, *bp = nullptr;
    for (int i = 0; i < n_in; i++) {
        switch (in_sizes[i]) {
            case 1048576: x  = (const float*)d_in[i]; break;  // x [1,256,16,16,16]
            case 196608:  wq = (const float*)d_in[i]; break;  // qkv_w [768,256]
            case 65536:   wp = (const float*)d_in[i]; break;  // proj_w [256,256]
            case 256:     bp = (const float*)d_in[i]; break;  // proj_b [256]
        }
    }
    float* out = (float*)d_out;

    reset_ctr<<<1, 1>>>();
    conv_w  <<<768, 256>>>(wq, wp);
    xpose   <<<dim3(NTOK/64, CDIM/32), 256>>>(x);
    qkv_mma <<<dim3(NTOK/64, 768/64), 128>>>();
    attn_kernel<<<592, 128>>>();
    proj_mma<<<dim3(NTOK/64, CDIM/64), 128>>>(bp, out);
}

// round 15
// speedup vs baseline: 1.9024x; 1.0763x over previous
#include <cuda_runtime.h>
#include <cuda_fp16.h>

#define NTOK 4096
#define CDIM 256
#define NH   8
#define HD   32
// 1/sqrt(32) * log2(e): scores produced directly in log2 domain
#define QSCALE 0.2550181757638722f
#define NITEMS ((NTOK/32)*NH)   // 1024 attention work items

typedef unsigned int u32;
typedef unsigned long long u64;

// ---------------- helpers ----------------
__device__ __forceinline__ float ex2f(float x) {
    float r; asm("ex2.approx.ftz.f32 %0, %1;" : "=f"(r) : "f"(x)); return r;
}
// pack two floats to f16x2: lower 16 bits = f16(lo), upper = f16(hi)
__device__ __forceinline__ u32 pkhf(float lo, float hi) {
    u32 r; asm("cvt.rn.f16x2.f32 %0, %1, %2;" : "=r"(r) : "f"(hi), "f"(lo)); return r;
}
__device__ __forceinline__ void mma16816(float* d, const u32* a, u32 b0, u32 b1) {
    asm volatile("mma.sync.aligned.m16n8k16.row.col.f32.f16.f16.f32 "
        "{%0,%1,%2,%3}, {%4,%5,%6,%7}, {%8,%9}, {%0,%1,%2,%3};"
        : "+f"(d[0]), "+f"(d[1]), "+f"(d[2]), "+f"(d[3])
        : "r"(a[0]), "r"(a[1]), "r"(a[2]), "r"(a[3]), "r"(b0), "r"(b1));
}
__device__ __forceinline__ void ldsm4(u32* r, u32 addr) {
    asm volatile("ldmatrix.sync.aligned.m8n8.x4.shared.b16 {%0,%1,%2,%3}, [%4];"
        : "=r"(r[0]), "=r"(r[1]), "=r"(r[2]), "=r"(r[3]) : "r"(addr));
}
__device__ __forceinline__ void ldsm4t(u32* r, u32 addr) {
    asm volatile("ldmatrix.sync.aligned.m8n8.x4.trans.shared.b16 {%0,%1,%2,%3}, [%4];"
        : "=r"(r[0]), "=r"(r[1]), "=r"(r[2]), "=r"(r[3]) : "r"(addr));
}
__device__ __forceinline__ u32 smem_u32(const void* p) {
    u32 a;
    asm("{ .reg .u64 t; cvta.to.shared.u64 t, %1; cvt.u32.u64 %0, t; }" : "=r"(a) : "l"(p));
    return a;
}
__device__ __forceinline__ void cpa16(u32 s, const void* g) {
    asm volatile("cp.async.cg.shared.global [%0], [%1], 16;" :: "r"(s), "l"(g));
}
#define CP_COMMIT() asm volatile("cp.async.commit_group;" ::: "memory")
#define CP_WAIT0()  asm volatile("cp.async.wait_group 0;" ::: "memory")
#define CP_WAIT1()  asm volatile("cp.async.wait_group 1;" ::: "memory")

// ---------------- scratch (device globals; no allocation allowed) ----------------
__device__ __align__(16) __half g_X [NTOK*CDIM];     // tok [n][c] fp16
__device__ __align__(16) __half g_Wh[3*CDIM*CDIM];   // qkv_w [o][c] hi
__device__ __align__(16) __half g_Wl[3*CDIM*CDIM];   // qkv_w lo residual
__device__ __align__(16) __half g_PWh[CDIM*CDIM];    // proj_w [o][c] hi
__device__ __align__(16) __half g_PWl[CDIM*CDIM];    // proj_w lo residual
__device__ __align__(16) __half g_Qh[NH*NTOK*HD];    // [h][n][d] (pre-scaled)
__device__ __align__(16) __half g_Kh[NH*NTOK*HD];
__device__ __align__(16) __half g_Vh[NH*NTOK*HD];
__device__ __align__(16) __half g_Th[NTOK*CDIM];     // attn out [n][c] fp16

__device__ int g_ctr;                     // work-queue counter
// central-z first so the long items schedule first
__constant__ int c_ztab[16] = {7,8,6,9,5,10,4,11,3,12,2,13,1,14,0,15};

// ---------------------------------------------------------------------------
// Kernel 0a: split qkv_w and proj_w into f16 hi/lo (+ reset work counter)
// ---------------------------------------------------------------------------
__global__ __launch_bounds__(256) void conv_w(const float* __restrict__ wq,
                                              const float* __restrict__ wp) {
    const int i = blockIdx.x * 256 + threadIdx.x;
    if (i == 0) g_ctr = 0;
    if (i < 3*CDIM*CDIM) {
        const float v = wq[i];
        const __half h = __float2half_rn(v);
        g_Wh[i] = h;
        g_Wl[i] = __float2half_rn(v - __half2float(h));
    }
    if (i < CDIM*CDIM) {
        const float v = wp[i];
        const __half h = __float2half_rn(v);
        g_PWh[i] = h;
        g_PWl[i] = __float2half_rn(v - __half2float(h));
    }
}

// ---------------------------------------------------------------------------
// Kernel 0b: transpose x [c][n] -> tok [n][c], fp16
// ---------------------------------------------------------------------------
__global__ __launch_bounds__(256) void xpose(const float* __restrict__ x) {
    __shared__ float t[32][65];
    const int n0 = blockIdx.x * 64, c0 = blockIdx.y * 32;
    const int tid = threadIdx.x;
    #pragma unroll
    for (int i = tid; i < 2048; i += 256) {
        const int c = i >> 6, n = i & 63;
        t[c][n] = x[(c0 + c)*NTOK + n0 + n];
    }
    __syncthreads();
    const int n = tid >> 2, cg = (tid & 3) * 8;
    u32 hi[4];
    #pragma unroll
    for (int k = 0; k < 4; k++)
        hi[k] = pkhf(t[cg + 2*k][n], t[cg + 2*k + 1][n]);
    const int ix = ((n0 + n)*CDIM + c0 + cg) >> 3;   // uint4 units (8 halves)
    ((uint4*)g_X)[ix] = make_uint4(hi[0], hi[1], hi[2], hi[3]);
}

// ---------------------------------------------------------------------------
// Kernel 1: QKV GEMM on HMMA. A = X (fp16), B = W hi/lo (2-term).
// Block = 64n x 64o, 128 threads (4 warps x 16n). cp.async double-buffered.
// ---------------------------------------------------------------------------
__global__ __launch_bounds__(128) void qkv_mma() {
    __shared__ __align__(16) uint4 sbuf[1536];   // 2 buffers x 12KB (A,Bh,Bl)
    const int tid = threadIdx.x;
    const int w = tid >> 5, l = tid & 31;
    const int g = l >> 2, tg = l & 3;
    const int n0 = blockIdx.x * 64, o0 = blockIdx.y * 64;
    const int qb = w * 16;
    const u32 sb = smem_u32(sbuf);

    const int rowa = qb + (l & 15);
    const int swa  = ((l & 15) >> 1) & 3;
    const int rowk = (l & 7) + ((l >> 4) << 3);
    const u32 kbse = (u32)(rowk * 64);
    const int swk  = (rowk >> 1) & 3;
    const int chpk = (l >> 3) & 1;
    const u32 ck[2] = { (u32)(((0 + chpk) ^ swk) * 16),
                        (u32)(((2 + chpk) ^ swk) * 16) };

    float S[8][4] = {};

    {
        const int c0 = 0;
        for (int i = tid; i < 256; i += 128) {
            const int row = i >> 2, ch = i & 3;
            const u32 dst = sb + (u32)(((row*4) + (ch ^ ((row >> 1) & 3))) * 16);
            cpa16(dst,        g_X  + (n0+row)*CDIM + c0 + ch*8);
            cpa16(dst + 4096, g_Wh + (o0+row)*CDIM + c0 + ch*8);
            cpa16(dst + 8192, g_Wl + (o0+row)*CDIM + c0 + ch*8);
        }
        CP_COMMIT();
    }

    for (int it = 0; it < 8; it++) {
        if (it < 7) {
            const int c0 = 32*(it + 1);
            const u32 boff = (u32)(((it + 1) & 1) * 12288);
            for (int i = tid; i < 256; i += 128) {
                const int row = i >> 2, ch = i & 3;
                const u32 dst = sb + boff + (u32)(((row*4) + (ch ^ ((row >> 1) & 3))) * 16);
                cpa16(dst,        g_X  + (n0+row)*CDIM + c0 + ch*8);
                cpa16(dst + 4096, g_Wh + (o0+row)*CDIM + c0 + ch*8);
                cpa16(dst + 8192, g_Wl + (o0+row)*CDIM + c0 + ch*8);
            }
            CP_COMMIT();
            CP_WAIT1();
        } else {
            CP_WAIT0();
        }
        __syncthreads();
        const u32 cb = sb + (u32)((it & 1) * 12288);

        u32 ah[2][4];
        #pragma unroll
        for (int kc = 0; kc < 2; kc++) {
            const u32 ch = (u32)((2*kc + (l >> 4)) ^ swa);
            ldsm4(ah[kc], cb + (u32)(rowa*64) + ch*16);
        }
        #pragma unroll
        for (int kc = 0; kc < 2; kc++) {
            #pragma unroll
            for (int jp = 0; jp < 4; jp++) {
                u32 bh[4], bl[4];
                const u32 a = cb + 4096 + (u32)(jp*1024) + kbse + ck[kc];
                ldsm4(bh, a);
                ldsm4(bl, a + 4096);
                mma16816(S[2*jp],   ah[kc], bh[0], bh[1]);
                mma16816(S[2*jp],   ah[kc], bl[0], bl[1]);
                mma16816(S[2*jp+1], ah[kc], bh[2], bh[3]);
                mma16816(S[2*jp+1], ah[kc], bl[2], bl[3]);
            }
        }
        __syncthreads();
    }

    const int t = o0 >> 8;
    #pragma unroll
    for (int j = 0; j < 8; j++) {
        const int o = o0 + 16*(j >> 1) + 8*(j & 1) + 2*tg;
        const int hh = (o >> 5) & 7, d = o & 31;
        #pragma unroll
        for (int u = 0; u < 2; u++) {
            const int n = n0 + qb + g + 8*u;
            float f0 = S[j][2*u], f1 = S[j][2*u + 1];
            if (t == 0) { f0 *= QSCALE; f1 *= QSCALE; }
            const u32 hi = pkhf(f0, f1);
            const int ix = ((hh*NTOK + n)*HD + d) >> 1;
            if (t == 0)      ((u32*)g_Qh)[ix] = hi;
            else if (t == 1) ((u32*)g_Kh)[ix] = hi;
            else             ((u32*)g_Vh)[ix] = hi;
        }
    }
}

// ---------------------------------------------------------------------------
// Kernel 2: HMMA flash attention, persistent work-queue, pure fp16 (1-term).
// Grid = 592. Item = (32 queries, 1 head). Mask dist^2 <= 99.
// Warp w: query rows (w&1)*16.., key half (w>>1)*32 of each 64-key tile.
// ---------------------------------------------------------------------------
__device__ __forceinline__ bool tile_ok(int m0, int zq, int y0q) {
    const int dz  = zq - (m0 >> 8);
    const int y0k = (m0 >> 4) & 15;
    int gap = y0k - (y0q + 1);
    const int g2 = y0q - (y0k + 3);
    if (g2 > gap) gap = g2;
    if (gap < 0) gap = 0;
    return dz*dz + gap*gap <= 99;
}
__device__ __forceinline__ int next_tile(int m0, int mend, int zq, int y0q) {
    for (m0 += 64; m0 <= mend; m0 += 64)
        if (tile_ok(m0, zq, y0q)) return m0;
    return -1;
}

__global__ __launch_bounds__(128, 5) void attn_kernel() {
    // Q: 2KB; two 8KB K/V buffers (KH 4KB + VH 4KB)
    __shared__ __align__(16) uint4 sbuf[1152];   // 18 KB
    __shared__ int s_item;
    const int tid = threadIdx.x;
    const int w  = tid >> 5, l = tid & 31;
    const int g  = l >> 2, tg = l & 3;
    const int qhalf = w & 1;          // 16-row query group
    const int khalf = w >> 1;         // 32-key half of each tile

    const u32 sb = smem_u32(sbuf);
    const u32 QH = sb;                // 2KB
    const u32 KV0 = sb + 2048;        // buffer stride 8192

    // per-thread ldmatrix constants (item-independent)
    const int rowk = (l & 7) + ((l >> 4) << 3);
    const u32 kbse = (u32)(rowk * 64);
    const int swk  = (rowk >> 1) & 3;
    const int chpk = (l >> 3) & 1;
    const u32 ck[2] = { (u32)(((0 + chpk) ^ swk) * 16),
                        (u32)(((2 + chpk) ^ swk) * 16) };
    const int rowv = l & 15;
    const u32 vbse = (u32)(rowv * 64);
    const int swv  = (rowv >> 1) & 3;
    const int tbv  = l >> 4;
    const u32 cv[2] = { (u32)(((0 + tbv) ^ swv) * 16),
                        (u32)(((2 + tbv) ^ swv) * 16) };
    const int qrow = qhalf*16 + (l & 15);
    const int qsw  = ((l & 15) >> 1) & 3;

    for (;;) {
        __syncthreads();             // protect s_item + smem from prior item
        if (tid == 0) s_item = atomicAdd(&g_ctr, 1);
        __syncthreads();
        const int item = s_item;
        if (item >= NITEMS) break;

        const int h = item & 7;
        const int r = item >> 3;
        const int n0 = (c_ztab[r >> 3] * 8 + (r & 7)) * 32;

        const __half* gqh = g_Qh + h*NTOK*HD;
        const __half* gkh = g_Kh + h*NTOK*HD;
        const __half* gvh = g_Vh + h*NTOK*HD;

        const int zq  = n0 >> 8;
        const int y0q = (n0 >> 4) & 15;
        const int zlo = (zq - 9 < 0) ? 0 : zq - 9;
        const int zhi = (zq + 9 > 15) ? 15 : zq + 9;
        const int mend = zhi*256 + 192;

        int xq[2], yq[2];
        int dx2[2][4];               // tile-invariant mask terms
        #pragma unroll
        for (int u = 0; u < 2; u++) {
            const int nq = n0 + qhalf*16 + g + 8*u;
            xq[u] = nq & 15;
            yq[u] = (nq >> 4) & 15;
            #pragma unroll
            for (int pc = 0; pc < 4; pc++) {     // pc = par*2+cc
                const int dx = xq[u] - (2*tg + (pc & 1) + 8*(pc >> 1));
                dx2[u][pc] = dx*dx;
            }
        }

        // ---- prologue: Q + first K/V tile, one group ----
        int cur = tile_ok(zlo*256, zq, y0q) ? zlo*256
                                            : next_tile(zlo*256, mend, zq, y0q);
        {
            const int row = tid >> 2, ch = tid & 3;
            const u32 dst = QH + (u32)(((row*4) + (ch ^ ((row >> 1) & 3))) * 16);
            cpa16(dst, gqh + (n0+row)*HD + ch*8);
        }
        for (int i = tid; i < 256; i += 128) {
            const int row = i >> 2, ch = i & 3;
            const u32 dst = KV0 + (u32)(((row*4) + (ch ^ ((row >> 1) & 3))) * 16);
            cpa16(dst,        gkh + (cur+row)*HD + ch*8);
            cpa16(dst + 4096, gvh + (cur+row)*HD + ch*8);
        }
        CP_COMMIT();
        CP_WAIT0();
        __syncthreads();

        // ---- Q fragments ----
        u32 qh[2][4];
        #pragma unroll
        for (int kc = 0; kc < 2; kc++) {
            const u32 ch = (u32)((2*kc + (l >> 4)) ^ qsw);
            ldsm4(qh[kc], QH + qrow*64 + ch*16);
        }

        float O[4][4] = {};
        float ls[2] = {0.f, 0.f};
        u32 buf = 0;

        while (cur >= 0) {
            // prefetch next valid tile into the other buffer, then compute
            const int nxt = next_tile(cur, mend, zq, y0q);
            if (nxt >= 0) {
                const u32 kvb = KV0 + (buf ^ 1) * 8192;
                for (int i = tid; i < 256; i += 128) {
                    const int row = i >> 2, ch = i & 3;
                    const u32 dst = kvb + (u32)(((row*4) + (ch ^ ((row >> 1) & 3))) * 16);
                    cpa16(dst,        gkh + (nxt+row)*HD + ch*8);
                    cpa16(dst + 4096, gvh + (nxt+row)*HD + ch*8);
                }
                CP_COMMIT();
            }

            const u32 KH = KV0 + buf * 8192;
            const u32 VH = KH + 4096;

            // ---- S = Q K^T (this warp's 32 keys, single-term) ----
            float S[4][4] = {};
            #pragma unroll
            for (int kc = 0; kc < 2; kc++) {
                #pragma unroll
                for (int jp = 0; jp < 2; jp++) {
                    u32 bh[4];
                    ldsm4(bh, KH + (u32)((khalf*2 + jp)*1024) + kbse + ck[kc]);
                    mma16816(S[2*jp],   qh[kc], bh[0], bh[1]);
                    mma16816(S[2*jp+1], qh[kc], bh[2], bh[3]);
                }
            }

            // ---- mask + exp2 (dx^2 precomputed) ----
            const int dz   = zq - (cur >> 8);
            const int y0kw = ((cur >> 4) & 15) + khalf*2;
            const int thr  = 99 - dz*dz;
            #pragma unroll
            for (int j = 0; j < 4; j++) {
                const int par = j & 1, jj = j >> 1;
                const int yk = y0kw + jj;
                #pragma unroll
                for (int u = 0; u < 2; u++) {
                    const int dy = yq[u] - yk;
                    const int t2 = thr - dy*dy;
                    #pragma unroll
                    for (int cc = 0; cc < 2; cc++) {
                        float p = ex2f(S[j][2*u + cc]);
                        p = (dx2[u][par*2 + cc] <= t2) ? p : 0.f;
                        S[j][2*u + cc] = p;
                        ls[u] += p;
                    }
                }
            }

            // ---- O += P V (single-term) ----
            #pragma unroll
            for (int kc = 0; kc < 2; kc++) {
                u32 ph[4];
                #pragma unroll
                for (int hf = 0; hf < 2; hf++) {
                    const float* Pj = S[2*kc + hf];
                    ph[2*hf]   = pkhf(Pj[0], Pj[1]);
                    ph[2*hf+1] = pkhf(Pj[2], Pj[3]);
                }
                #pragma unroll
                for (int np = 0; np < 2; np++) {
                    u32 vh[4];
                    ldsm4t(vh, VH + (u32)((khalf*2 + kc)*1024) + vbse + cv[np]);
                    mma16816(O[2*np],   ph, vh[0], vh[1]);
                    mma16816(O[2*np+1], ph, vh[2], vh[3]);
                }
            }

            // single sync per tile: prefetch data ready+visible, buffer safe
            CP_WAIT0();
            __syncthreads();
            buf ^= 1;
            cur = nxt;
        }

        // ---- combine key-half partials (khalf 1 -> khalf 0), then store ----
        float* red = (float*)sbuf;
        if (khalf == 1) {
            float* p = red + (qhalf*32 + l)*18;
            #pragma unroll
            for (int t4 = 0; t4 < 4; t4++)
                #pragma unroll
                for (int k = 0; k < 4; k++) p[t4*4 + k] = O[t4][k];
            p[16] = ls[0]; p[17] = ls[1];
        }
        __syncthreads();
        if (khalf == 0) {
            const float* p = red + (qhalf*32 + l)*18;
            #pragma unroll
            for (int t4 = 0; t4 < 4; t4++)
                #pragma unroll
                for (int k = 0; k < 4; k++) O[t4][k] += p[t4*4 + k];
            ls[0] += p[16]; ls[1] += p[17];

            #pragma unroll
            for (int u = 0; u < 2; u++) {
                ls[u] += __shfl_xor_sync(0xffffffffu, ls[u], 1);
                ls[u] += __shfl_xor_sync(0xffffffffu, ls[u], 2);
                const float inv = 1.0f / ls[u];
                const int row = n0 + qhalf*16 + g + 8*u;
                const int base = row*CDIM + h*HD;
                #pragma unroll
                for (int t4 = 0; t4 < 4; t4++) {
                    const u32 hi = pkhf(O[t4][2*u] * inv, O[t4][2*u + 1] * inv);
                    ((u32*)g_Th)[(base + 8*t4 + 2*tg) >> 1] = hi;
                }
            }
        }
    }
}

// ---------------------------------------------------------------------------
// Kernel 3: proj GEMM on HMMA. A = PW hi/lo (2-term), B = T (fp16).
// Block = 64o x 64n, 128 threads. fp32 [C][N] output with fused bias.
// ---------------------------------------------------------------------------
__global__ __launch_bounds__(128) void proj_mma(const float* __restrict__ bias,
                                                float* __restrict__ out) {
    __shared__ __align__(16) uint4 sbuf[1536];   // 2 buffers x 12KB (Ah,Al,B)
    const int tid = threadIdx.x;
    const int w = tid >> 5, l = tid & 31;
    const int g = l >> 2, tg = l & 3;
    const int n0 = blockIdx.x * 64, o0 = blockIdx.y * 64;
    const int ob = w * 16;
    const u32 sb = smem_u32(sbuf);

    const int rowa = ob + (l & 15);
    const int swa  = ((l & 15) >> 1) & 3;
    const int rowk = (l & 7) + ((l >> 4) << 3);
    const u32 kbse = (u32)(rowk * 64);
    const int swk  = (rowk >> 1) & 3;
    const int chpk = (l >> 3) & 1;
    const u32 ck[2] = { (u32)(((0 + chpk) ^ swk) * 16),
                        (u32)(((2 + chpk) ^ swk) * 16) };

    float S[8][4] = {};

    {
        const int c0 = 0;
        for (int i = tid; i < 256; i += 128) {
            const int row = i >> 2, ch = i & 3;
            const u32 dst = sb + (u32)(((row*4) + (ch ^ ((row >> 1) & 3))) * 16);
            cpa16(dst,        g_PWh + (o0+row)*CDIM + c0 + ch*8);
            cpa16(dst + 4096, g_PWl + (o0+row)*CDIM + c0 + ch*8);
            cpa16(dst + 8192, g_Th  + (n0+row)*CDIM + c0 + ch*8);
        }
        CP_COMMIT();
    }

    for (int it = 0; it < 8; it++) {
        if (it < 7) {
            const int c0 = 32*(it + 1);
            const u32 boff = (u32)(((it + 1) & 1) * 12288);
            for (int i = tid; i < 256; i += 128) {
                const int row = i >> 2, ch = i & 3;
                const u32 dst = sb + boff + (u32)(((row*4) + (ch ^ ((row >> 1) & 3))) * 16);
                cpa16(dst,        g_PWh + (o0+row)*CDIM + c0 + ch*8);
                cpa16(dst + 4096, g_PWl + (o0+row)*CDIM + c0 + ch*8);
                cpa16(dst + 8192, g_Th  + (n0+row)*CDIM + c0 + ch*8);
            }
            CP_COMMIT();
            CP_WAIT1();
        } else {
            CP_WAIT0();
        }
        __syncthreads();
        const u32 cb = sb + (u32)((it & 1) * 12288);

        u32 ah[2][4], al[2][4];
        #pragma unroll
        for (int kc = 0; kc < 2; kc++) {
            const u32 ch = (u32)((2*kc + (l >> 4)) ^ swa);
            const u32 a = cb + (u32)(rowa*64) + ch*16;
            ldsm4(ah[kc], a);
            ldsm4(al[kc], a + 4096);
        }
        #pragma unroll
        for (int kc = 0; kc < 2; kc++) {
            #pragma unroll
            for (int jp = 0; jp < 4; jp++) {
                u32 bh[4];
                ldsm4(bh, cb + 8192 + (u32)(jp*1024) + kbse + ck[kc]);
                mma16816(S[2*jp],   ah[kc], bh[0], bh[1]);
                mma16816(S[2*jp],   al[kc], bh[0], bh[1]);
                mma16816(S[2*jp+1], ah[kc], bh[2], bh[3]);
                mma16816(S[2*jp+1], al[kc], bh[2], bh[3]);
            }
        }
        __syncthreads();
    }

    #pragma unroll
    for (int u = 0; u < 2; u++) {
        const int o = o0 + ob + g + 8*u;
        const float bo = bias[o];
        #pragma unroll
        for (int j = 0; j < 8; j++) {
            const int n = n0 + 16*(j >> 1) + 8*(j & 1) + 2*tg;
            float2 v;
            v.x = S[j][2*u]     + bo;
            v.y = S[j][2*u + 1] + bo;
            *(float2*)(out + (size_t)o*NTOK + n) = v;
        }
    }
}

// ---------------------------------------------------------------------------
extern "C" void kernel_launch(void* const* d_in, const int* in_sizes, int n_in,
                              void* d_out, int out_size) {
    const float *x = nullptr, *wq = nullptr, *wp = nullptr, *bp = nullptr;
    for (int i = 0; i < n_in; i++) {
        switch (in_sizes[i]) {
            case 1048576: x  = (const float*)d_in[i]; break;  // x [1,256,16,16,16]
            case 196608:  wq = (const float*)d_in[i]; break;  // qkv_w [768,256]
            case 65536:   wp = (const float*)d_in[i]; break;  // proj_w [256,256]
            case 256:     bp = (const float*)d_in[i]; break;  // proj_b [256]
        }
    }
    float* out = (float*)d_out;

    conv_w  <<<768, 256>>>(wq, wp);
    xpose   <<<dim3(NTOK/64, CDIM/32), 256>>>(x);
    qkv_mma <<<dim3(NTOK/64, 768/64), 128>>>();
    attn_kernel<<<592, 128>>>();
    proj_mma<<<dim3(NTOK/64, CDIM/64), 128>>>(bp, out);
}

// round 16
// speedup vs baseline: 2.1433x; 1.1266x over previous
#include <cuda_runtime.h>
#include <cuda_fp16.h>

#define NTOK 4096
#define CDIM 256
#define NH   8
#define HD   32
// 1/sqrt(32) * log2(e): scores produced directly in log2 domain
#define QSCALE 0.2550181757638722f
#define NITEMS ((NTOK/32)*NH)   // 1024 attention work items

typedef unsigned int u32;
typedef unsigned long long u64;

// ---------------- helpers ----------------
__device__ __forceinline__ float ex2f(float x) {
    float r; asm("ex2.approx.ftz.f32 %0, %1;" : "=f"(r) : "f"(x)); return r;
}
// pack two floats to f16x2: lower 16 bits = f16(lo), upper = f16(hi)
__device__ __forceinline__ u32 pkhf(float lo, float hi) {
    u32 r; asm("cvt.rn.f16x2.f32 %0, %1, %2;" : "=r"(r) : "f"(hi), "f"(lo)); return r;
}
__device__ __forceinline__ void mma16816(float* d, const u32* a, u32 b0, u32 b1) {
    asm volatile("mma.sync.aligned.m16n8k16.row.col.f32.f16.f16.f32 "
        "{%0,%1,%2,%3}, {%4,%5,%6,%7}, {%8,%9}, {%0,%1,%2,%3};"
        : "+f"(d[0]), "+f"(d[1]), "+f"(d[2]), "+f"(d[3])
        : "r"(a[0]), "r"(a[1]), "r"(a[2]), "r"(a[3]), "r"(b0), "r"(b1));
}
__device__ __forceinline__ void ldsm4(u32* r, u32 addr) {
    asm volatile("ldmatrix.sync.aligned.m8n8.x4.shared.b16 {%0,%1,%2,%3}, [%4];"
        : "=r"(r[0]), "=r"(r[1]), "=r"(r[2]), "=r"(r[3]) : "r"(addr));
}
__device__ __forceinline__ void ldsm4t(u32* r, u32 addr) {
    asm volatile("ldmatrix.sync.aligned.m8n8.x4.trans.shared.b16 {%0,%1,%2,%3}, [%4];"
        : "=r"(r[0]), "=r"(r[1]), "=r"(r[2]), "=r"(r[3]) : "r"(addr));
}
__device__ __forceinline__ u32 smem_u32(const void* p) {
    u32 a;
    asm("{ .reg .u64 t; cvta.to.shared.u64 t, %1; cvt.u32.u64 %0, t; }" : "=r"(a) : "l"(p));
    return a;
}
__device__ __forceinline__ void cpa16(u32 s, const void* g) {
    asm volatile("cp.async.cg.shared.global [%0], [%1], 16;" :: "r"(s), "l"(g));
}
#define CP_COMMIT() asm volatile("cp.async.commit_group;" ::: "memory")
#define CP_WAIT0()  asm volatile("cp.async.wait_group 0;" ::: "memory")
#define CP_WAIT1()  asm volatile("cp.async.wait_group 1;" ::: "memory")

// ---------------- scratch (device globals; no allocation allowed) ----------------
__device__ __align__(16) __half g_X [NTOK*CDIM];     // tok [n][c] fp16
__device__ __align__(16) __half g_Wh[3*CDIM*CDIM];   // qkv_w [o][c] hi
__device__ __align__(16) __half g_Wl[3*CDIM*CDIM];   // qkv_w lo residual
__device__ __align__(16) __half g_PWh[CDIM*CDIM];    // proj_w [o][c] hi
__device__ __align__(16) __half g_PWl[CDIM*CDIM];    // proj_w lo residual
__device__ __align__(16) __half g_Qh[NH*NTOK*HD];    // [h][n][d] (pre-scaled)
__device__ __align__(16) __half g_Kh[NH*NTOK*HD];
__device__ __align__(16) __half g_Vh[NH*NTOK*HD];
__device__ __align__(16) __half g_Th[NTOK*CDIM];     // attn out [n][c] fp16

__device__ int g_ctr;                     // work-queue counter
// central-z first so the long items schedule first
__constant__ int c_ztab[16] = {7,8,6,9,5,10,4,11,3,12,2,13,1,14,0,15};

// ---------------------------------------------------------------------------
// Kernel 0a: split qkv_w and proj_w into f16 hi/lo (+ reset work counter)
// ---------------------------------------------------------------------------
__global__ __launch_bounds__(256) void conv_w(const float* __restrict__ wq,
                                              const float* __restrict__ wp) {
    const int i = blockIdx.x * 256 + threadIdx.x;
    if (i == 0) g_ctr = 0;
    if (i < 3*CDIM*CDIM) {
        const float v = wq[i];
        const __half h = __float2half_rn(v);
        g_Wh[i] = h;
        g_Wl[i] = __float2half_rn(v - __half2float(h));
    }
    if (i < CDIM*CDIM) {
        const float v = wp[i];
        const __half h = __float2half_rn(v);
        g_PWh[i] = h;
        g_PWl[i] = __float2half_rn(v - __half2float(h));
    }
}

// ---------------------------------------------------------------------------
// Kernel 0b: transpose x [c][n] -> tok [n][c], fp16
// ---------------------------------------------------------------------------
__global__ __launch_bounds__(256) void xpose(const float* __restrict__ x) {
    __shared__ float t[32][65];
    const int n0 = blockIdx.x * 64, c0 = blockIdx.y * 32;
    const int tid = threadIdx.x;
    #pragma unroll
    for (int i = tid; i < 2048; i += 256) {
        const int c = i >> 6, n = i & 63;
        t[c][n] = x[(c0 + c)*NTOK + n0 + n];
    }
    __syncthreads();
    const int n = tid >> 2, cg = (tid & 3) * 8;
    u32 hi[4];
    #pragma unroll
    for (int k = 0; k < 4; k++)
        hi[k] = pkhf(t[cg + 2*k][n], t[cg + 2*k + 1][n]);
    const int ix = ((n0 + n)*CDIM + c0 + cg) >> 3;   // uint4 units (8 halves)
    ((uint4*)g_X)[ix] = make_uint4(hi[0], hi[1], hi[2], hi[3]);
}

// ---------------------------------------------------------------------------
// Kernel 1: QKV GEMM on HMMA. A = X (fp16), B = W hi/lo (2-term).
// Block = 64n x 64o, 128 threads (4 warps x 16n). cp.async double-buffered.
// ---------------------------------------------------------------------------
__global__ __launch_bounds__(128) void qkv_mma() {
    __shared__ __align__(16) uint4 sbuf[1536];   // 2 buffers x 12KB (A,Bh,Bl)
    const int tid = threadIdx.x;
    const int w = tid >> 5, l = tid & 31;
    const int g = l >> 2, tg = l & 3;
    const int n0 = blockIdx.x * 64, o0 = blockIdx.y * 64;
    const int qb = w * 16;
    const u32 sb = smem_u32(sbuf);

    const int rowa = qb + (l & 15);
    const int swa  = ((l & 15) >> 1) & 3;
    const int rowk = (l & 7) + ((l >> 4) << 3);
    const u32 kbse = (u32)(rowk * 64);
    const int swk  = (rowk >> 1) & 3;
    const int chpk = (l >> 3) & 1;
    const u32 ck[2] = { (u32)(((0 + chpk) ^ swk) * 16),
                        (u32)(((2 + chpk) ^ swk) * 16) };

    float S[8][4] = {};

    {
        const int c0 = 0;
        for (int i = tid; i < 256; i += 128) {
            const int row = i >> 2, ch = i & 3;
            const u32 dst = sb + (u32)(((row*4) + (ch ^ ((row >> 1) & 3))) * 16);
            cpa16(dst,        g_X  + (n0+row)*CDIM + c0 + ch*8);
            cpa16(dst + 4096, g_Wh + (o0+row)*CDIM + c0 + ch*8);
            cpa16(dst + 8192, g_Wl + (o0+row)*CDIM + c0 + ch*8);
        }
        CP_COMMIT();
    }

    for (int it = 0; it < 8; it++) {
        if (it < 7) {
            const int c0 = 32*(it + 1);
            const u32 boff = (u32)(((it + 1) & 1) * 12288);
            for (int i = tid; i < 256; i += 128) {
                const int row = i >> 2, ch = i & 3;
                const u32 dst = sb + boff + (u32)(((row*4) + (ch ^ ((row >> 1) & 3))) * 16);
                cpa16(dst,        g_X  + (n0+row)*CDIM + c0 + ch*8);
                cpa16(dst + 4096, g_Wh + (o0+row)*CDIM + c0 + ch*8);
                cpa16(dst + 8192, g_Wl + (o0+row)*CDIM + c0 + ch*8);
            }
            CP_COMMIT();
            CP_WAIT1();
        } else {
            CP_WAIT0();
        }
        __syncthreads();
        const u32 cb = sb + (u32)((it & 1) * 12288);

        u32 ah[2][4];
        #pragma unroll
        for (int kc = 0; kc < 2; kc++) {
            const u32 ch = (u32)((2*kc + (l >> 4)) ^ swa);
            ldsm4(ah[kc], cb + (u32)(rowa*64) + ch*16);
        }
        #pragma unroll
        for (int kc = 0; kc < 2; kc++) {
            #pragma unroll
            for (int jp = 0; jp < 4; jp++) {
                u32 bh[4], bl[4];
                const u32 a = cb + 4096 + (u32)(jp*1024) + kbse + ck[kc];
                ldsm4(bh, a);
                ldsm4(bl, a + 4096);
                mma16816(S[2*jp],   ah[kc], bh[0], bh[1]);
                mma16816(S[2*jp],   ah[kc], bl[0], bl[1]);
                mma16816(S[2*jp+1], ah[kc], bh[2], bh[3]);
                mma16816(S[2*jp+1], ah[kc], bl[2], bl[3]);
            }
        }
        __syncthreads();
    }

    const int t = o0 >> 8;
    #pragma unroll
    for (int j = 0; j < 8; j++) {
        const int o = o0 + 16*(j >> 1) + 8*(j & 1) + 2*tg;
        const int hh = (o >> 5) & 7, d = o & 31;
        #pragma unroll
        for (int u = 0; u < 2; u++) {
            const int n = n0 + qb + g + 8*u;
            float f0 = S[j][2*u], f1 = S[j][2*u + 1];
            if (t == 0) { f0 *= QSCALE; f1 *= QSCALE; }
            const u32 hi = pkhf(f0, f1);
            const int ix = ((hh*NTOK + n)*HD + d) >> 1;
            if (t == 0)      ((u32*)g_Qh)[ix] = hi;
            else if (t == 1) ((u32*)g_Kh)[ix] = hi;
            else             ((u32*)g_Vh)[ix] = hi;
        }
    }
}

// ---------------------------------------------------------------------------
// Kernel 2: HMMA flash attention, persistent work-queue, pure fp16.
// Valid tiles precomputed per item (ballot-compacted smem list); main loop
// unrolled x2 over the double buffer so smem addresses are loop constants.
// Grid = 592. Item = (32 queries, 1 head). Mask dist^2 <= 99.
// ---------------------------------------------------------------------------
__device__ __forceinline__ bool tile_ok(int m0, int zq, int y0q) {
    const int dz  = zq - (m0 >> 8);
    const int y0k = (m0 >> 4) & 15;
    int gap = y0k - (y0q + 1);
    const int g2 = y0q - (y0k + 3);
    if (g2 > gap) gap = g2;
    if (gap < 0) gap = 0;
    return dz*dz + gap*gap <= 99;
}

__global__ __launch_bounds__(128, 5) void attn_kernel() {
    // Q: 2KB; two 8KB K/V buffers (KH 4KB + VH 4KB)
    __shared__ __align__(16) uint4 sbuf[1152];   // 18 KB
    __shared__ int s_item;
    __shared__ int s_wcnt[4];
    __shared__ int s_ntile;
    __shared__ short s_tiles[64];
    const int tid = threadIdx.x;
    const int w  = tid >> 5, l = tid & 31;
    const int g  = l >> 2, tg = l & 3;
    const int qhalf = w & 1;          // 16-row query group
    const int khalf = w >> 1;         // 32-key half of each tile

    const u32 sb = smem_u32(sbuf);
    const u32 QH = sb;                // 2KB
    const u32 KV0 = sb + 2048;        // buffer stride 8192

    // per-thread ldmatrix constants (item-independent)
    const int rowk = (l & 7) + ((l >> 4) << 3);
    const u32 kbse = (u32)(rowk * 64);
    const int swk  = (rowk >> 1) & 3;
    const int chpk = (l >> 3) & 1;
    const u32 ck[2] = { (u32)(((0 + chpk) ^ swk) * 16),
                        (u32)(((2 + chpk) ^ swk) * 16) };
    const int rowv = l & 15;
    const u32 vbse = (u32)(rowv * 64);
    const int swv  = (rowv >> 1) & 3;
    const int tbv  = l >> 4;
    const u32 cv[2] = { (u32)(((0 + tbv) ^ swv) * 16),
                        (u32)(((2 + tbv) ^ swv) * 16) };
    const int qrow = qhalf*16 + (l & 15);
    const int qsw  = ((l & 15) >> 1) & 3;

    // cp.async per-thread smem dst offsets (2 lines: i = tid, tid+128)
    const int ldrow0 = tid >> 2, ldch = tid & 3;
    const u32 dstA = (u32)((ldrow0*4 + (ldch ^ ((ldrow0 >> 1) & 3))) * 16);
    const int ldrow1 = ldrow0 + 32;
    const u32 dstB = (u32)((ldrow1*4 + (ldch ^ ((ldrow1 >> 1) & 3))) * 16);

    for (;;) {
        __syncthreads();             // protect smem state from prior item
        if (tid == 0) s_item = atomicAdd(&g_ctr, 1);
        __syncthreads();
        const int item = s_item;
        if (item >= NITEMS) break;

        const int h = item & 7;
        const int r = item >> 3;
        const int n0 = (c_ztab[r >> 3] * 8 + (r & 7)) * 32;

        const __half* gqh = g_Qh + h*NTOK*HD;
        // per-thread global K/V base addresses (add m0*HD per tile)
        const __half* gkA = g_Kh + h*NTOK*HD + ldrow0*HD + ldch*8;
        const __half* gkB = gkA + 32*HD;
        const __half* gvA = g_Vh + h*NTOK*HD + ldrow0*HD + ldch*8;
        const __half* gvB = gvA + 32*HD;

        const int zq  = n0 >> 8;
        const int y0q = (n0 >> 4) & 15;
        const int zlo = (zq - 9 < 0) ? 0 : zq - 9;
        const int zhi = (zq + 9 > 15) ? 15 : zq + 9;

        // ---- Q load (own group, issued before list build) ----
        cpa16(QH + dstA, gqh + (n0 + ldrow0)*HD + ldch*8);
        CP_COMMIT();

        // ---- cooperative valid-tile list build ----
        {
            const int nrange = (zhi - zlo + 1) * 4;
            const int m0 = zlo*256 + tid*64;
            const bool ok = (tid < nrange) && tile_ok(m0, zq, y0q);
            const unsigned bal = __ballot_sync(0xffffffffu, ok);
            if (l == 0) s_wcnt[w] = __popc(bal);
            __syncthreads();
            int base = 0;
            #pragma unroll
            for (int i = 0; i < 4; i++) if (i < w) base += s_wcnt[i];
            if (ok)
                s_tiles[base + __popc(bal & ((1u << l) - 1u))] = (short)(m0 >> 6);
            if (tid == 0)
                s_ntile = s_wcnt[0] + s_wcnt[1] + s_wcnt[2] + s_wcnt[3];
            __syncthreads();
        }
        const int nt = s_ntile;

        // ---- first K/V prefetch into buffer 0 ----
        {
            const int m0 = ((int)s_tiles[0]) << 6;
            const int mo = m0 * HD;
            cpa16(KV0 + dstA,        gkA + mo);
            cpa16(KV0 + dstB,        gkB + mo);
            cpa16(KV0 + 4096 + dstA, gvA + mo);
            cpa16(KV0 + 4096 + dstB, gvB + mo);
        }
        CP_COMMIT();
        CP_WAIT0();
        __syncthreads();

        // ---- Q fragments ----
        u32 qh[2][4];
        #pragma unroll
        for (int kc = 0; kc < 2; kc++) {
            const u32 ch = (u32)((2*kc + (l >> 4)) ^ qsw);
            ldsm4(qh[kc], QH + qrow*64 + ch*16);
        }

        int xq[2], yq[2];
        int dx2[2][4];
        #pragma unroll
        for (int u = 0; u < 2; u++) {
            const int nq = n0 + qhalf*16 + g + 8*u;
            xq[u] = nq & 15;
            yq[u] = (nq >> 4) & 15;
            #pragma unroll
            for (int pc = 0; pc < 4; pc++) {
                const int dx = xq[u] - (2*tg + (pc & 1) + 8*(pc >> 1));
                dx2[u][pc] = dx*dx;
            }
        }

        float O[4][4] = {};
        float ls[2] = {0.f, 0.f};

#define TILE_BODY(CURB, NXTB)                                                  \
        {                                                                      \
            const int cur = ((int)s_tiles[ti]) << 6;                           \
            if (ti + 1 < nt) {                                                 \
                const int mo = (((int)s_tiles[ti+1]) << 6) * HD;               \
                cpa16((NXTB) + dstA,        gkA + mo);                         \
                cpa16((NXTB) + dstB,        gkB + mo);                         \
                cpa16((NXTB) + 4096 + dstA, gvA + mo);                         \
                cpa16((NXTB) + 4096 + dstB, gvB + mo);                         \
                CP_COMMIT();                                                   \
            }                                                                  \
            float S[4][4] = {};                                                \
            _Pragma("unroll")                                                  \
            for (int kc = 0; kc < 2; kc++) {                                   \
                _Pragma("unroll")                                              \
                for (int jp = 0; jp < 2; jp++) {                               \
                    u32 bh[4];                                                 \
                    ldsm4(bh, (CURB) + (u32)((khalf*2 + jp)*1024) + kbse + ck[kc]); \
                    mma16816(S[2*jp],   qh[kc], bh[0], bh[1]);                 \
                    mma16816(S[2*jp+1], qh[kc], bh[2], bh[3]);                 \
                }                                                              \
            }                                                                  \
            const int dz   = zq - (cur >> 8);                                  \
            const int y0kw = ((cur >> 4) & 15) + khalf*2;                      \
            const int thr  = 99 - dz*dz;                                      \
            _Pragma("unroll")                                                  \
            for (int j = 0; j < 4; j++) {                                      \
                const int par = j & 1, jj = j >> 1;                            \
                const int yk = y0kw + jj;                                      \
                _Pragma("unroll")                                              \
                for (int u = 0; u < 2; u++) {                                  \
                    const int dy = yq[u] - yk;                                 \
                    const int t2 = thr - dy*dy;                                \
                    _Pragma("unroll")                                          \
                    for (int cc = 0; cc < 2; cc++) {                           \
                        float p = ex2f(S[j][2*u + cc]);                        \
                        p = (dx2[u][par*2 + cc] <= t2) ? p : 0.f;              \
                        S[j][2*u + cc] = p;                                    \
                        ls[u] += p;                                            \
                    }                                                          \
                }                                                              \
            }                                                                  \
            _Pragma("unroll")                                                  \
            for (int kc = 0; kc < 2; kc++) {                                   \
                u32 ph[4];                                                     \
                _Pragma("unroll")                                              \
                for (int hf = 0; hf < 2; hf++) {                               \
                    const float* Pj = S[2*kc + hf];                            \
                    ph[2*hf]   = pkhf(Pj[0], Pj[1]);                           \
                    ph[2*hf+1] = pkhf(Pj[2], Pj[3]);                           \
                }                                                              \
                _Pragma("unroll")                                              \
                for (int np = 0; np < 2; np++) {                               \
                    u32 vh[4];                                                 \
                    ldsm4t(vh, (CURB) + 4096 + (u32)((khalf*2 + kc)*1024) + vbse + cv[np]); \
                    mma16816(O[2*np],   ph, vh[0], vh[1]);                     \
                    mma16816(O[2*np+1], ph, vh[2], vh[3]);                     \
                }                                                              \
            }                                                                  \
            CP_WAIT0();                                                        \
            __syncthreads();                                                   \
        }

        int ti = 0;
        while (ti < nt) {
            TILE_BODY(KV0, KV0 + 8192)
            ti++;
            if (ti >= nt) break;
            TILE_BODY(KV0 + 8192, KV0)
            ti++;
        }
#undef TILE_BODY

        // ---- combine key-half partials (khalf 1 -> khalf 0), then store ----
        float* red = (float*)sbuf;
        if (khalf == 1) {
            float* p = red + (qhalf*32 + l)*18;
            #pragma unroll
            for (int t4 = 0; t4 < 4; t4++)
                #pragma unroll
                for (int k = 0; k < 4; k++) p[t4*4 + k] = O[t4][k];
            p[16] = ls[0]; p[17] = ls[1];
        }
        __syncthreads();
        if (khalf == 0) {
            const float* p = red + (qhalf*32 + l)*18;
            #pragma unroll
            for (int t4 = 0; t4 < 4; t4++)
                #pragma unroll
                for (int k = 0; k < 4; k++) O[t4][k] += p[t4*4 + k];
            ls[0] += p[16]; ls[1] += p[17];

            #pragma unroll
            for (int u = 0; u < 2; u++) {
                ls[u] += __shfl_xor_sync(0xffffffffu, ls[u], 1);
                ls[u] += __shfl_xor_sync(0xffffffffu, ls[u], 2);
                const float inv = 1.0f / ls[u];
                const int row = n0 + qhalf*16 + g + 8*u;
                const int base = row*CDIM + h*HD;
                #pragma unroll
                for (int t4 = 0; t4 < 4; t4++) {
                    const u32 hi = pkhf(O[t4][2*u] * inv, O[t4][2*u + 1] * inv);
                    ((u32*)g_Th)[(base + 8*t4 + 2*tg) >> 1] = hi;
                }
            }
        }
    }
}

// ---------------------------------------------------------------------------
// Kernel 3: proj GEMM on HMMA. A = PW hi/lo (2-term), B = T (fp16).
// Block = 64o x 64n, 128 threads. fp32 [C][N] output with fused bias.
// ---------------------------------------------------------------------------
__global__ __launch_bounds__(128) void proj_mma(const float* __restrict__ bias,
                                                float* __restrict__ out) {
    __shared__ __align__(16) uint4 sbuf[1536];   // 2 buffers x 12KB (Ah,Al,B)
    const int tid = threadIdx.x;
    const int w = tid >> 5, l = tid & 31;
    const int g = l >> 2, tg = l & 3;
    const int n0 = blockIdx.x * 64, o0 = blockIdx.y * 64;
    const int ob = w * 16;
    const u32 sb = smem_u32(sbuf);

    const int rowa = ob + (l & 15);
    const int swa  = ((l & 15) >> 1) & 3;
    const int rowk = (l & 7) + ((l >> 4) << 3);
    const u32 kbse = (u32)(rowk * 64);
    const int swk  = (rowk >> 1) & 3;
    const int chpk = (l >> 3) & 1;
    const u32 ck[2] = { (u32)(((0 + chpk) ^ swk) * 16),
                        (u32)(((2 + chpk) ^ swk) * 16) };

    float S[8][4] = {};

    {
        const int c0 = 0;
        for (int i = tid; i < 256; i += 128) {
            const int row = i >> 2, ch = i & 3;
            const u32 dst = sb + (u32)(((row*4) + (ch ^ ((row >> 1) & 3))) * 16);
            cpa16(dst,        g_PWh + (o0+row)*CDIM + c0 + ch*8);
            cpa16(dst + 4096, g_PWl + (o0+row)*CDIM + c0 + ch*8);
            cpa16(dst + 8192, g_Th  + (n0+row)*CDIM + c0 + ch*8);
        }
        CP_COMMIT();
    }

    for (int it = 0; it < 8; it++) {
        if (it < 7) {
            const int c0 = 32*(it + 1);
            const u32 boff = (u32)(((it + 1) & 1) * 12288);
            for (int i = tid; i < 256; i += 128) {
                const int row = i >> 2, ch = i & 3;
                const u32 dst = sb + boff + (u32)(((row*4) + (ch ^ ((row >> 1) & 3))) * 16);
                cpa16(dst,        g_PWh + (o0+row)*CDIM + c0 + ch*8);
                cpa16(dst + 4096, g_PWl + (o0+row)*CDIM + c0 + ch*8);
                cpa16(dst + 8192, g_Th  + (n0+row)*CDIM + c0 + ch*8);
            }
            CP_COMMIT();
            CP_WAIT1();
        } else {
            CP_WAIT0();
        }
        __syncthreads();
        const u32 cb = sb + (u32)((it & 1) * 12288);

        u32 ah[2][4], al[2][4];
        #pragma unroll
        for (int kc = 0; kc < 2; kc++) {
            const u32 ch = (u32)((2*kc + (l >> 4)) ^ swa);
            const u32 a = cb + (u32)(rowa*64) + ch*16;
            ldsm4(ah[kc], a);
            ldsm4(al[kc], a + 4096);
        }
        #pragma unroll
        for (int kc = 0; kc < 2; kc++) {
            #pragma unroll
            for (int jp = 0; jp < 4; jp++) {
                u32 bh[4];
                ldsm4(bh, cb + 8192 + (u32)(jp*1024) + kbse + ck[kc]);
                mma16816(S[2*jp],   ah[kc], bh[0], bh[1]);
                mma16816(S[2*jp],   al[kc], bh[0], bh[1]);
                mma16816(S[2*jp+1], ah[kc], bh[2], bh[3]);
                mma16816(S[2*jp+1], al[kc], bh[2], bh[3]);
            }
        }
        __syncthreads();
    }

    #pragma unroll
    for (int u = 0; u < 2; u++) {
        const int o = o0 + ob + g + 8*u;
        const float bo = bias[o];
        #pragma unroll
        for (int j = 0; j < 8; j++) {
            const int n = n0 + 16*(j >> 1) + 8*(j & 1) + 2*tg;
            float2 v;
            v.x = S[j][2*u]     + bo;
            v.y = S[j][2*u + 1] + bo;
            *(float2*)(out + (size_t)o*NTOK + n) = v;
        }
    }
}

// ---------------------------------------------------------------------------
extern "C" void kernel_launch(void* const* d_in, const int* in_sizes, int n_in,
                              void* d_out, int out_size) {
    const float *x = nullptr, *wq = nullptr, *wp = nullptr, *bp = nullptr;
    for (int i = 0; i < n_in; i++) {
        switch (in_sizes[i]) {
            case 1048576: x  = (const float*)d_in[i]; break;  // x [1,256,16,16,16]
            case 196608:  wq = (const float*)d_in[i]; break;  // qkv_w [768,256]
            case 65536:   wp = (const float*)d_in[i]; break;  // proj_w [256,256]
            case 256:     bp = (const float*)d_in[i]; break;  // proj_b [256]
        }
    }
    float* out = (float*)d_out;

    conv_w  <<<768, 256>>>(wq, wp);
    xpose   <<<dim3(NTOK/64, CDIM/32), 256>>>(x);
    qkv_mma <<<dim3(NTOK/64, 768/64), 128>>>();
    attn_kernel<<<592, 128>>>();
    proj_mma<<<dim3(NTOK/64, CDIM/64), 128>>>(bp, out);
}

// round 17
// speedup vs baseline: 2.1503x; 1.0033x over previous
#include <cuda_runtime.h>
#include <cuda_fp16.h>

#define NTOK 4096
#define CDIM 256
#define NH   8
#define HD   32
// 1/sqrt(32) * log2(e): scores produced directly in log2 domain
#define QSCALE 0.2550181757638722f
#define NITEMS ((NTOK/32)*NH)   // 1024 attention work items
#define ONES2  0x3C003C00u      // f16x2 {1.0, 1.0}

typedef unsigned int u32;
typedef unsigned long long u64;

// ---------------- helpers ----------------
__device__ __forceinline__ float ex2f(float x) {
    float r; asm("ex2.approx.ftz.f32 %0, %1;" : "=f"(r) : "f"(x)); return r;
}
// pack two floats to f16x2: lower 16 bits = f16(lo), upper = f16(hi)
__device__ __forceinline__ u32 pkhf(float lo, float hi) {
    u32 r; asm("cvt.rn.f16x2.f32 %0, %1, %2;" : "=r"(r) : "f"(hi), "f"(lo)); return r;
}
__device__ __forceinline__ void mma16816(float* d, const u32* a, u32 b0, u32 b1) {
    asm volatile("mma.sync.aligned.m16n8k16.row.col.f32.f16.f16.f32 "
        "{%0,%1,%2,%3}, {%4,%5,%6,%7}, {%8,%9}, {%0,%1,%2,%3};"
        : "+f"(d[0]), "+f"(d[1]), "+f"(d[2]), "+f"(d[3])
        : "r"(a[0]), "r"(a[1]), "r"(a[2]), "r"(a[3]), "r"(b0), "r"(b1));
}
__device__ __forceinline__ void ldsm4(u32* r, u32 addr) {
    asm volatile("ldmatrix.sync.aligned.m8n8.x4.shared.b16 {%0,%1,%2,%3}, [%4];"
        : "=r"(r[0]), "=r"(r[1]), "=r"(r[2]), "=r"(r[3]) : "r"(addr));
}
__device__ __forceinline__ void ldsm4t(u32* r, u32 addr) {
    asm volatile("ldmatrix.sync.aligned.m8n8.x4.trans.shared.b16 {%0,%1,%2,%3}, [%4];"
        : "=r"(r[0]), "=r"(r[1]), "=r"(r[2]), "=r"(r[3]) : "r"(addr));
}
__device__ __forceinline__ u32 smem_u32(const void* p) {
    u32 a;
    asm("{ .reg .u64 t; cvta.to.shared.u64 t, %1; cvt.u32.u64 %0, t; }" : "=r"(a) : "l"(p));
    return a;
}
__device__ __forceinline__ void cpa16(u32 s, const void* g) {
    asm volatile("cp.async.cg.shared.global [%0], [%1], 16;" :: "r"(s), "l"(g));
}
#define CP_COMMIT() asm volatile("cp.async.commit_group;" ::: "memory")
#define CP_WAIT0()  asm volatile("cp.async.wait_group 0;" ::: "memory")
#define CP_WAIT1()  asm volatile("cp.async.wait_group 1;" ::: "memory")

// ---------------- scratch (device globals; no allocation allowed) ----------------
__device__ __align__(16) __half g_X [NTOK*CDIM];     // tok [n][c] fp16
__device__ __align__(16) __half g_Wh[3*CDIM*CDIM];   // qkv_w [o][c] hi
__device__ __align__(16) __half g_Wl[3*CDIM*CDIM];   // qkv_w lo residual
__device__ __align__(16) __half g_PWh[CDIM*CDIM];    // proj_w [o][c] hi
__device__ __align__(16) __half g_PWl[CDIM*CDIM];    // proj_w lo residual
__device__ __align__(16) __half g_Qh[NH*NTOK*HD];    // [h][n][d] (pre-scaled)
__device__ __align__(16) __half g_Kh[NH*NTOK*HD];
__device__ __align__(16) __half g_Vh[NH*NTOK*HD];
__device__ __align__(16) __half g_Th[NTOK*CDIM];     // attn out [n][c] fp16

__device__ int g_ctr;                     // work-queue counter
// central-z first so the long items schedule first
__constant__ int c_ztab[16] = {7,8,6,9,5,10,4,11,3,12,2,13,1,14,0,15};

// ---------------------------------------------------------------------------
// Kernel 0a: split qkv_w and proj_w into f16 hi/lo (+ reset work counter)
// ---------------------------------------------------------------------------
__global__ __launch_bounds__(256) void conv_w(const float* __restrict__ wq,
                                              const float* __restrict__ wp) {
    const int i = blockIdx.x * 256 + threadIdx.x;
    if (i == 0) g_ctr = 0;
    if (i < 3*CDIM*CDIM) {
        const float v = wq[i];
        const __half h = __float2half_rn(v);
        g_Wh[i] = h;
        g_Wl[i] = __float2half_rn(v - __half2float(h));
    }
    if (i < CDIM*CDIM) {
        const float v = wp[i];
        const __half h = __float2half_rn(v);
        g_PWh[i] = h;
        g_PWl[i] = __float2half_rn(v - __half2float(h));
    }
}

// ---------------------------------------------------------------------------
// Kernel 0b: transpose x [c][n] -> tok [n][c], fp16
// ---------------------------------------------------------------------------
__global__ __launch_bounds__(256) void xpose(const float* __restrict__ x) {
    __shared__ float t[32][65];
    const int n0 = blockIdx.x * 64, c0 = blockIdx.y * 32;
    const int tid = threadIdx.x;
    #pragma unroll
    for (int i = tid; i < 2048; i += 256) {
        const int c = i >> 6, n = i & 63;
        t[c][n] = x[(c0 + c)*NTOK + n0 + n];
    }
    __syncthreads();
    const int n = tid >> 2, cg = (tid & 3) * 8;
    u32 hi[4];
    #pragma unroll
    for (int k = 0; k < 4; k++)
        hi[k] = pkhf(t[cg + 2*k][n], t[cg + 2*k + 1][n]);
    const int ix = ((n0 + n)*CDIM + c0 + cg) >> 3;   // uint4 units (8 halves)
    ((uint4*)g_X)[ix] = make_uint4(hi[0], hi[1], hi[2], hi[3]);
}

// ---------------------------------------------------------------------------
// Kernel 1: QKV GEMM on HMMA. A = X (fp16), B = W hi/lo (2-term).
// Block = 64n x 64o, 128 threads (4 warps x 16n). cp.async double-buffered.
// ---------------------------------------------------------------------------
__global__ __launch_bounds__(128) void qkv_mma() {
    __shared__ __align__(16) uint4 sbuf[1536];   // 2 buffers x 12KB (A,Bh,Bl)
    const int tid = threadIdx.x;
    const int w = tid >> 5, l = tid & 31;
    const int g = l >> 2, tg = l & 3;
    const int n0 = blockIdx.x * 64, o0 = blockIdx.y * 64;
    const int qb = w * 16;
    const u32 sb = smem_u32(sbuf);

    const int rowa = qb + (l & 15);
    const int swa  = ((l & 15) >> 1) & 3;
    const int rowk = (l & 7) + ((l >> 4) << 3);
    const u32 kbse = (u32)(rowk * 64);
    const int swk  = (rowk >> 1) & 3;
    const int chpk = (l >> 3) & 1;
    const u32 ck[2] = { (u32)(((0 + chpk) ^ swk) * 16),
                        (u32)(((2 + chpk) ^ swk) * 16) };

    float S[8][4] = {};

    {
        const int c0 = 0;
        for (int i = tid; i < 256; i += 128) {
            const int row = i >> 2, ch = i & 3;
            const u32 dst = sb + (u32)(((row*4) + (ch ^ ((row >> 1) & 3))) * 16);
            cpa16(dst,        g_X  + (n0+row)*CDIM + c0 + ch*8);
            cpa16(dst + 4096, g_Wh + (o0+row)*CDIM + c0 + ch*8);
            cpa16(dst + 8192, g_Wl + (o0+row)*CDIM + c0 + ch*8);
        }
        CP_COMMIT();
    }

    for (int it = 0; it < 8; it++) {
        if (it < 7) {
            const int c0 = 32*(it + 1);
            const u32 boff = (u32)(((it + 1) & 1) * 12288);
            for (int i = tid; i < 256; i += 128) {
                const int row = i >> 2, ch = i & 3;
                const u32 dst = sb + boff + (u32)(((row*4) + (ch ^ ((row >> 1) & 3))) * 16);
                cpa16(dst,        g_X  + (n0+row)*CDIM + c0 + ch*8);
                cpa16(dst + 4096, g_Wh + (o0+row)*CDIM + c0 + ch*8);
                cpa16(dst + 8192, g_Wl + (o0+row)*CDIM + c0 + ch*8);
            }
            CP_COMMIT();
            CP_WAIT1();
        } else {
            CP_WAIT0();
        }
        __syncthreads();
        const u32 cb = sb + (u32)((it & 1) * 12288);

        u32 ah[2][4];
        #pragma unroll
        for (int kc = 0; kc < 2; kc++) {
            const u32 ch = (u32)((2*kc + (l >> 4)) ^ swa);
            ldsm4(ah[kc], cb + (u32)(rowa*64) + ch*16);
        }
        #pragma unroll
        for (int kc = 0; kc < 2; kc++) {
            #pragma unroll
            for (int jp = 0; jp < 4; jp++) {
                u32 bh[4], bl[4];
                const u32 a = cb + 4096 + (u32)(jp*1024) + kbse + ck[kc];
                ldsm4(bh, a);
                ldsm4(bl, a + 4096);
                mma16816(S[2*jp],   ah[kc], bh[0], bh[1]);
                mma16816(S[2*jp],   ah[kc], bl[0], bl[1]);
                mma16816(S[2*jp+1], ah[kc], bh[2], bh[3]);
                mma16816(S[2*jp+1], ah[kc], bl[2], bl[3]);
            }
        }
        __syncthreads();
    }

    const int t = o0 >> 8;
    #pragma unroll
    for (int j = 0; j < 8; j++) {
        const int o = o0 + 16*(j >> 1) + 8*(j & 1) + 2*tg;
        const int hh = (o >> 5) & 7, d = o & 31;
        #pragma unroll
        for (int u = 0; u < 2; u++) {
            const int n = n0 + qb + g + 8*u;
            float f0 = S[j][2*u], f1 = S[j][2*u + 1];
            if (t == 0) { f0 *= QSCALE; f1 *= QSCALE; }
            const u32 hi = pkhf(f0, f1);
            const int ix = ((hh*NTOK + n)*HD + d) >> 1;
            if (t == 0)      ((u32*)g_Qh)[ix] = hi;
            else if (t == 1) ((u32*)g_Kh)[ix] = hi;
            else             ((u32*)g_Vh)[ix] = hi;
        }
    }
}

// ---------------------------------------------------------------------------
// Kernel 2: HMMA flash attention, persistent work-queue, pure fp16.
// Tile list ballot-compacted per item; buffer-unrolled main loop; row sums
// accumulated by a ones-column MMA (no scalar FADDs, no final shfl).
// Grid = 740 (5 blocks/SM). Item = (32 queries, 1 head). Mask dist^2 <= 99.
// ---------------------------------------------------------------------------
__device__ __forceinline__ bool tile_ok(int m0, int zq, int y0q) {
    const int dz  = zq - (m0 >> 8);
    const int y0k = (m0 >> 4) & 15;
    int gap = y0k - (y0q + 1);
    const int g2 = y0q - (y0k + 3);
    if (g2 > gap) gap = g2;
    if (gap < 0) gap = 0;
    return dz*dz + gap*gap <= 99;
}

__global__ __launch_bounds__(128, 5) void attn_kernel() {
    // Q: 2KB; two 8KB K/V buffers (KH 4KB + VH 4KB)
    __shared__ __align__(16) uint4 sbuf[1152];   // 18 KB
    __shared__ int s_item;
    __shared__ int s_wcnt[4];
    __shared__ int s_ntile;
    __shared__ short s_tiles[64];
    const int tid = threadIdx.x;
    const int w  = tid >> 5, l = tid & 31;
    const int g  = l >> 2, tg = l & 3;
    const int qhalf = w & 1;          // 16-row query group
    const int khalf = w >> 1;         // 32-key half of each tile

    const u32 sb = smem_u32(sbuf);
    const u32 QH = sb;                // 2KB
    const u32 KV0 = sb + 2048;        // buffer stride 8192

    // per-thread ldmatrix constants (item-independent)
    const int rowk = (l & 7) + ((l >> 4) << 3);
    const u32 kbse = (u32)(rowk * 64);
    const int swk  = (rowk >> 1) & 3;
    const int chpk = (l >> 3) & 1;
    const u32 ck[2] = { (u32)(((0 + chpk) ^ swk) * 16),
                        (u32)(((2 + chpk) ^ swk) * 16) };
    const int rowv = l & 15;
    const u32 vbse = (u32)(rowv * 64);
    const int swv  = (rowv >> 1) & 3;
    const int tbv  = l >> 4;
    const u32 cv[2] = { (u32)(((0 + tbv) ^ swv) * 16),
                        (u32)(((2 + tbv) ^ swv) * 16) };
    const int qrow = qhalf*16 + (l & 15);
    const int qsw  = ((l & 15) >> 1) & 3;

    // cp.async per-thread smem dst offsets (2 lines: i = tid, tid+128)
    const int ldrow0 = tid >> 2, ldch = tid & 3;
    const u32 dstA = (u32)((ldrow0*4 + (ldch ^ ((ldrow0 >> 1) & 3))) * 16);
    const int ldrow1 = ldrow0 + 32;
    const u32 dstB = (u32)((ldrow1*4 + (ldch ^ ((ldrow1 >> 1) & 3))) * 16);

    for (;;) {
        __syncthreads();             // protect smem state from prior item
        if (tid == 0) s_item = atomicAdd(&g_ctr, 1);
        __syncthreads();
        const int item = s_item;
        if (item >= NITEMS) break;

        const int h = item & 7;
        const int r = item >> 3;
        const int n0 = (c_ztab[r >> 3] * 8 + (r & 7)) * 32;

        const __half* gqh = g_Qh + h*NTOK*HD;
        // per-thread global K/V base addresses (add m0*HD per tile)
        const __half* gkA = g_Kh + h*NTOK*HD + ldrow0*HD + ldch*8;
        const __half* gkB = gkA + 32*HD;
        const __half* gvA = g_Vh + h*NTOK*HD + ldrow0*HD + ldch*8;
        const __half* gvB = gvA + 32*HD;

        const int zq  = n0 >> 8;
        const int y0q = (n0 >> 4) & 15;
        const int zlo = (zq - 9 < 0) ? 0 : zq - 9;
        const int zhi = (zq + 9 > 15) ? 15 : zq + 9;

        // ---- Q load (own group, issued before list build) ----
        cpa16(QH + dstA, gqh + (n0 + ldrow0)*HD + ldch*8);
        CP_COMMIT();

        // ---- cooperative valid-tile list build ----
        {
            const int nrange = (zhi - zlo + 1) * 4;
            const int m0 = zlo*256 + tid*64;
            const bool ok = (tid < nrange) && tile_ok(m0, zq, y0q);
            const unsigned bal = __ballot_sync(0xffffffffu, ok);
            if (l == 0) s_wcnt[w] = __popc(bal);
            __syncthreads();
            int base = 0;
            #pragma unroll
            for (int i = 0; i < 4; i++) if (i < w) base += s_wcnt[i];
            if (ok)
                s_tiles[base + __popc(bal & ((1u << l) - 1u))] = (short)(m0 >> 6);
            if (tid == 0)
                s_ntile = s_wcnt[0] + s_wcnt[1] + s_wcnt[2] + s_wcnt[3];
            __syncthreads();
        }
        const int nt = s_ntile;

        // ---- first K/V prefetch into buffer 0 ----
        {
            const int mo = (((int)s_tiles[0]) << 6) * HD;
            cpa16(KV0 + dstA,        gkA + mo);
            cpa16(KV0 + dstB,        gkB + mo);
            cpa16(KV0 + 4096 + dstA, gvA + mo);
            cpa16(KV0 + 4096 + dstB, gvB + mo);
        }
        CP_COMMIT();
        CP_WAIT0();
        __syncthreads();

        // ---- Q fragments ----
        u32 qh[2][4];
        #pragma unroll
        for (int kc = 0; kc < 2; kc++) {
            const u32 ch = (u32)((2*kc + (l >> 4)) ^ qsw);
            ldsm4(qh[kc], QH + qrow*64 + ch*16);
        }

        int xq[2], yq[2];
        int dx2[2][4];
        #pragma unroll
        for (int u = 0; u < 2; u++) {
            const int nq = n0 + qhalf*16 + g + 8*u;
            xq[u] = nq & 15;
            yq[u] = (nq >> 4) & 15;
            #pragma unroll
            for (int pc = 0; pc < 4; pc++) {
                const int dx = xq[u] - (2*tg + (pc & 1) + 8*(pc >> 1));
                dx2[u][pc] = dx*dx;
            }
        }

        float O[4][4] = {};
        float Osum[4] = {};   // ones-column row-sum accumulator

#define TILE_BODY(CURB, NXTB)                                                  \
        {                                                                      \
            const int cur = ((int)s_tiles[ti]) << 6;                           \
            if (ti + 1 < nt) {                                                 \
                const int mo = (((int)s_tiles[ti+1]) << 6) * HD;               \
                cpa16((NXTB) + dstA,        gkA + mo);                         \
                cpa16((NXTB) + dstB,        gkB + mo);                         \
                cpa16((NXTB) + 4096 + dstA, gvA + mo);                         \
                cpa16((NXTB) + 4096 + dstB, gvB + mo);                         \
                CP_COMMIT();                                                   \
            }                                                                  \
            float S[4][4] = {};                                                \
            _Pragma("unroll")                                                  \
            for (int kc = 0; kc < 2; kc++) {                                   \
                _Pragma("unroll")                                              \
                for (int jp = 0; jp < 2; jp++) {                               \
                    u32 bh[4];                                                 \
                    ldsm4(bh, (CURB) + (u32)((khalf*2 + jp)*1024) + kbse + ck[kc]); \
                    mma16816(S[2*jp],   qh[kc], bh[0], bh[1]);                 \
                    mma16816(S[2*jp+1], qh[kc], bh[2], bh[3]);                 \
                }                                                              \
            }                                                                  \
            const int dz   = zq - (cur >> 8);                                  \
            const int y0kw = ((cur >> 4) & 15) + khalf*2;                      \
            const int thr  = 99 - dz*dz;                                      \
            _Pragma("unroll")                                                  \
            for (int j = 0; j < 4; j++) {                                      \
                const int par = j & 1, jj = j >> 1;                            \
                const int yk = y0kw + jj;                                      \
                _Pragma("unroll")                                              \
                for (int u = 0; u < 2; u++) {                                  \
                    const int dy = yq[u] - yk;                                 \
                    const int t2 = thr - dy*dy;                                \
                    _Pragma("unroll")                                          \
                    for (int cc = 0; cc < 2; cc++) {                           \
                        float p = ex2f(S[j][2*u + cc]);                        \
                        p = (dx2[u][par*2 + cc] <= t2) ? p : 0.f;              \
                        S[j][2*u + cc] = p;                                    \
                    }                                                          \
                }                                                              \
            }                                                                  \
            _Pragma("unroll")                                                  \
            for (int kc = 0; kc < 2; kc++) {                                   \
                u32 ph[4];                                                     \
                _Pragma("unroll")                                              \
                for (int hf = 0; hf < 2; hf++) {                               \
                    const float* Pj = S[2*kc + hf];                            \
                    ph[2*hf]   = pkhf(Pj[0], Pj[1]);                           \
                    ph[2*hf+1] = pkhf(Pj[2], Pj[3]);                           \
                }                                                              \
                _Pragma("unroll")                                              \
                for (int np = 0; np < 2; np++) {                               \
                    u32 vh[4];                                                 \
                    ldsm4t(vh, (CURB) + 4096 + (u32)((khalf*2 + kc)*1024) + vbse + cv[np]); \
                    mma16816(O[2*np],   ph, vh[0], vh[1]);                     \
                    mma16816(O[2*np+1], ph, vh[2], vh[3]);                     \
                }                                                              \
                mma16816(Osum, ph, ONES2, ONES2);                              \
            }                                                                  \
            CP_WAIT0();                                                        \
            __syncthreads();                                                   \
        }

        int ti = 0;
        while (ti < nt) {
            TILE_BODY(KV0, KV0 + 8192)
            ti++;
            if (ti >= nt) break;
            TILE_BODY(KV0 + 8192, KV0)
            ti++;
        }
#undef TILE_BODY

        // ---- combine key-half partials (khalf 1 -> khalf 0), then store ----
        // Osum[0] = row g sum over this warp's keys; Osum[2] = row g+8.
        float* red = (float*)sbuf;
        if (khalf == 1) {
            float* p = red + (qhalf*32 + l)*18;
            #pragma unroll
            for (int t4 = 0; t4 < 4; t4++)
                #pragma unroll
                for (int k = 0; k < 4; k++) p[t4*4 + k] = O[t4][k];
            p[16] = Osum[0]; p[17] = Osum[2];
        }
        __syncthreads();
        if (khalf == 0) {
            const float* p = red + (qhalf*32 + l)*18;
            #pragma unroll
            for (int t4 = 0; t4 < 4; t4++)
                #pragma unroll
                for (int k = 0; k < 4; k++) O[t4][k] += p[t4*4 + k];
            const float inv0 = 1.0f / (Osum[0] + p[16]);
            const float inv1 = 1.0f / (Osum[2] + p[17]);
            #pragma unroll
            for (int u = 0; u < 2; u++) {
                const float inv = u ? inv1 : inv0;
                const int row = n0 + qhalf*16 + g + 8*u;
                const int base = row*CDIM + h*HD;
                #pragma unroll
                for (int t4 = 0; t4 < 4; t4++) {
                    const u32 hi = pkhf(O[t4][2*u] * inv, O[t4][2*u + 1] * inv);
                    ((u32*)g_Th)[(base + 8*t4 + 2*tg) >> 1] = hi;
                }
            }
        }
    }
}

// ---------------------------------------------------------------------------
// Kernel 3: proj GEMM on HMMA. A = PW hi/lo (2-term), B = T (fp16).
// Block = 64o x 64n, 128 threads. fp32 [C][N] output with fused bias.
// ---------------------------------------------------------------------------
__global__ __launch_bounds__(128) void proj_mma(const float* __restrict__ bias,
                                                float* __restrict__ out) {
    __shared__ __align__(16) uint4 sbuf[1536];   // 2 buffers x 12KB (Ah,Al,B)
    const int tid = threadIdx.x;
    const int w = tid >> 5, l = tid & 31;
    const int g = l >> 2, tg = l & 3;
    const int n0 = blockIdx.x * 64, o0 = blockIdx.y * 64;
    const int ob = w * 16;
    const u32 sb = smem_u32(sbuf);

    const int rowa = ob + (l & 15);
    const int swa  = ((l & 15) >> 1) & 3;
    const int rowk = (l & 7) + ((l >> 4) << 3);
    const u32 kbse = (u32)(rowk * 64);
    const int swk  = (rowk >> 1) & 3;
    const int chpk = (l >> 3) & 1;
    const u32 ck[2] = { (u32)(((0 + chpk) ^ swk) * 16),
                        (u32)(((2 + chpk) ^ swk) * 16) };

    float S[8][4] = {};

    {
        const int c0 = 0;
        for (int i = tid; i < 256; i += 128) {
            const int row = i >> 2, ch = i & 3;
            const u32 dst = sb + (u32)(((row*4) + (ch ^ ((row >> 1) & 3))) * 16);
            cpa16(dst,        g_PWh + (o0+row)*CDIM + c0 + ch*8);
            cpa16(dst + 4096, g_PWl + (o0+row)*CDIM + c0 + ch*8);
            cpa16(dst + 8192, g_Th  + (n0+row)*CDIM + c0 + ch*8);
        }
        CP_COMMIT();
    }

    for (int it = 0; it < 8; it++) {
        if (it < 7) {
            const int c0 = 32*(it + 1);
            const u32 boff = (u32)(((it + 1) & 1) * 12288);
            for (int i = tid; i < 256; i += 128) {
                const int row = i >> 2, ch = i & 3;
                const u32 dst = sb + boff + (u32)(((row*4) + (ch ^ ((row >> 1) & 3))) * 16);
                cpa16(dst,        g_PWh + (o0+row)*CDIM + c0 + ch*8);
                cpa16(dst + 4096, g_PWl + (o0+row)*CDIM + c0 + ch*8);
                cpa16(dst + 8192, g_Th  + (n0+row)*CDIM + c0 + ch*8);
            }
            CP_COMMIT();
            CP_WAIT1();
        } else {
            CP_WAIT0();
        }
        __syncthreads();
        const u32 cb = sb + (u32)((it & 1) * 12288);

        u32 ah[2][4], al[2][4];
        #pragma unroll
        for (int kc = 0; kc < 2; kc++) {
            const u32 ch = (u32)((2*kc + (l >> 4)) ^ swa);
            const u32 a = cb + (u32)(rowa*64) + ch*16;
            ldsm4(ah[kc], a);
            ldsm4(al[kc], a + 4096);
        }
        #pragma unroll
        for (int kc = 0; kc < 2; kc++) {
            #pragma unroll
            for (int jp = 0; jp < 4; jp++) {
                u32 bh[4];
                ldsm4(bh, cb + 8192 + (u32)(jp*1024) + kbse + ck[kc]);
                mma16816(S[2*jp],   ah[kc], bh[0], bh[1]);
                mma16816(S[2*jp],   al[kc], bh[0], bh[1]);
                mma16816(S[2*jp+1], ah[kc], bh[2], bh[3]);
                mma16816(S[2*jp+1], al[kc], bh[2], bh[3]);
            }
        }
        __syncthreads();
    }

    #pragma unroll
    for (int u = 0; u < 2; u++) {
        const int o = o0 + ob + g + 8*u;
        const float bo = bias[o];
        #pragma unroll
        for (int j = 0; j < 8; j++) {
            const int n = n0 + 16*(j >> 1) + 8*(j & 1) + 2*tg;
            float2 v;
            v.x = S[j][2*u]     + bo;
            v.y = S[j][2*u + 1] + bo;
            *(float2*)(out + (size_t)o*NTOK + n) = v;
        }
    }
}

// ---------------------------------------------------------------------------
extern "C" void kernel_launch(void* const* d_in, const int* in_sizes, int n_in,
                              void* d_out, int out_size) {
    const float *x = nullptr, *wq = nullptr, *wp = nullptr, *bp = nullptr;
    for (int i = 0; i < n_in; i++) {
        switch (in_sizes[i]) {
            case 1048576: x  = (const float*)d_in[i]; break;  // x [1,256,16,16,16]
            case 196608:  wq = (const float*)d_in[i]; break;  // qkv_w [768,256]
            case 65536:   wp = (const float*)d_in[i]; break;  // proj_w [256,256]
            case 256:     bp = (const float*)d_in[i]; break;  // proj_b [256]
        }
    }
    float* out = (float*)d_out;

    conv_w  <<<768, 256>>>(wq, wp);
    xpose   <<<dim3(NTOK/64, CDIM/32), 256>>>(x);
    qkv_mma <<<dim3(NTOK/64, 768/64), 128>>>();
    attn_kernel<<<740, 128>>>();
    proj_mma<<<dim3(NTOK/64, CDIM/64), 128>>>(bp, out);
}